// round 2
// baseline (speedup 1.0000x reference)
#include <cuda_runtime.h>
#include <cuda_bf16.h>

// Problem constants
#define Nn   50000
#define Ee   400000
#define Rr   32
#define Ff   132
#define EVd  15

// ---------------- device scratch (no allocs allowed) ----------------
__device__ float g_q_inv[Nn * Ff];
__device__ float g_k_inv[Nn * Ff];
__device__ float g_v_inv[Nn * Ff];
__device__ float g_q_ev [Nn * Ff];
__device__ float g_k_ev [Nn * Ff];
__device__ float g_dinv [Nn * Ff];
__device__ float g_dev  [Nn * EVd];

__device__ __forceinline__ float silu_f(float x) {
    return x / (1.0f + __expf(-x));
}

// ---------------- zero accumulators ----------------
__global__ void zero_kernel() {
    int i = blockIdx.x * blockDim.x + threadIdx.x;
    int stride = gridDim.x * blockDim.x;
    for (int j = i; j < Nn * Ff; j += stride) g_dinv[j] = 0.0f;
    for (int j = i; j < Nn * EVd; j += stride) g_dev[j] = 0.0f;
}

// ---------------- per-node projections ----------------
// q_inv/k_inv/v_inv: (N,4,33)x(4,33,33);  q_ev/k_ev: (N,3,44)x(3,44,44)
#define TNA 16
__global__ __launch_bounds__(256) void node_proj_kernel(
    const float* __restrict__ x,
    const float* __restrict__ Wq_inv, const float* __restrict__ Wk_inv,
    const float* __restrict__ Wv_inv, const float* __restrict__ Wq_ev,
    const float* __restrict__ Wk_ev)
{
    __shared__ float xs[TNA][Ff];
    const int n0 = blockIdx.x * TNA;
    for (int i = threadIdx.x; i < TNA * Ff; i += blockDim.x)
        xs[i / Ff][i % Ff] = x[n0 * Ff + i];
    __syncthreads();

    for (int f = threadIdx.x; f < 5 * Ff; f += blockDim.x) {
        const int m = f / Ff, c = f - m * Ff;
        const float* W;
        float* out;
        int D, h, e;
        bool dosilu = true;
        if (m < 3) {
            D = 33; h = c / 33; e = c - h * 33;
            W = (m == 0 ? Wq_inv : (m == 1 ? Wk_inv : Wv_inv)) + h * 33 * 33;
            out = (m == 0 ? g_q_inv : (m == 1 ? g_k_inv : g_v_inv));
            dosilu = (m != 2);
        } else {
            D = 44; h = c / 44; e = c - h * 44;
            W = (m == 3 ? Wq_ev : Wk_ev) + h * 44 * 44;
            out = (m == 3 ? g_q_ev : g_k_ev);
        }
        float acc[TNA];
#pragma unroll
        for (int t = 0; t < TNA; t++) acc[t] = 0.0f;
        const int xb = h * D;
        for (int d = 0; d < D; d++) {
            const float w = W[d * D + e];
#pragma unroll
            for (int t = 0; t < TNA; t++) acc[t] += xs[t][xb + d] * w;
        }
#pragma unroll
        for (int t = 0; t < TNA; t++) {
            float v = acc[t];
            if (dosilu) v = silu_f(v);
            out[(n0 + t) * Ff + c] = v;
        }
    }
}

// ---------------- per-edge: filter nets + attention + scatter ----------------
#define TE 32
struct EdgeSmem {
    float rbf[TE][Rr];    // 4096 B
    float h1 [TE][264];   // 33792 B (fi cols 0..131, fe cols 132..263)
    float fw [TE][264];   // 33792 B
    float he [TE][66];    // 8448 B  (fi hidden 0..32, fe hidden 33..65)
    float ev3[TE][3];     // 384 B
    float al [TE][8];     // 1024 B  (0..3 inv heads, 4..6 ev heads, *cutoff/norm)
    float cut[TE];        // 128 B
    int   sidx[TE];       // 128 B
    int   ridx[TE];       // 128 B
};

__global__ __launch_bounds__(256, 2) void edge_kernel(
    const float* __restrict__ ev_features,
    const float* __restrict__ rbf,
    const float* __restrict__ sh,
    const float* __restrict__ cutoffs,
    const int*   __restrict__ senders,
    const int*   __restrict__ receivers,
    const float* __restrict__ fi_rW1, const float* __restrict__ fi_rb1,
    const float* __restrict__ fi_rW2, const float* __restrict__ fi_rb2,
    const float* __restrict__ fi_eW1, const float* __restrict__ fi_eb1,
    const float* __restrict__ fi_eW2, const float* __restrict__ fi_eb2,
    const float* __restrict__ fe_rW1, const float* __restrict__ fe_rb1,
    const float* __restrict__ fe_rW2, const float* __restrict__ fe_rb2,
    const float* __restrict__ fe_eW1, const float* __restrict__ fe_eb1,
    const float* __restrict__ fe_eW2, const float* __restrict__ fe_eb2)
{
    extern __shared__ char smraw[];
    EdgeSmem& sm = *reinterpret_cast<EdgeSmem*>(smraw);
    const int tid = threadIdx.x;
    const int e0 = blockIdx.x * TE;

    // phase 0: edge metadata + rbf tile + ev_diff group sums-of-squares
    for (int i = tid; i < TE; i += 256) {
        sm.sidx[i] = senders[e0 + i];
        sm.ridx[i] = receivers[e0 + i];
        sm.cut[i]  = cutoffs[e0 + i];
    }
    for (int i = tid; i < TE * Rr; i += 256)
        sm.rbf[i / Rr][i % Rr] = rbf[e0 * Rr + i];
    __syncthreads();
    for (int i = tid; i < TE * 3; i += 256) {
        const int t = i / 3, g = i - 3 * t;
        const int js = (g == 0) ? 0 : ((g == 1) ? 3 : 8);
        const int je = (g == 0) ? 3 : ((g == 1) ? 8 : 15);
        const float* evs = ev_features + sm.sidx[t] * EVd;
        const float* evr = ev_features + sm.ridx[t] * EVd;
        float a = 0.0f;
        for (int j = js; j < je; j++) {
            const float d = evs[j] - evr[j];
            a += d * d;
        }
        sm.ev3[t][g] = a;
    }
    __syncthreads();

    // phase 1: layer-1 of both filter nets (rbf branch + ev branch hidden)
    for (int f = tid; f < 264; f += 256) {
        const int net = (f >= 132);
        const int c = f - net * 132;
        const float* W1 = net ? fe_rW1 : fi_rW1;
        const float b = (net ? fe_rb1 : fi_rb1)[c];
        float acc[TE];
#pragma unroll
        for (int t = 0; t < TE; t++) acc[t] = b;
        for (int k = 0; k < Rr; k++) {
            const float w = W1[k * 132 + c];
#pragma unroll
            for (int t = 0; t < TE; t++) acc[t] += sm.rbf[t][k] * w;
        }
#pragma unroll
        for (int t = 0; t < TE; t++) sm.h1[t][f] = silu_f(acc[t]);
    }
    for (int f = tid; f < 66; f += 256) {
        const int net = (f >= 33);
        const int c = f - net * 33;
        const float* W = net ? fe_eW1 : fi_eW1;
        const float b = (net ? fe_eb1 : fi_eb1)[c];
        const float w0 = W[c], w1 = W[33 + c], w2 = W[66 + c];
#pragma unroll
        for (int t = 0; t < TE; t++) {
            const float a = b + sm.ev3[t][0] * w0 + sm.ev3[t][1] * w1 + sm.ev3[t][2] * w2;
            sm.he[t][f] = silu_f(a);
        }
    }
    __syncthreads();

    // phase 2: layer-2 (132->132 rbf branch + 33->132 ev branch), summed
    for (int f = tid; f < 264; f += 256) {
        const int net = (f >= 132);
        const int c = f - net * 132;
        const float* W2 = net ? fe_rW2 : fi_rW2;
        const float* E2 = net ? fe_eW2 : fi_eW2;
        const float b = (net ? fe_rb2 : fi_rb2)[c] + (net ? fe_eb2 : fi_eb2)[c];
        float acc[TE];
#pragma unroll
        for (int t = 0; t < TE; t++) acc[t] = b;
        const int hb = net * 132;
        for (int k = 0; k < 132; k++) {
            const float w = W2[k * 132 + c];
#pragma unroll
            for (int t = 0; t < TE; t++) acc[t] += sm.h1[t][hb + k] * w;
        }
        const int eb = net * 33;
        for (int k = 0; k < 33; k++) {
            const float w = E2[k * 132 + c];
#pragma unroll
            for (int t = 0; t < TE; t++) acc[t] += sm.he[t][eb + k] * w;
        }
#pragma unroll
        for (int t = 0; t < TE; t++) sm.fw[t][f] = acc[t];
    }
    __syncthreads();

    // phase 3: attention logits (q*k*fw reductions), fold in cutoff and 1/sqrt(D)
    const float INVN = 0.17407765595569785f;  // 1/sqrt(33)
    const float INVE = 0.15075567228888181f;  // 1/sqrt(44)
    for (int i = tid; i < TE * 7; i += 256) {
        const int t = i / 7, h = i - 7 * t;
        const int se = sm.sidx[t], re = sm.ridx[t];
        float a = 0.0f;
        if (h < 4) {
            const float* q  = g_q_inv + re * Ff + h * 33;
            const float* k  = g_k_inv + se * Ff + h * 33;
            const float* fw = &sm.fw[t][h * 33];
#pragma unroll
            for (int d = 0; d < 33; d++) a += q[d] * k[d] * fw[d];
            sm.al[t][h] = a * INVN * sm.cut[t];
        } else {
            const int hh = h - 4;
            const float* q  = g_q_ev + re * Ff + hh * 44;
            const float* k  = g_k_ev + se * Ff + hh * 44;
            const float* fw = &sm.fw[t][132 + hh * 44];
#pragma unroll
            for (int d = 0; d < 44; d++) a += q[d] * k[d] * fw[d];
            sm.al[t][4 + hh] = a * INVE * sm.cut[t];
        }
    }
    __syncthreads();

    // phase 4: message scatter (segment_sum via atomics)
    for (int i = tid; i < TE * Ff; i += 256) {
        const int t = i / Ff, f = i - Ff * t;
        const int h = f / 33;
        const float val = sm.al[t][h] * g_v_inv[sm.sidx[t] * Ff + f];
        atomicAdd(&g_dinv[sm.ridx[t] * Ff + f], val);
    }
    for (int i = tid; i < TE * EVd; i += 256) {
        const int t = i / EVd, j = i - EVd * t;
        const int g = (j < 3) ? 0 : ((j < 8) ? 1 : 2);
        const float val = sm.al[t][4 + g] * sh[(e0 + t) * EVd + j];
        atomicAdd(&g_dev[sm.ridx[t] * EVd + j], val);
    }
}

// ---------------- final node update ----------------
#define TNF 8
__global__ __launch_bounds__(256) void final_kernel(
    const float* __restrict__ inv_features,
    const float* __restrict__ ev_features,
    const float* __restrict__ W_int,
    const float* __restrict__ b_int,
    float* __restrict__ out)
{
    __shared__ float cat_s[TNF][136];   // inv1 (132) + ev1_inv (3)
    __shared__ float ev1_s[TNF][EVd];
    __shared__ float tb_s[TNF][3];
    const int n0 = blockIdx.x * TNF;

    for (int i = threadIdx.x; i < TNF * Ff; i += blockDim.x) {
        const int t = i / Ff, f = i - Ff * t;
        cat_s[t][f] = inv_features[(n0 + t) * Ff + f] + g_dinv[(n0 + t) * Ff + f];
    }
    for (int i = threadIdx.x; i < TNF * EVd; i += blockDim.x) {
        const int t = i / EVd, j = i - EVd * t;
        ev1_s[t][j] = ev_features[(n0 + t) * EVd + j] + g_dev[(n0 + t) * EVd + j];
    }
    __syncthreads();
    for (int i = threadIdx.x; i < TNF * 3; i += blockDim.x) {
        const int t = i / 3, g = i - 3 * t;
        const int js = (g == 0) ? 0 : ((g == 1) ? 3 : 8);
        const int je = (g == 0) ? 3 : ((g == 1) ? 8 : 15);
        float a = 0.0f;
        for (int j = js; j < je; j++) {
            const float v = ev1_s[t][j];
            a += v * v;
        }
        cat_s[t][132 + g] = a;
    }
    __syncthreads();

    if (threadIdx.x < 135) {
        const int f = threadIdx.x;
        float acc[TNF];
#pragma unroll
        for (int t = 0; t < TNF; t++) acc[t] = b_int[f];
        for (int k = 0; k < 135; k++) {
            const float w = W_int[k * 135 + f];
#pragma unroll
            for (int t = 0; t < TNF; t++) acc[t] += cat_s[t][k] * w;
        }
        if (f < 132) {
#pragma unroll
            for (int t = 0; t < TNF; t++)
                out[(n0 + t) * Ff + f] = cat_s[t][f] + acc[t];
        } else {
#pragma unroll
            for (int t = 0; t < TNF; t++) tb_s[t][f - 132] = acc[t];
        }
    }
    __syncthreads();

    float* out_ev = out + Nn * Ff;
    for (int i = threadIdx.x; i < TNF * EVd; i += blockDim.x) {
        const int t = i / EVd, j = i - EVd * t;
        const int g = (j < 3) ? 0 : ((j < 8) ? 1 : 2);
        out_ev[(n0 + t) * EVd + j] = ev1_s[t][j] * (1.0f + tb_s[t][g]);
    }
}

// ---------------- launch ----------------
extern "C" void kernel_launch(void* const* d_in, const int* in_sizes, int n_in,
                              void* d_out, int out_size)
{
    const float* inv_features = (const float*)d_in[0];
    const float* ev_features  = (const float*)d_in[1];
    const float* rbf          = (const float*)d_in[2];
    const float* sh_vectors   = (const float*)d_in[3];
    const float* cutoffs      = (const float*)d_in[4];
    const int*   senders      = (const int*)d_in[5];
    const int*   receivers    = (const int*)d_in[6];
    const float* Wq_inv = (const float*)d_in[7];
    const float* Wk_inv = (const float*)d_in[8];
    const float* Wv_inv = (const float*)d_in[9];
    const float* Wq_ev  = (const float*)d_in[10];
    const float* Wk_ev  = (const float*)d_in[11];
    const float* fi_rW1 = (const float*)d_in[12];
    const float* fi_rb1 = (const float*)d_in[13];
    const float* fi_rW2 = (const float*)d_in[14];
    const float* fi_rb2 = (const float*)d_in[15];
    const float* fi_eW1 = (const float*)d_in[16];
    const float* fi_eb1 = (const float*)d_in[17];
    const float* fi_eW2 = (const float*)d_in[18];
    const float* fi_eb2 = (const float*)d_in[19];
    const float* fe_rW1 = (const float*)d_in[20];
    const float* fe_rb1 = (const float*)d_in[21];
    const float* fe_rW2 = (const float*)d_in[22];
    const float* fe_rb2 = (const float*)d_in[23];
    const float* fe_eW1 = (const float*)d_in[24];
    const float* fe_eb1 = (const float*)d_in[25];
    const float* fe_eW2 = (const float*)d_in[26];
    const float* fe_eb2 = (const float*)d_in[27];
    const float* W_int  = (const float*)d_in[28];
    const float* b_int  = (const float*)d_in[29];
    float* out = (float*)d_out;

    cudaFuncSetAttribute(edge_kernel,
                         cudaFuncAttributeMaxDynamicSharedMemorySize,
                         (int)sizeof(EdgeSmem));

    zero_kernel<<<512, 256>>>();
    node_proj_kernel<<<Nn / TNA, 256>>>(inv_features, Wq_inv, Wk_inv, Wv_inv,
                                        Wq_ev, Wk_ev);
    edge_kernel<<<Ee / TE, 256, sizeof(EdgeSmem)>>>(
        ev_features, rbf, sh_vectors, cutoffs, senders, receivers,
        fi_rW1, fi_rb1, fi_rW2, fi_rb2, fi_eW1, fi_eb1, fi_eW2, fi_eb2,
        fe_rW1, fe_rb1, fe_rW2, fe_rb2, fe_eW1, fe_eb1, fe_eW2, fe_eb2);
    final_kernel<<<Nn / TNF, 256>>>(inv_features, ev_features, W_int, b_int, out);
}

// round 3
// speedup vs baseline: 2.2908x; 2.2908x over previous
#include <cuda_runtime.h>
#include <cuda_fp16.h>

// Problem constants
#define Nn   50000
#define Ee   400000
#define Rr   32
#define Ff   132
#define EVd  15

// GEMM geometry (block-diagonal over both filter nets)
#define TE   64      // edges per block
#define KC   352     // padded K for layer2 (176 per net)
#define NC   272     // padded N (136 per net)
#define AS   360     // h1 smem row stride (halves) -> 180 words, conflict-free
#define FS   272     // fw smem row stride (halves)
#define RS   40      // rbf smem row stride (halves) -> 20 words, conflict-free
#define NT_L2 22     // K/16 for layer 2
#define NT_N  34     // N/8 tiles

// ---------------- device scratch ----------------
__device__ float g_q_inv[Nn * Ff];
__device__ float g_k_inv[Nn * Ff];
__device__ float g_v_inv[Nn * Ff];
__device__ float g_q_ev [Nn * Ff];
__device__ float g_k_ev [Nn * Ff];
__device__ float g_dinv [Nn * Ff];
__device__ float g_dev  [Nn * EVd];

// fragment-major (swizzled) weights: per (n-tile, k-step): 64 u32
// [0..31] = b0 per lane, [32..63] = b1 per lane
__device__ unsigned int g_W2sw[NT_N * NT_L2 * 64];
__device__ unsigned int g_W1sw[NT_N * 2 * 64];
__device__ float g_b1c[NC];
__device__ float g_b2c[NC];

__device__ __forceinline__ float silu_f(float x) {
    return x / (1.0f + __expf(-x));
}

__device__ __forceinline__ void mma16816(float c[4],
    unsigned a0, unsigned a1, unsigned a2, unsigned a3,
    unsigned b0, unsigned b1)
{
    asm volatile(
        "mma.sync.aligned.m16n8k16.row.col.f32.f16.f16.f32 "
        "{%0,%1,%2,%3},{%4,%5,%6,%7},{%8,%9},{%0,%1,%2,%3};\n"
        : "+f"(c[0]), "+f"(c[1]), "+f"(c[2]), "+f"(c[3])
        : "r"(a0), "r"(a1), "r"(a2), "r"(a3), "r"(b0), "r"(b1));
}

// ---------------- zero accumulators ----------------
__global__ void zero_kernel() {
    int i = blockIdx.x * blockDim.x + threadIdx.x;
    int stride = gridDim.x * blockDim.x;
    for (int j = i; j < Nn * Ff; j += stride) g_dinv[j] = 0.0f;
    for (int j = i; j < Nn * EVd; j += stride) g_dev[j] = 0.0f;
}

// ---------------- weight prep: pack fp16 fragment-major ----------------
__device__ __forceinline__ float W2val(int k, int n,
    const float* fi_rW2, const float* fi_eW2,
    const float* fe_rW2, const float* fe_eW2)
{
    if (n < 132) {
        if (k < 132) return fi_rW2[k * 132 + n];
        if (k < 165) return fi_eW2[(k - 132) * 132 + n];
        return 0.0f;
    }
    if (n < 136 || n >= 268) return 0.0f;
    int nn = n - 136;
    if (k >= 176 && k < 308) return fe_rW2[(k - 176) * 132 + nn];
    if (k >= 308 && k < 341) return fe_eW2[(k - 308) * 132 + nn];
    return 0.0f;
}

__device__ __forceinline__ float W1val(int k, int n,
    const float* fi_rW1, const float* fe_rW1)
{
    if (n < 132) return fi_rW1[k * 132 + n];
    if (n >= 136 && n < 268) return fe_rW1[k * 132 + (n - 136)];
    return 0.0f;
}

__global__ void prep_kernel(
    const float* __restrict__ fi_rW1, const float* __restrict__ fi_rb1,
    const float* __restrict__ fi_rW2, const float* __restrict__ fi_rb2,
    const float* __restrict__ fi_eW2, const float* __restrict__ fi_eb2,
    const float* __restrict__ fe_rW1, const float* __restrict__ fe_rb1,
    const float* __restrict__ fe_rW2, const float* __restrict__ fe_rb2,
    const float* __restrict__ fe_eW2, const float* __restrict__ fe_eb2)
{
    int i = blockIdx.x * blockDim.x + threadIdx.x;
    if (i < NT_N * NT_L2 * 64) {
        int nt = i / (NT_L2 * 64);
        int r  = i - nt * (NT_L2 * 64);
        int ks = r / 64;
        int slot = r - ks * 64;
        int lane = slot & 31;
        int gq = lane >> 2, t4 = lane & 3;
        int n = nt * 8 + gq;
        int k = ks * 16 + ((slot >= 32) ? 8 : 0) + 2 * t4;
        __half2 v = __floats2half2_rn(
            W2val(k,     n, fi_rW2, fi_eW2, fe_rW2, fe_eW2),
            W2val(k + 1, n, fi_rW2, fi_eW2, fe_rW2, fe_eW2));
        ((__half2*)g_W2sw)[i] = v;
    }
    if (i < NT_N * 2 * 64) {
        int nt = i / (2 * 64);
        int r  = i - nt * (2 * 64);
        int ks = r / 64;
        int slot = r - ks * 64;
        int lane = slot & 31;
        int gq = lane >> 2, t4 = lane & 3;
        int n = nt * 8 + gq;
        int k = ks * 16 + ((slot >= 32) ? 8 : 0) + 2 * t4;
        __half2 v = __floats2half2_rn(W1val(k, n, fi_rW1, fe_rW1),
                                      W1val(k + 1, n, fi_rW1, fe_rW1));
        ((__half2*)g_W1sw)[i] = v;
    }
    if (i < NC) {
        float b1 = 0.0f, b2 = 0.0f;
        if (i < 132) { b1 = fi_rb1[i]; b2 = fi_rb2[i] + fi_eb2[i]; }
        else if (i >= 136 && i < 268) {
            int nn = i - 136;
            b1 = fe_rb1[nn]; b2 = fe_rb2[nn] + fe_eb2[nn];
        }
        g_b1c[i] = b1;
        g_b2c[i] = b2;
    }
}

// ---------------- per-node projections (fp32) ----------------
#define TNA 16
__global__ __launch_bounds__(256) void node_proj_kernel(
    const float* __restrict__ x,
    const float* __restrict__ Wq_inv, const float* __restrict__ Wk_inv,
    const float* __restrict__ Wv_inv, const float* __restrict__ Wq_ev,
    const float* __restrict__ Wk_ev)
{
    __shared__ float xs[TNA][Ff];
    const int n0 = blockIdx.x * TNA;
    for (int i = threadIdx.x; i < TNA * Ff; i += blockDim.x)
        xs[i / Ff][i % Ff] = x[n0 * Ff + i];
    __syncthreads();

    for (int f = threadIdx.x; f < 5 * Ff; f += blockDim.x) {
        const int m = f / Ff, c = f - m * Ff;
        const float* W;
        float* out;
        int D, h, e;
        bool dosilu = true;
        if (m < 3) {
            D = 33; h = c / 33; e = c - h * 33;
            W = (m == 0 ? Wq_inv : (m == 1 ? Wk_inv : Wv_inv)) + h * 33 * 33;
            out = (m == 0 ? g_q_inv : (m == 1 ? g_k_inv : g_v_inv));
            dosilu = (m != 2);
        } else {
            D = 44; h = c / 44; e = c - h * 44;
            W = (m == 3 ? Wq_ev : Wk_ev) + h * 44 * 44;
            out = (m == 3 ? g_q_ev : g_k_ev);
        }
        float acc[TNA];
#pragma unroll
        for (int t = 0; t < TNA; t++) acc[t] = 0.0f;
        const int xb = h * D;
        for (int d = 0; d < D; d++) {
            const float w = W[d * D + e];
#pragma unroll
            for (int t = 0; t < TNA; t++) acc[t] += xs[t][xb + d] * w;
        }
#pragma unroll
        for (int t = 0; t < TNA; t++) {
            float v = acc[t];
            if (dosilu) v = silu_f(v);
            out[(n0 + t) * Ff + c] = v;
        }
    }
}

// ---------------- fused edge kernel: filter nets (HMMA) + attention + scatter ----------------
struct ESm {
    __half h1[TE * AS];     // 46080 B : layer-1 outputs (both nets) + ev hidden
    __half fw[TE * FS];     // 34816 B : filter weights (layer-2 output)
    __half rbf[TE * RS];    //  5120 B
    float  ev3[TE][3];
    float  al [TE][8];
    float  cut[TE];
    int    sidx[TE];
    int    ridx[TE];
};

__global__ __launch_bounds__(256, 2) void edge_kernel(
    const float* __restrict__ ev_features,
    const float* __restrict__ rbf_g,
    const float* __restrict__ sh,
    const float* __restrict__ cutoffs,
    const int*   __restrict__ senders,
    const int*   __restrict__ receivers,
    const float* __restrict__ fi_eW1, const float* __restrict__ fi_eb1,
    const float* __restrict__ fe_eW1, const float* __restrict__ fe_eb1)
{
    extern __shared__ char smraw[];
    ESm& sm = *reinterpret_cast<ESm*>(smraw);
    const int tid = threadIdx.x;
    const int e0 = blockIdx.x * TE;
    const int w = tid >> 5, lane = tid & 31;
    const int gq = lane >> 2, t4 = lane & 3;

    // ---- phase 0: metadata, rbf (fp16), zero h1 ----
    for (int i = tid; i < TE; i += 256) {
        sm.sidx[i] = senders[e0 + i];
        sm.ridx[i] = receivers[e0 + i];
        sm.cut[i]  = cutoffs[e0 + i];
    }
    for (int i = tid; i < TE * Rr; i += 256) {
        int t = i >> 5, c = i & 31;
        sm.rbf[t * RS + c] = __float2half(rbf_g[e0 * Rr + i]);
    }
    for (int i = tid; i < TE * (AS / 2); i += 256)
        ((unsigned int*)sm.h1)[i] = 0u;
    __syncthreads();

    // ---- ev_diff group sums-of-squares ----
    for (int i = tid; i < TE * 3; i += 256) {
        int t = i / 3, g3 = i - 3 * t;
        int js = (g3 == 0) ? 0 : ((g3 == 1) ? 3 : 8);
        int je = (g3 == 0) ? 3 : ((g3 == 1) ? 8 : 15);
        const float* evs = ev_features + sm.sidx[t] * EVd;
        const float* evr = ev_features + sm.ridx[t] * EVd;
        float a = 0.0f;
        for (int j = js; j < je; j++) {
            float d = evs[j] - evr[j];
            a += d * d;
        }
        sm.ev3[t][g3] = a;
    }
    __syncthreads();

    // ---- layer 1: rbf branch via HMMA -> silu -> h1 fp16 ----
    {
        float acc[5][4][4];
#pragma unroll
        for (int j = 0; j < 5; j++)
#pragma unroll
            for (int m = 0; m < 4; m++)
#pragma unroll
                for (int c = 0; c < 4; c++) acc[j][m][c] = 0.0f;

#pragma unroll
        for (int ks = 0; ks < 2; ks++) {
            const int k0 = ks * 16;
            unsigned a[4][4];
#pragma unroll
            for (int m = 0; m < 4; m++) {
                const __half* ap = sm.rbf + (m * 16 + gq) * RS + k0 + 2 * t4;
                a[m][0] = *(const unsigned*)(ap);
                a[m][1] = *(const unsigned*)(ap + 8 * RS);
                a[m][2] = *(const unsigned*)(ap + 8);
                a[m][3] = *(const unsigned*)(ap + 8 * RS + 8);
            }
#pragma unroll
            for (int j = 0; j < 5; j++) {
                int nt = w + 8 * j;
                if (nt < NT_N) {
                    const unsigned* bp = g_W1sw + (nt * 2 + ks) * 64;
                    unsigned b0 = bp[lane], b1 = bp[32 + lane];
#pragma unroll
                    for (int m = 0; m < 4; m++)
                        mma16816(acc[j][m], a[m][0], a[m][1], a[m][2], a[m][3], b0, b1);
                }
            }
        }
        // writeback with silu, map n -> h1 column
#pragma unroll
        for (int j = 0; j < 5; j++) {
            int nt = w + 8 * j;
            if (nt < NT_N) {
                int n = nt * 8 + 2 * t4;
                bool valid = (n < 132) || (n >= 136 && n < 268);
                if (valid) {
                    int col = (n < 132) ? n : (n + 40);  // net1 cols start at 176
                    float b0f = g_b1c[n], b1f = g_b1c[n + 1];
#pragma unroll
                    for (int m = 0; m < 4; m++) {
                        int r0 = m * 16 + gq;
                        *(__half2*)&sm.h1[r0 * AS + col] =
                            __floats2half2_rn(silu_f(acc[j][m][0] + b0f),
                                              silu_f(acc[j][m][1] + b1f));
                        *(__half2*)&sm.h1[(r0 + 8) * AS + col] =
                            __floats2half2_rn(silu_f(acc[j][m][2] + b0f),
                                              silu_f(acc[j][m][3] + b1f));
                    }
                }
            }
        }
    }

    // ---- layer 1: ev branch (3 -> 33 per net), scalar ----
    for (int i = tid; i < TE * 66; i += 256) {
        int t = i / 66, c = i - 66 * t;
        int net = (c >= 33);
        int cc = c - 33 * net;
        const float* W = net ? fe_eW1 : fi_eW1;
        float b = (net ? fe_eb1 : fi_eb1)[cc];
        float v = b + sm.ev3[t][0] * W[cc] + sm.ev3[t][1] * W[33 + cc]
                    + sm.ev3[t][2] * W[66 + cc];
        sm.h1[t * AS + (net ? 308 : 132) + cc] = __float2half(silu_f(v));
    }
    __syncthreads();

    // ---- layer 2: [64 x 352] x [352 x 272] via HMMA -> fw fp16 ----
    {
        float acc[5][4][4];
#pragma unroll
        for (int j = 0; j < 5; j++)
#pragma unroll
            for (int m = 0; m < 4; m++)
#pragma unroll
                for (int c = 0; c < 4; c++) acc[j][m][c] = 0.0f;

#pragma unroll 2
        for (int ks = 0; ks < NT_L2; ks++) {
            const int k0 = ks * 16;
            unsigned a[4][4];
#pragma unroll
            for (int m = 0; m < 4; m++) {
                const __half* ap = sm.h1 + (m * 16 + gq) * AS + k0 + 2 * t4;
                a[m][0] = *(const unsigned*)(ap);
                a[m][1] = *(const unsigned*)(ap + 8 * AS);
                a[m][2] = *(const unsigned*)(ap + 8);
                a[m][3] = *(const unsigned*)(ap + 8 * AS + 8);
            }
#pragma unroll
            for (int j = 0; j < 5; j++) {
                int nt = w + 8 * j;
                if (nt < NT_N) {
                    const unsigned* bp = g_W2sw + (nt * NT_L2 + ks) * 64;
                    unsigned b0 = bp[lane], b1 = bp[32 + lane];
#pragma unroll
                    for (int m = 0; m < 4; m++)
                        mma16816(acc[j][m], a[m][0], a[m][1], a[m][2], a[m][3], b0, b1);
                }
            }
        }
#pragma unroll
        for (int j = 0; j < 5; j++) {
            int nt = w + 8 * j;
            if (nt < NT_N) {
                int n = nt * 8 + 2 * t4;
                float b0f = g_b2c[n], b1f = g_b2c[n + 1];
#pragma unroll
                for (int m = 0; m < 4; m++) {
                    int r0 = m * 16 + gq;
                    *(__half2*)&sm.fw[r0 * FS + n] =
                        __floats2half2_rn(acc[j][m][0] + b0f, acc[j][m][1] + b1f);
                    *(__half2*)&sm.fw[(r0 + 8) * FS + n] =
                        __floats2half2_rn(acc[j][m][2] + b0f, acc[j][m][3] + b1f);
                }
            }
        }
    }
    __syncthreads();

    // ---- phase 3: attention logits, warp-cooperative (coalesced q/k) ----
    {
        const float INVN = 0.17407765595569785f;  // 1/sqrt(33)
        const float INVE = 0.15075567228888181f;  // 1/sqrt(44)
        for (int task = w; task < TE * 7; task += 8) {
            int t = task / 7, h = task - 7 * t;
            int se = sm.sidx[t], re = sm.ridx[t];
            float a = 0.0f;
            float norm;
            if (h < 4) {
                const float* q = g_q_inv + re * Ff + h * 33;
                const float* k = g_k_inv + se * Ff + h * 33;
                int fb = h * 33;
                for (int d = lane; d < 33; d += 32)
                    a += q[d] * k[d] * __half2float(sm.fw[t * FS + fb + d]);
                norm = INVN;
            } else {
                int hh = h - 4;
                const float* q = g_q_ev + re * Ff + hh * 44;
                const float* k = g_k_ev + se * Ff + hh * 44;
                int fb = 136 + hh * 44;
                for (int d = lane; d < 44; d += 32)
                    a += q[d] * k[d] * __half2float(sm.fw[t * FS + fb + d]);
                norm = INVE;
            }
            a += __shfl_xor_sync(0xFFFFFFFFu, a, 16);
            a += __shfl_xor_sync(0xFFFFFFFFu, a, 8);
            a += __shfl_xor_sync(0xFFFFFFFFu, a, 4);
            a += __shfl_xor_sync(0xFFFFFFFFu, a, 2);
            a += __shfl_xor_sync(0xFFFFFFFFu, a, 1);
            if (lane == 0) sm.al[t][h] = a * norm * sm.cut[t];
        }
    }
    __syncthreads();

    // ---- phase 4: message scatter ----
    for (int i = tid; i < TE * Ff; i += 256) {
        int t = i / Ff, f = i - Ff * t;
        int h = f / 33;
        float val = sm.al[t][h] * g_v_inv[sm.sidx[t] * Ff + f];
        atomicAdd(&g_dinv[sm.ridx[t] * Ff + f], val);
    }
    for (int i = tid; i < TE * EVd; i += 256) {
        int t = i / EVd, j = i - EVd * t;
        int gg = (j < 3) ? 0 : ((j < 8) ? 1 : 2);
        float val = sm.al[t][4 + gg] * sh[(e0 + t) * EVd + j];
        atomicAdd(&g_dev[sm.ridx[t] * EVd + j], val);
    }
}

// ---------------- final node update ----------------
#define TNF 8
__global__ __launch_bounds__(256) void final_kernel(
    const float* __restrict__ inv_features,
    const float* __restrict__ ev_features,
    const float* __restrict__ W_int,
    const float* __restrict__ b_int,
    float* __restrict__ out)
{
    __shared__ float cat_s[TNF][136];
    __shared__ float ev1_s[TNF][EVd];
    __shared__ float tb_s[TNF][3];
    const int n0 = blockIdx.x * TNF;

    for (int i = threadIdx.x; i < TNF * Ff; i += blockDim.x) {
        const int t = i / Ff, f = i - Ff * t;
        cat_s[t][f] = inv_features[(n0 + t) * Ff + f] + g_dinv[(n0 + t) * Ff + f];
    }
    for (int i = threadIdx.x; i < TNF * EVd; i += blockDim.x) {
        const int t = i / EVd, j = i - EVd * t;
        ev1_s[t][j] = ev_features[(n0 + t) * EVd + j] + g_dev[(n0 + t) * EVd + j];
    }
    __syncthreads();
    for (int i = threadIdx.x; i < TNF * 3; i += blockDim.x) {
        const int t = i / 3, g = i - 3 * t;
        const int js = (g == 0) ? 0 : ((g == 1) ? 3 : 8);
        const int je = (g == 0) ? 3 : ((g == 1) ? 8 : 15);
        float a = 0.0f;
        for (int j = js; j < je; j++) {
            const float v = ev1_s[t][j];
            a += v * v;
        }
        cat_s[t][132 + g] = a;
    }
    __syncthreads();

    if (threadIdx.x < 135) {
        const int f = threadIdx.x;
        float acc[TNF];
#pragma unroll
        for (int t = 0; t < TNF; t++) acc[t] = b_int[f];
        for (int k = 0; k < 135; k++) {
            const float w = W_int[k * 135 + f];
#pragma unroll
            for (int t = 0; t < TNF; t++) acc[t] += cat_s[t][k] * w;
        }
        if (f < 132) {
#pragma unroll
            for (int t = 0; t < TNF; t++)
                out[(n0 + t) * Ff + f] = cat_s[t][f] + acc[t];
        } else {
#pragma unroll
            for (int t = 0; t < TNF; t++) tb_s[t][f - 132] = acc[t];
        }
    }
    __syncthreads();

    float* out_ev = out + Nn * Ff;
    for (int i = threadIdx.x; i < TNF * EVd; i += blockDim.x) {
        const int t = i / EVd, j = i - EVd * t;
        const int g = (j < 3) ? 0 : ((j < 8) ? 1 : 2);
        out_ev[(n0 + t) * EVd + j] = ev1_s[t][j] * (1.0f + tb_s[t][g]);
    }
}

// ---------------- launch ----------------
extern "C" void kernel_launch(void* const* d_in, const int* in_sizes, int n_in,
                              void* d_out, int out_size)
{
    const float* inv_features = (const float*)d_in[0];
    const float* ev_features  = (const float*)d_in[1];
    const float* rbf          = (const float*)d_in[2];
    const float* sh_vectors   = (const float*)d_in[3];
    const float* cutoffs      = (const float*)d_in[4];
    const int*   senders      = (const int*)d_in[5];
    const int*   receivers    = (const int*)d_in[6];
    const float* Wq_inv = (const float*)d_in[7];
    const float* Wk_inv = (const float*)d_in[8];
    const float* Wv_inv = (const float*)d_in[9];
    const float* Wq_ev  = (const float*)d_in[10];
    const float* Wk_ev  = (const float*)d_in[11];
    const float* fi_rW1 = (const float*)d_in[12];
    const float* fi_rb1 = (const float*)d_in[13];
    const float* fi_rW2 = (const float*)d_in[14];
    const float* fi_rb2 = (const float*)d_in[15];
    const float* fi_eW1 = (const float*)d_in[16];
    const float* fi_eb1 = (const float*)d_in[17];
    const float* fi_eW2 = (const float*)d_in[18];
    const float* fi_eb2 = (const float*)d_in[19];
    const float* fe_rW1 = (const float*)d_in[20];
    const float* fe_rb1 = (const float*)d_in[21];
    const float* fe_rW2 = (const float*)d_in[22];
    const float* fe_rb2 = (const float*)d_in[23];
    const float* fe_eW1 = (const float*)d_in[24];
    const float* fe_eb1 = (const float*)d_in[25];
    const float* fe_eW2 = (const float*)d_in[26];
    const float* fe_eb2 = (const float*)d_in[27];
    const float* W_int  = (const float*)d_in[28];
    const float* b_int  = (const float*)d_in[29];
    float* out = (float*)d_out;

    cudaFuncSetAttribute(edge_kernel,
                         cudaFuncAttributeMaxDynamicSharedMemorySize,
                         (int)sizeof(ESm));

    zero_kernel<<<512, 256>>>();
    prep_kernel<<<(NT_N * NT_L2 * 64 + 255) / 256, 256>>>(
        fi_rW1, fi_rb1, fi_rW2, fi_rb2, fi_eW2, fi_eb2,
        fe_rW1, fe_rb1, fe_rW2, fe_rb2, fe_eW2, fe_eb2);
    node_proj_kernel<<<Nn / TNA, 256>>>(inv_features, Wq_inv, Wk_inv, Wv_inv,
                                        Wq_ev, Wk_ev);
    edge_kernel<<<Ee / TE, 256, sizeof(ESm)>>>(
        ev_features, rbf, sh_vectors, cutoffs, senders, receivers,
        fi_eW1, fi_eb1, fe_eW1, fe_eb1);
    final_kernel<<<Nn / TNF, 256>>>(inv_features, ev_features, W_int, b_int, out);
}

// round 4
// speedup vs baseline: 2.5795x; 1.1260x over previous
#include <cuda_runtime.h>
#include <cuda_fp16.h>

// Problem constants
#define Nn   50000
#define Ee   400000
#define Rr   32
#define Ff   132
#define EVd  15

#define TE     64    // edges per tile
#define NTILES 6250  // Ee / TE
#define GRID   148   // persistent blocks

#define NTT  18      // n-tiles per net (N padded 144)
#define KS2  12      // layer-2 k-steps (K padded 192)
#define AS   392     // h1 row stride (halves): 2 nets * 192 + pad
#define FS   296     // fw row stride (halves): 2 nets * 144 + pad
#define RS   40      // rbf row stride (halves)

// ---------------- device scratch ----------------
__device__ float g_q_inv[Nn * Ff];
__device__ float g_k_inv[Nn * Ff];
__device__ float g_v_inv[Nn * Ff];
__device__ float g_q_ev [Nn * Ff];
__device__ float g_k_ev [Nn * Ff];
__device__ float g_dinv [Nn * Ff];
__device__ float g_dev  [Nn * EVd];

// fragment-packed weights (compact, block-diagonal)
__device__ unsigned int g_W2sw[2 * NTT * KS2 * 64];  // 27648
__device__ unsigned int g_W1sw[2 * NTT * 2 * 64];    // 4608
__device__ float g_b1c[2 * 144];
__device__ float g_b2c[2 * 144];

__device__ __forceinline__ float silu_f(float x) {
    return x / (1.0f + __expf(-x));
}

__device__ __forceinline__ void mma16816(float c[4],
    unsigned a0, unsigned a1, unsigned a2, unsigned a3,
    unsigned b0, unsigned b1)
{
    asm volatile(
        "mma.sync.aligned.m16n8k16.row.col.f32.f16.f16.f32 "
        "{%0,%1,%2,%3},{%4,%5,%6,%7},{%8,%9},{%0,%1,%2,%3};\n"
        : "+f"(c[0]), "+f"(c[1]), "+f"(c[2]), "+f"(c[3])
        : "r"(a0), "r"(a1), "r"(a2), "r"(a3), "r"(b0), "r"(b1));
}

__device__ __forceinline__ void ldsm4(unsigned& r0, unsigned& r1,
                                      unsigned& r2, unsigned& r3,
                                      unsigned addr)
{
    asm volatile(
        "ldmatrix.sync.aligned.m8n8.x4.shared.b16 {%0,%1,%2,%3}, [%4];\n"
        : "=r"(r0), "=r"(r1), "=r"(r2), "=r"(r3) : "r"(addr));
}

// ---------------- zero accumulators ----------------
__global__ void zero_kernel() {
    int i = blockIdx.x * blockDim.x + threadIdx.x;
    int stride = gridDim.x * blockDim.x;
    for (int j = i; j < Nn * Ff; j += stride) g_dinv[j] = 0.0f;
    for (int j = i; j < Nn * EVd; j += stride) g_dev[j] = 0.0f;
}

// ---------------- weight prep (compact block-diagonal packing) ----------------
__device__ __forceinline__ float W2com(int net, int k, int n,
    const float* fi_rW2, const float* fi_eW2,
    const float* fe_rW2, const float* fe_eW2)
{
    if (n >= 132) return 0.0f;
    if (k < 132)  return (net ? fe_rW2 : fi_rW2)[k * 132 + n];
    if (k >= 144 && k < 177) return (net ? fe_eW2 : fi_eW2)[(k - 144) * 132 + n];
    return 0.0f;
}

__global__ void prep_kernel(
    const float* __restrict__ fi_rW1, const float* __restrict__ fi_rb1,
    const float* __restrict__ fi_rW2, const float* __restrict__ fi_rb2,
    const float* __restrict__ fi_eW2, const float* __restrict__ fi_eb2,
    const float* __restrict__ fe_rW1, const float* __restrict__ fe_rb1,
    const float* __restrict__ fe_rW2, const float* __restrict__ fe_rb2,
    const float* __restrict__ fe_eW2, const float* __restrict__ fe_eb2)
{
    int i = blockIdx.x * blockDim.x + threadIdx.x;
    if (i < 2 * NTT * KS2 * 64) {
        int slot = i & 63;
        int blk = i >> 6;
        int ks = blk % KS2;
        int tmp = blk / KS2;
        int tt = tmp % NTT;
        int net = tmp / NTT;
        int lane = slot & 31;
        int gq = lane >> 2, t4 = lane & 3;
        int k = ks * 16 + ((slot & 32) ? 8 : 0) + 2 * t4;
        int n = tt * 8 + gq;
        __half2 v = __floats2half2_rn(
            W2com(net, k,     n, fi_rW2, fi_eW2, fe_rW2, fe_eW2),
            W2com(net, k + 1, n, fi_rW2, fi_eW2, fe_rW2, fe_eW2));
        ((__half2*)g_W2sw)[i] = v;
    }
    if (i < 2 * NTT * 2 * 64) {
        int slot = i & 63;
        int blk = i >> 6;
        int ks = blk & 1;
        int tmp = blk >> 1;
        int tt = tmp % NTT;
        int net = tmp / NTT;
        int lane = slot & 31;
        int gq = lane >> 2, t4 = lane & 3;
        int k = ks * 16 + ((slot & 32) ? 8 : 0) + 2 * t4;
        int n = tt * 8 + gq;
        const float* W = net ? fe_rW1 : fi_rW1;
        float v0 = (n < 132) ? W[k * 132 + n] : 0.0f;
        float v1 = (n + 1 < 132) ? W[(k + 1) * 132 + n] : 0.0f;
        // careful: v1 is same n, k+1
        v1 = (n < 132) ? W[(k + 1) * 132 + n] : 0.0f;
        ((__half2*)g_W1sw)[i] = __floats2half2_rn(v0, v1);
    }
    if (i < 2 * 144) {
        int net = i / 144, n = i % 144;
        float b1 = 0.0f, b2 = 0.0f;
        if (n < 132) {
            b1 = (net ? fe_rb1 : fi_rb1)[n];
            b2 = (net ? fe_rb2 : fi_rb2)[n] + (net ? fe_eb2 : fi_eb2)[n];
        }
        g_b1c[i] = b1;
        g_b2c[i] = b2;
    }
}

// ---------------- per-node projections ----------------
#define TNA 16
__global__ __launch_bounds__(256) void node_proj_kernel(
    const float* __restrict__ x,
    const float* __restrict__ Wq_inv, const float* __restrict__ Wk_inv,
    const float* __restrict__ Wv_inv, const float* __restrict__ Wq_ev,
    const float* __restrict__ Wk_ev)
{
    __shared__ float xs[TNA][Ff];
    const int n0 = blockIdx.x * TNA;
    for (int i = threadIdx.x; i < TNA * Ff; i += blockDim.x)
        xs[i / Ff][i % Ff] = x[n0 * Ff + i];
    __syncthreads();

    for (int f = threadIdx.x; f < 5 * Ff; f += blockDim.x) {
        const int m = f / Ff, c = f - m * Ff;
        const float* W;
        float* out;
        int D, h, e;
        bool dosilu = true;
        if (m < 3) {
            D = 33; h = c / 33; e = c - h * 33;
            W = (m == 0 ? Wq_inv : (m == 1 ? Wk_inv : Wv_inv)) + h * 33 * 33;
            out = (m == 0 ? g_q_inv : (m == 1 ? g_k_inv : g_v_inv));
            dosilu = (m != 2);
        } else {
            D = 44; h = c / 44; e = c - h * 44;
            W = (m == 3 ? Wq_ev : Wk_ev) + h * 44 * 44;
            out = (m == 3 ? g_q_ev : g_k_ev);
        }
        float acc[TNA];
#pragma unroll
        for (int t = 0; t < TNA; t++) acc[t] = 0.0f;
        const int xb = h * D;
        for (int d = 0; d < D; d++) {
            const float w = W[d * D + e];
#pragma unroll
            for (int t = 0; t < TNA; t++) acc[t] += xs[t][xb + d] * w;
        }
#pragma unroll
        for (int t = 0; t < TNA; t++) {
            float v = acc[t];
            if (dosilu) v = silu_f(v);
            out[(n0 + t) * Ff + c] = v;
        }
    }
}

// ---------------- persistent fused edge kernel ----------------
struct ESm {
    unsigned sW2[2 * NTT * KS2 * 64];  // 110592 B
    unsigned sW1[2 * NTT * 2 * 64];    //  18432 B
    float sb1[2 * 144];                //   1152 B
    float sb2[2 * 144];                //   1152 B
    float sevW[2 * 99];                //    792 B
    float sevB[2 * 33];                //    264 B
    __half h1[TE * AS];                //  50176 B
    __half fw[TE * FS];                //  37888 B
    __half rbfs[TE * RS];              //   5120 B
    float ev3[TE * 3];                 //    768 B
    float al [TE * 8];                 //   2048 B
    float cut[TE];                     //    256 B
    int   sidx[TE];                    //    256 B
    int   ridx[TE];                    //    256 B
};                                     // total 229152 B

__global__ __launch_bounds__(512, 1) void edge_kernel(
    const float* __restrict__ ev_features,
    const float* __restrict__ rbf_g,
    const float* __restrict__ sh,
    const float* __restrict__ cutoffs,
    const int*   __restrict__ senders,
    const int*   __restrict__ receivers,
    const float* __restrict__ fi_eW1, const float* __restrict__ fi_eb1,
    const float* __restrict__ fe_eW1, const float* __restrict__ fe_eb1)
{
    extern __shared__ char smraw[];
    ESm& sm = *reinterpret_cast<ESm*>(smraw);
    const int tid = threadIdx.x;
    const int w = tid >> 5, lane = tid & 31;
    const int gq = lane >> 2, t4 = lane & 3;
    const int net = w >> 3, wn = w & 7;
    const int ntile = (wn < 2) ? 3 : 2;
    const int l15 = lane & 15;
    const int lc8 = (lane & 16) ? 8 : 0;

    // ---- one-time staging of weights + zero h1 ----
    for (int i = tid; i < 2 * NTT * KS2 * 64; i += 512) sm.sW2[i] = g_W2sw[i];
    for (int i = tid; i < 2 * NTT * 2 * 64; i += 512)   sm.sW1[i] = g_W1sw[i];
    for (int i = tid; i < 2 * 144; i += 512) { sm.sb1[i] = g_b1c[i]; sm.sb2[i] = g_b2c[i]; }
    for (int i = tid; i < 2 * 99; i += 512)
        sm.sevW[i] = (i < 99) ? fi_eW1[i] : fe_eW1[i - 99];
    for (int i = tid; i < 2 * 33; i += 512)
        sm.sevB[i] = (i < 33) ? fi_eb1[i] : fe_eb1[i - 33];
    for (int i = tid; i < TE * AS / 2; i += 512)
        ((unsigned*)sm.h1)[i] = 0u;
    __syncthreads();

    const unsigned h1s  = (unsigned)__cvta_generic_to_shared(sm.h1);
    const unsigned rbss = (unsigned)__cvta_generic_to_shared(sm.rbfs);
    // per-lane ldmatrix address bases (bytes)
    const unsigned a2base = h1s  + 2 * (l15 * AS + net * 192 + lc8);
    const unsigned a1base = rbss + 2 * (l15 * RS + lc8);

    for (int tile = blockIdx.x; tile < NTILES; tile += gridDim.x) {
        const int e0 = tile * TE;
        __syncthreads();   // protect smem reuse vs previous iteration readers

        // ---- phase 0: metadata + rbf ----
        if (tid < TE) {
            sm.sidx[tid] = senders[e0 + tid];
            sm.ridx[tid] = receivers[e0 + tid];
            sm.cut[tid]  = cutoffs[e0 + tid];
        }
        for (int i = tid; i < TE * Rr; i += 512) {
            int t = i >> 5, c = i & 31;
            sm.rbfs[t * RS + c] = __float2half(rbf_g[e0 * Rr + i]);
        }
        __syncthreads();

        // ---- ev3 sums-of-squares (threads < 192) ----
        if (tid < TE * 3) {
            int t = tid / 3, g3 = tid - 3 * t;
            int js = (g3 == 0) ? 0 : ((g3 == 1) ? 3 : 8);
            int je = (g3 == 0) ? 3 : ((g3 == 1) ? 8 : 15);
            const float* evs = ev_features + sm.sidx[t] * EVd;
            const float* evr = ev_features + sm.ridx[t] * EVd;
            float a = 0.0f;
            for (int j = js; j < je; j++) {
                float d = evs[j] - evr[j];
                a += d * d;
            }
            sm.ev3[t * 3 + g3] = a;
        }

        // ---- layer 1 (rbf branch): [64x32] x [32x144] per net ----
        {
            float acc[3][4][4];
#pragma unroll
            for (int j = 0; j < 3; j++) {
                if (j < ntile) {
                    int nidx = net * 144 + (wn + 8 * j) * 8 + 2 * t4;
                    float b0f = sm.sb1[nidx], b1f = sm.sb1[nidx + 1];
#pragma unroll
                    for (int m = 0; m < 4; m++) {
                        acc[j][m][0] = b0f; acc[j][m][1] = b1f;
                        acc[j][m][2] = b0f; acc[j][m][3] = b1f;
                    }
                }
            }
#pragma unroll
            for (int ks = 0; ks < 2; ks++) {
                unsigned a[4][4];
#pragma unroll
                for (int m = 0; m < 4; m++)
                    ldsm4(a[m][0], a[m][1], a[m][2], a[m][3],
                          a1base + 2 * (m * 16 * RS + ks * 16));
#pragma unroll
                for (int j = 0; j < 3; j++) {
                    if (j < ntile) {
                        int tt = wn + 8 * j;
                        int bi = ((net * NTT + tt) * 2 + ks) * 64;
                        unsigned b0 = sm.sW1[bi + lane], b1 = sm.sW1[bi + 32 + lane];
#pragma unroll
                        for (int m = 0; m < 4; m++)
                            mma16816(acc[j][m], a[m][0], a[m][1], a[m][2], a[m][3], b0, b1);
                    }
                }
            }
#pragma unroll
            for (int j = 0; j < 3; j++) {
                if (j < ntile) {
                    int col = net * 192 + (wn + 8 * j) * 8 + 2 * t4;
#pragma unroll
                    for (int m = 0; m < 4; m++) {
                        int r = m * 16 + gq;
                        *(__half2*)&sm.h1[r * AS + col] =
                            __floats2half2_rn(silu_f(acc[j][m][0]), silu_f(acc[j][m][1]));
                        *(__half2*)&sm.h1[(r + 8) * AS + col] =
                            __floats2half2_rn(silu_f(acc[j][m][2]), silu_f(acc[j][m][3]));
                    }
                }
            }
        }
        __syncthreads();

        // ---- layer 1 ev branch (3 -> 33 per net) -> h1 cols 144..176 ----
        for (int i = tid; i < TE * 66; i += 512) {
            int t = i / 66, c = i - 66 * t;
            int nb = (c >= 33);
            int cc = c - 33 * nb;
            float v = sm.sevB[nb * 33 + cc]
                    + sm.ev3[t * 3 + 0] * sm.sevW[nb * 99 + cc]
                    + sm.ev3[t * 3 + 1] * sm.sevW[nb * 99 + 33 + cc]
                    + sm.ev3[t * 3 + 2] * sm.sevW[nb * 99 + 66 + cc];
            sm.h1[t * AS + nb * 192 + 144 + cc] = __float2half(silu_f(v));
        }
        __syncthreads();

        // ---- layer 2: [64x192] x [192x144] per net -> fw ----
        {
            float acc[3][4][4];
#pragma unroll
            for (int j = 0; j < 3; j++) {
                if (j < ntile) {
                    int nidx = net * 144 + (wn + 8 * j) * 8 + 2 * t4;
                    float b0f = sm.sb2[nidx], b1f = sm.sb2[nidx + 1];
#pragma unroll
                    for (int m = 0; m < 4; m++) {
                        acc[j][m][0] = b0f; acc[j][m][1] = b1f;
                        acc[j][m][2] = b0f; acc[j][m][3] = b1f;
                    }
                }
            }
#pragma unroll 2
            for (int ks = 0; ks < KS2; ks++) {
                unsigned a[4][4];
#pragma unroll
                for (int m = 0; m < 4; m++)
                    ldsm4(a[m][0], a[m][1], a[m][2], a[m][3],
                          a2base + 2 * (m * 16 * AS + ks * 16));
#pragma unroll
                for (int j = 0; j < 3; j++) {
                    if (j < ntile) {
                        int tt = wn + 8 * j;
                        int bi = ((net * NTT + tt) * KS2 + ks) * 64;
                        unsigned b0 = sm.sW2[bi + lane], b1 = sm.sW2[bi + 32 + lane];
#pragma unroll
                        for (int m = 0; m < 4; m++)
                            mma16816(acc[j][m], a[m][0], a[m][1], a[m][2], a[m][3], b0, b1);
                    }
                }
            }
#pragma unroll
            for (int j = 0; j < 3; j++) {
                if (j < ntile) {
                    int col = net * 144 + (wn + 8 * j) * 8 + 2 * t4;
#pragma unroll
                    for (int m = 0; m < 4; m++) {
                        int r = m * 16 + gq;
                        *(__half2*)&sm.fw[r * FS + col] =
                            __floats2half2_rn(acc[j][m][0], acc[j][m][1]);
                        *(__half2*)&sm.fw[(r + 8) * FS + col] =
                            __floats2half2_rn(acc[j][m][2], acc[j][m][3]);
                    }
                }
            }
        }
        __syncthreads();

        // ---- phase 3: attention logits, warp-cooperative, 2-way interleaved ----
        {
            const float INVN = 0.17407765595569785f;  // 1/sqrt(33)
            const float INVE = 0.15075567228888181f;  // 1/sqrt(44)
            for (int p = 0; p < 28; p += 2) {
                int taskA = w + 16 * p;
                int taskB = taskA + 16;
                int tA = taskA / 7, hA = taskA - 7 * tA;
                int tB = taskB / 7, hB = taskB - 7 * tB;

                const float *qA, *kA; int fbA, DA; float nmA;
                if (hA < 4) { qA = g_q_inv + sm.ridx[tA] * Ff + hA * 33;
                              kA = g_k_inv + sm.sidx[tA] * Ff + hA * 33;
                              fbA = tA * FS + hA * 33; DA = 33; nmA = INVN; }
                else        { int hh = hA - 4;
                              qA = g_q_ev + sm.ridx[tA] * Ff + hh * 44;
                              kA = g_k_ev + sm.sidx[tA] * Ff + hh * 44;
                              fbA = tA * FS + 144 + hh * 44; DA = 44; nmA = INVE; }
                const float *qB, *kB; int fbB, DB; float nmB;
                if (hB < 4) { qB = g_q_inv + sm.ridx[tB] * Ff + hB * 33;
                              kB = g_k_inv + sm.sidx[tB] * Ff + hB * 33;
                              fbB = tB * FS + hB * 33; DB = 33; nmB = INVN; }
                else        { int hh = hB - 4;
                              qB = g_q_ev + sm.ridx[tB] * Ff + hh * 44;
                              kB = g_k_ev + sm.sidx[tB] * Ff + hh * 44;
                              fbB = tB * FS + 144 + hh * 44; DB = 44; nmB = INVE; }

                float aA = qA[lane] * kA[lane] * __half2float(sm.fw[fbA + lane]);
                float aB = qB[lane] * kB[lane] * __half2float(sm.fw[fbB + lane]);
                int d1 = lane + 32;
                if (d1 < DA) aA += qA[d1] * kA[d1] * __half2float(sm.fw[fbA + d1]);
                if (d1 < DB) aB += qB[d1] * kB[d1] * __half2float(sm.fw[fbB + d1]);
#pragma unroll
                for (int s = 16; s > 0; s >>= 1) {
                    aA += __shfl_xor_sync(0xFFFFFFFFu, aA, s);
                    aB += __shfl_xor_sync(0xFFFFFFFFu, aB, s);
                }
                if (lane == 0) {
                    sm.al[tA * 8 + hA] = aA * nmA * sm.cut[tA];
                    sm.al[tB * 8 + hB] = aB * nmB * sm.cut[tB];
                }
            }
        }
        __syncthreads();

        // ---- phase 4: message scatter ----
        for (int i = tid; i < TE * Ff; i += 512) {
            int t = i / Ff, f = i - Ff * t;
            int h = f / 33;
            float val = sm.al[t * 8 + h] * g_v_inv[sm.sidx[t] * Ff + f];
            atomicAdd(&g_dinv[sm.ridx[t] * Ff + f], val);
        }
        for (int i = tid; i < TE * EVd; i += 512) {
            int t = i / EVd, jj = i - EVd * t;
            int gg = (jj < 3) ? 0 : ((jj < 8) ? 1 : 2);
            float val = sm.al[t * 8 + 4 + gg] * sh[(e0 + t) * EVd + jj];
            atomicAdd(&g_dev[sm.ridx[t] * EVd + jj], val);
        }
    }
}

// ---------------- final node update ----------------
#define TNF 8
__global__ __launch_bounds__(256) void final_kernel(
    const float* __restrict__ inv_features,
    const float* __restrict__ ev_features,
    const float* __restrict__ W_int,
    const float* __restrict__ b_int,
    float* __restrict__ out)
{
    __shared__ float cat_s[TNF][136];
    __shared__ float ev1_s[TNF][EVd];
    __shared__ float tb_s[TNF][3];
    const int n0 = blockIdx.x * TNF;

    for (int i = threadIdx.x; i < TNF * Ff; i += blockDim.x) {
        const int t = i / Ff, f = i - Ff * t;
        cat_s[t][f] = inv_features[(n0 + t) * Ff + f] + g_dinv[(n0 + t) * Ff + f];
    }
    for (int i = threadIdx.x; i < TNF * EVd; i += blockDim.x) {
        const int t = i / EVd, j = i - EVd * t;
        ev1_s[t][j] = ev_features[(n0 + t) * EVd + j] + g_dev[(n0 + t) * EVd + j];
    }
    __syncthreads();
    for (int i = threadIdx.x; i < TNF * 3; i += blockDim.x) {
        const int t = i / 3, g = i - 3 * t;
        const int js = (g == 0) ? 0 : ((g == 1) ? 3 : 8);
        const int je = (g == 0) ? 3 : ((g == 1) ? 8 : 15);
        float a = 0.0f;
        for (int j = js; j < je; j++) {
            const float v = ev1_s[t][j];
            a += v * v;
        }
        cat_s[t][132 + g] = a;
    }
    __syncthreads();

    if (threadIdx.x < 135) {
        const int f = threadIdx.x;
        float acc[TNF];
#pragma unroll
        for (int t = 0; t < TNF; t++) acc[t] = b_int[f];
        for (int k = 0; k < 135; k++) {
            const float w = W_int[k * 135 + f];
#pragma unroll
            for (int t = 0; t < TNF; t++) acc[t] += cat_s[t][k] * w;
        }
        if (f < 132) {
#pragma unroll
            for (int t = 0; t < TNF; t++)
                out[(n0 + t) * Ff + f] = cat_s[t][f] + acc[t];
        } else {
#pragma unroll
            for (int t = 0; t < TNF; t++) tb_s[t][f - 132] = acc[t];
        }
    }
    __syncthreads();

    float* out_ev = out + Nn * Ff;
    for (int i = threadIdx.x; i < TNF * EVd; i += blockDim.x) {
        const int t = i / EVd, j = i - EVd * t;
        const int g = (j < 3) ? 0 : ((j < 8) ? 1 : 2);
        out_ev[(n0 + t) * EVd + j] = ev1_s[t][j] * (1.0f + tb_s[t][g]);
    }
}

// ---------------- launch ----------------
extern "C" void kernel_launch(void* const* d_in, const int* in_sizes, int n_in,
                              void* d_out, int out_size)
{
    const float* inv_features = (const float*)d_in[0];
    const float* ev_features  = (const float*)d_in[1];
    const float* rbf          = (const float*)d_in[2];
    const float* sh_vectors   = (const float*)d_in[3];
    const float* cutoffs      = (const float*)d_in[4];
    const int*   senders      = (const int*)d_in[5];
    const int*   receivers    = (const int*)d_in[6];
    const float* Wq_inv = (const float*)d_in[7];
    const float* Wk_inv = (const float*)d_in[8];
    const float* Wv_inv = (const float*)d_in[9];
    const float* Wq_ev  = (const float*)d_in[10];
    const float* Wk_ev  = (const float*)d_in[11];
    const float* fi_rW1 = (const float*)d_in[12];
    const float* fi_rb1 = (const float*)d_in[13];
    const float* fi_rW2 = (const float*)d_in[14];
    const float* fi_rb2 = (const float*)d_in[15];
    const float* fi_eW1 = (const float*)d_in[16];
    const float* fi_eb1 = (const float*)d_in[17];
    const float* fi_eW2 = (const float*)d_in[18];
    const float* fi_eb2 = (const float*)d_in[19];
    const float* fe_rW1 = (const float*)d_in[20];
    const float* fe_rb1 = (const float*)d_in[21];
    const float* fe_rW2 = (const float*)d_in[22];
    const float* fe_rb2 = (const float*)d_in[23];
    const float* fe_eW1 = (const float*)d_in[24];
    const float* fe_eb1 = (const float*)d_in[25];
    const float* fe_eW2 = (const float*)d_in[26];
    const float* fe_eb2 = (const float*)d_in[27];
    const float* W_int  = (const float*)d_in[28];
    const float* b_int  = (const float*)d_in[29];
    float* out = (float*)d_out;

    cudaFuncSetAttribute(edge_kernel,
                         cudaFuncAttributeMaxDynamicSharedMemorySize,
                         (int)sizeof(ESm));

    zero_kernel<<<512, 256>>>();
    prep_kernel<<<(2 * NTT * KS2 * 64 + 255) / 256, 256>>>(
        fi_rW1, fi_rb1, fi_rW2, fi_rb2, fi_eW2, fi_eb2,
        fe_rW1, fe_rb1, fe_rW2, fe_rb2, fe_eW2, fe_eb2);
    node_proj_kernel<<<Nn / TNA, 256>>>(inv_features, Wq_inv, Wk_inv, Wv_inv,
                                        Wq_ev, Wk_ev);
    edge_kernel<<<GRID, 512, sizeof(ESm)>>>(
        ev_features, rbf, sh_vectors, cutoffs, senders, receivers,
        fi_eW1, fi_eb1, fe_eW1, fe_eb1);
    final_kernel<<<Nn / TNF, 256>>>(inv_features, ev_features, W_int, b_int, out);
}

// round 6
// speedup vs baseline: 3.5831x; 1.3891x over previous
#include <cuda_runtime.h>
#include <cuda_fp16.h>

// Problem constants
#define Nn   50000
#define Ee   400000
#define Rr   32
#define Ff   132
#define EVd  15

#define TE     64    // edges per tile
#define NTILES 6250  // Ee / TE
#define GRID   148   // persistent blocks (K_gemm)

#define NTT  18      // n-tiles per net (N padded 144)
#define KS2  12      // layer-2 k-steps (K padded 192)
#define AS   392     // h1 row stride (halves)
#define FS   296     // fw smem row stride (halves)
#define FSG  288     // fw gmem row stride (halves)
#define RS   40      // rbf smem row stride (halves)

// ---------------- device scratch ----------------
__device__ float g_q_inv[Nn * Ff];
__device__ float g_k_inv[Nn * Ff];
__device__ float g_v_inv[Nn * Ff];
__device__ float g_q_ev [Nn * Ff];
__device__ float g_k_ev [Nn * Ff];
__device__ float g_dinv [Nn * Ff];
__device__ float g_dev  [Nn * 16];          // padded to 16 for v4 reds
__device__ __align__(16) __half g_fw[Ee * FSG];  // filter weights, per-edge 288

// fragment-packed weights (compact, block-diagonal)
__device__ unsigned int g_W2sw[2 * NTT * KS2 * 64];
__device__ unsigned int g_W1sw[2 * NTT * 2 * 64];
__device__ float g_b1c[2 * 144];
__device__ float g_b2c[2 * 144];

__device__ __forceinline__ float silu_f(float x) {
    return x / (1.0f + __expf(-x));
}

__device__ __forceinline__ void mma16816(float c[4],
    unsigned a0, unsigned a1, unsigned a2, unsigned a3,
    unsigned b0, unsigned b1)
{
    asm volatile(
        "mma.sync.aligned.m16n8k16.row.col.f32.f16.f16.f32 "
        "{%0,%1,%2,%3},{%4,%5,%6,%7},{%8,%9},{%0,%1,%2,%3};\n"
        : "+f"(c[0]), "+f"(c[1]), "+f"(c[2]), "+f"(c[3])
        : "r"(a0), "r"(a1), "r"(a2), "r"(a3), "r"(b0), "r"(b1));
}

__device__ __forceinline__ void ldsm4(unsigned& r0, unsigned& r1,
                                      unsigned& r2, unsigned& r3,
                                      unsigned addr)
{
    asm volatile(
        "ldmatrix.sync.aligned.m8n8.x4.shared.b16 {%0,%1,%2,%3}, [%4];\n"
        : "=r"(r0), "=r"(r1), "=r"(r2), "=r"(r3) : "r"(addr));
}

__device__ __forceinline__ void red_add_v4(float* p, float a, float b,
                                           float c, float d)
{
    asm volatile("red.global.add.v4.f32 [%0], {%1,%2,%3,%4};"
                 :: "l"(p), "f"(a), "f"(b), "f"(c), "f"(d) : "memory");
}

// ---------------- zero accumulators ----------------
__global__ void zero_kernel() {
    int i = blockIdx.x * blockDim.x + threadIdx.x;
    int stride = gridDim.x * blockDim.x;
    for (int j = i; j < Nn * Ff; j += stride) g_dinv[j] = 0.0f;
    for (int j = i; j < Nn * 16; j += stride) g_dev[j] = 0.0f;
}

// ---------------- weight prep (compact block-diagonal packing) ----------------
__device__ __forceinline__ float W2com(int net, int k, int n,
    const float* fi_rW2, const float* fi_eW2,
    const float* fe_rW2, const float* fe_eW2)
{
    if (n >= 132) return 0.0f;
    if (k < 132)  return (net ? fe_rW2 : fi_rW2)[k * 132 + n];
    if (k >= 144 && k < 177) return (net ? fe_eW2 : fi_eW2)[(k - 144) * 132 + n];
    return 0.0f;
}

__global__ void prep_kernel(
    const float* __restrict__ fi_rW1, const float* __restrict__ fi_rb1,
    const float* __restrict__ fi_rW2, const float* __restrict__ fi_rb2,
    const float* __restrict__ fi_eW2, const float* __restrict__ fi_eb2,
    const float* __restrict__ fe_rW1, const float* __restrict__ fe_rb1,
    const float* __restrict__ fe_rW2, const float* __restrict__ fe_rb2,
    const float* __restrict__ fe_eW2, const float* __restrict__ fe_eb2)
{
    int i = blockIdx.x * blockDim.x + threadIdx.x;
    if (i < 2 * NTT * KS2 * 64) {
        int slot = i & 63;
        int blk = i >> 6;
        int ks = blk % KS2;
        int tmp = blk / KS2;
        int tt = tmp % NTT;
        int net = tmp / NTT;
        int lane = slot & 31;
        int gq = lane >> 2, t4 = lane & 3;
        int k = ks * 16 + ((slot & 32) ? 8 : 0) + 2 * t4;
        int n = tt * 8 + gq;
        __half2 v = __floats2half2_rn(
            W2com(net, k,     n, fi_rW2, fi_eW2, fe_rW2, fe_eW2),
            W2com(net, k + 1, n, fi_rW2, fi_eW2, fe_rW2, fe_eW2));
        ((__half2*)g_W2sw)[i] = v;
    }
    if (i < 2 * NTT * 2 * 64) {
        int slot = i & 63;
        int blk = i >> 6;
        int ks = blk & 1;
        int tmp = blk >> 1;
        int tt = tmp % NTT;
        int net = tmp / NTT;
        int lane = slot & 31;
        int gq = lane >> 2, t4 = lane & 3;
        int k = ks * 16 + ((slot & 32) ? 8 : 0) + 2 * t4;
        int n = tt * 8 + gq;
        const float* W = net ? fe_rW1 : fi_rW1;
        float v0 = (n < 132) ? W[k * 132 + n] : 0.0f;
        float v1 = (n < 132) ? W[(k + 1) * 132 + n] : 0.0f;
        ((__half2*)g_W1sw)[i] = __floats2half2_rn(v0, v1);
    }
    if (i < 2 * 144) {
        int net = i / 144, n = i % 144;
        float b1 = 0.0f, b2 = 0.0f;
        if (n < 132) {
            b1 = (net ? fe_rb1 : fi_rb1)[n];
            b2 = (net ? fe_rb2 : fi_rb2)[n] + (net ? fe_eb2 : fi_eb2)[n];
        }
        g_b1c[i] = b1;
        g_b2c[i] = b2;
    }
}

// ---------------- per-node projections ----------------
#define TNA 16
__global__ __launch_bounds__(256) void node_proj_kernel(
    const float* __restrict__ x,
    const float* __restrict__ Wq_inv, const float* __restrict__ Wk_inv,
    const float* __restrict__ Wv_inv, const float* __restrict__ Wq_ev,
    const float* __restrict__ Wk_ev)
{
    __shared__ float xs[TNA][Ff];
    const int n0 = blockIdx.x * TNA;
    for (int i = threadIdx.x; i < TNA * Ff; i += blockDim.x)
        xs[i / Ff][i % Ff] = x[n0 * Ff + i];
    __syncthreads();

    for (int f = threadIdx.x; f < 5 * Ff; f += blockDim.x) {
        const int m = f / Ff, c = f - m * Ff;
        const float* W;
        float* out;
        int D, h, e;
        bool dosilu = true;
        if (m < 3) {
            D = 33; h = c / 33; e = c - h * 33;
            W = (m == 0 ? Wq_inv : (m == 1 ? Wk_inv : Wv_inv)) + h * 33 * 33;
            out = (m == 0 ? g_q_inv : (m == 1 ? g_k_inv : g_v_inv));
            dosilu = (m != 2);
        } else {
            D = 44; h = c / 44; e = c - h * 44;
            W = (m == 3 ? Wq_ev : Wk_ev) + h * 44 * 44;
            out = (m == 3 ? g_q_ev : g_k_ev);
        }
        float acc[TNA];
#pragma unroll
        for (int t = 0; t < TNA; t++) acc[t] = 0.0f;
        const int xb = h * D;
        for (int d = 0; d < D; d++) {
            const float w = W[d * D + e];
#pragma unroll
            for (int t = 0; t < TNA; t++) acc[t] += xs[t][xb + d] * w;
        }
#pragma unroll
        for (int t = 0; t < TNA; t++) {
            float v = acc[t];
            if (dosilu) v = silu_f(v);
            out[(n0 + t) * Ff + c] = v;
        }
    }
}

// ---------------- K_gemm: persistent filter-net GEMM -> g_fw ----------------
struct GSm {
    unsigned sW2[2 * NTT * KS2 * 64];
    unsigned sW1[2 * NTT * 2 * 64];
    float sb1[2 * 144];
    float sb2[2 * 144];
    float sevW[2 * 99];
    float sevB[2 * 33];
    __half h1[TE * AS];
    __half fw[TE * FS];
    __half rbfs[TE * RS];
    float ev3[TE * 3];
    int   sidx[TE];
    int   ridx[TE];
};

__global__ __launch_bounds__(512, 1) void gemm_kernel(
    const float* __restrict__ ev_features,
    const float* __restrict__ rbf_g,
    const int*   __restrict__ senders,
    const int*   __restrict__ receivers,
    const float* __restrict__ fi_eW1, const float* __restrict__ fi_eb1,
    const float* __restrict__ fe_eW1, const float* __restrict__ fe_eb1)
{
    extern __shared__ char smraw[];
    GSm& sm = *reinterpret_cast<GSm*>(smraw);
    const int tid = threadIdx.x;
    const int w = tid >> 5, lane = tid & 31;
    const int gq = lane >> 2, t4 = lane & 3;
    const int net = w >> 3, wn = w & 7;
    const int ntile = (wn < 2) ? 3 : 2;
    const int l15 = lane & 15;
    const int lc8 = (lane & 16) ? 8 : 0;

    for (int i = tid; i < 2 * NTT * KS2 * 64; i += 512) sm.sW2[i] = g_W2sw[i];
    for (int i = tid; i < 2 * NTT * 2 * 64; i += 512)   sm.sW1[i] = g_W1sw[i];
    for (int i = tid; i < 2 * 144; i += 512) { sm.sb1[i] = g_b1c[i]; sm.sb2[i] = g_b2c[i]; }
    for (int i = tid; i < 2 * 99; i += 512)
        sm.sevW[i] = (i < 99) ? fi_eW1[i] : fe_eW1[i - 99];
    for (int i = tid; i < 2 * 33; i += 512)
        sm.sevB[i] = (i < 33) ? fi_eb1[i] : fe_eb1[i - 33];
    for (int i = tid; i < TE * AS / 2; i += 512)
        ((unsigned*)sm.h1)[i] = 0u;
    __syncthreads();

    const unsigned h1s  = (unsigned)__cvta_generic_to_shared(sm.h1);
    const unsigned rbss = (unsigned)__cvta_generic_to_shared(sm.rbfs);
    const unsigned a2base = h1s  + 2 * (l15 * AS + net * 192 + lc8);
    const unsigned a1base = rbss + 2 * (l15 * RS + lc8);

    for (int tile = blockIdx.x; tile < NTILES; tile += gridDim.x) {
        const int e0 = tile * TE;
        __syncthreads();

        if (tid < TE) {
            sm.sidx[tid] = senders[e0 + tid];
            sm.ridx[tid] = receivers[e0 + tid];
        }
        for (int i = tid; i < TE * Rr; i += 512) {
            int t = i >> 5, c = i & 31;
            sm.rbfs[t * RS + c] = __float2half(rbf_g[e0 * Rr + i]);
        }
        __syncthreads();

        if (tid < TE * 3) {
            int t = tid / 3, g3 = tid - 3 * t;
            int js = (g3 == 0) ? 0 : ((g3 == 1) ? 3 : 8);
            int je = (g3 == 0) ? 3 : ((g3 == 1) ? 8 : 15);
            const float* evs = ev_features + sm.sidx[t] * EVd;
            const float* evr = ev_features + sm.ridx[t] * EVd;
            float a = 0.0f;
            for (int j = js; j < je; j++) {
                float d = evs[j] - evr[j];
                a += d * d;
            }
            sm.ev3[t * 3 + g3] = a;
        }

        // layer 1 (rbf branch)
        {
            float acc[3][4][4];
#pragma unroll
            for (int j = 0; j < 3; j++) {
                if (j < ntile) {
                    int nidx = net * 144 + (wn + 8 * j) * 8 + 2 * t4;
                    float b0f = sm.sb1[nidx], b1f = sm.sb1[nidx + 1];
#pragma unroll
                    for (int m = 0; m < 4; m++) {
                        acc[j][m][0] = b0f; acc[j][m][1] = b1f;
                        acc[j][m][2] = b0f; acc[j][m][3] = b1f;
                    }
                }
            }
#pragma unroll
            for (int ks = 0; ks < 2; ks++) {
                unsigned a[4][4];
#pragma unroll
                for (int m = 0; m < 4; m++)
                    ldsm4(a[m][0], a[m][1], a[m][2], a[m][3],
                          a1base + 2 * (m * 16 * RS + ks * 16));
#pragma unroll
                for (int j = 0; j < 3; j++) {
                    if (j < ntile) {
                        int tt = wn + 8 * j;
                        int bi = ((net * NTT + tt) * 2 + ks) * 64;
                        unsigned b0 = sm.sW1[bi + lane], b1 = sm.sW1[bi + 32 + lane];
#pragma unroll
                        for (int m = 0; m < 4; m++)
                            mma16816(acc[j][m], a[m][0], a[m][1], a[m][2], a[m][3], b0, b1);
                    }
                }
            }
#pragma unroll
            for (int j = 0; j < 3; j++) {
                if (j < ntile) {
                    int col = net * 192 + (wn + 8 * j) * 8 + 2 * t4;
#pragma unroll
                    for (int m = 0; m < 4; m++) {
                        int r = m * 16 + gq;
                        *(__half2*)&sm.h1[r * AS + col] =
                            __floats2half2_rn(silu_f(acc[j][m][0]), silu_f(acc[j][m][1]));
                        *(__half2*)&sm.h1[(r + 8) * AS + col] =
                            __floats2half2_rn(silu_f(acc[j][m][2]), silu_f(acc[j][m][3]));
                    }
                }
            }
        }
        __syncthreads();

        // layer 1 ev branch
        for (int i = tid; i < TE * 66; i += 512) {
            int t = i / 66, c = i - 66 * t;
            int nb = (c >= 33);
            int cc = c - 33 * nb;
            float v = sm.sevB[nb * 33 + cc]
                    + sm.ev3[t * 3 + 0] * sm.sevW[nb * 99 + cc]
                    + sm.ev3[t * 3 + 1] * sm.sevW[nb * 99 + 33 + cc]
                    + sm.ev3[t * 3 + 2] * sm.sevW[nb * 99 + 66 + cc];
            sm.h1[t * AS + nb * 192 + 144 + cc] = __float2half(silu_f(v));
        }
        __syncthreads();

        // layer 2
        {
            float acc[3][4][4];
#pragma unroll
            for (int j = 0; j < 3; j++) {
                if (j < ntile) {
                    int nidx = net * 144 + (wn + 8 * j) * 8 + 2 * t4;
                    float b0f = sm.sb2[nidx], b1f = sm.sb2[nidx + 1];
#pragma unroll
                    for (int m = 0; m < 4; m++) {
                        acc[j][m][0] = b0f; acc[j][m][1] = b1f;
                        acc[j][m][2] = b0f; acc[j][m][3] = b1f;
                    }
                }
            }
#pragma unroll 2
            for (int ks = 0; ks < KS2; ks++) {
                unsigned a[4][4];
#pragma unroll
                for (int m = 0; m < 4; m++)
                    ldsm4(a[m][0], a[m][1], a[m][2], a[m][3],
                          a2base + 2 * (m * 16 * AS + ks * 16));
#pragma unroll
                for (int j = 0; j < 3; j++) {
                    if (j < ntile) {
                        int tt = wn + 8 * j;
                        int bi = ((net * NTT + tt) * KS2 + ks) * 64;
                        unsigned b0 = sm.sW2[bi + lane], b1 = sm.sW2[bi + 32 + lane];
#pragma unroll
                        for (int m = 0; m < 4; m++)
                            mma16816(acc[j][m], a[m][0], a[m][1], a[m][2], a[m][3], b0, b1);
                    }
                }
            }
#pragma unroll
            for (int j = 0; j < 3; j++) {
                if (j < ntile) {
                    int col = net * 144 + (wn + 8 * j) * 8 + 2 * t4;
#pragma unroll
                    for (int m = 0; m < 4; m++) {
                        int r = m * 16 + gq;
                        *(__half2*)&sm.fw[r * FS + col] =
                            __floats2half2_rn(acc[j][m][0], acc[j][m][1]);
                        *(__half2*)&sm.fw[(r + 8) * FS + col] =
                            __floats2half2_rn(acc[j][m][2], acc[j][m][3]);
                    }
                }
            }
        }
        __syncthreads();

        // coalesced fw writeout: 64 rows x 36 uint4
        {
            uint4* dst = (uint4*)(g_fw + (size_t)e0 * FSG);
            for (int i = tid; i < TE * (FSG / 8); i += 512) {
                int r = i / (FSG / 8), c = i - r * (FSG / 8);
                dst[i] = *(const uint4*)&sm.fw[r * FS + c * 8];
            }
        }
    }
}

// ---------------- K_att: attention logits + scatter (high occupancy) ----------------
struct __align__(16) ASm {
    __half fwa[TE * FSG];   // 36864 B
    float  al [TE * 8];     //  2048 B
    float  cut[TE];
    int    sidx[TE];
    int    ridx[TE];
};

__global__ __launch_bounds__(256) void att_kernel(
    const float* __restrict__ cutoffs,
    const int*   __restrict__ senders,
    const int*   __restrict__ receivers,
    const float* __restrict__ sh)
{
    __shared__ ASm sm;
    const int tid = threadIdx.x;
    const int w = tid >> 5, lane = tid & 31;
    const int e0 = blockIdx.x * TE;

    if (tid < TE) {
        sm.sidx[tid] = senders[e0 + tid];
        sm.ridx[tid] = receivers[e0 + tid];
        sm.cut[tid]  = cutoffs[e0 + tid];
    }
    {
        const uint4* src = (const uint4*)(g_fw + (size_t)e0 * FSG);
        uint4* dst = (uint4*)sm.fwa;
        for (int i = tid; i < TE * (FSG / 8); i += 256)
            dst[i] = src[i];
    }
    __syncthreads();

    // alpha: 448 tasks over 8 warps, 2-way interleaved
    {
        const float INVN = 0.17407765595569785f;  // 1/sqrt(33)
        const float INVE = 0.15075567228888181f;  // 1/sqrt(44)
        for (int p = 0; p < 28; p++) {
            int taskA = w + 8 * (2 * p);
            int taskB = w + 8 * (2 * p + 1);
            int tA = taskA / 7, hA = taskA - 7 * tA;
            int tB = taskB / 7, hB = taskB - 7 * tB;

            const float *qA, *kA; int fbA, DA; float nmA;
            if (hA < 4) { qA = g_q_inv + sm.ridx[tA] * Ff + hA * 33;
                          kA = g_k_inv + sm.sidx[tA] * Ff + hA * 33;
                          fbA = tA * FSG + hA * 33; DA = 33; nmA = INVN; }
            else        { int hh = hA - 4;
                          qA = g_q_ev + sm.ridx[tA] * Ff + hh * 44;
                          kA = g_k_ev + sm.sidx[tA] * Ff + hh * 44;
                          fbA = tA * FSG + 144 + hh * 44; DA = 44; nmA = INVE; }
            const float *qB, *kB; int fbB, DB; float nmB;
            if (hB < 4) { qB = g_q_inv + sm.ridx[tB] * Ff + hB * 33;
                          kB = g_k_inv + sm.sidx[tB] * Ff + hB * 33;
                          fbB = tB * FSG + hB * 33; DB = 33; nmB = INVN; }
            else        { int hh = hB - 4;
                          qB = g_q_ev + sm.ridx[tB] * Ff + hh * 44;
                          kB = g_k_ev + sm.sidx[tB] * Ff + hh * 44;
                          fbB = tB * FSG + 144 + hh * 44; DB = 44; nmB = INVE; }

            float aA = qA[lane] * kA[lane] * __half2float(sm.fwa[fbA + lane]);
            float aB = qB[lane] * kB[lane] * __half2float(sm.fwa[fbB + lane]);
            int d1 = lane + 32;
            if (d1 < DA) aA += qA[d1] * kA[d1] * __half2float(sm.fwa[fbA + d1]);
            if (d1 < DB) aB += qB[d1] * kB[d1] * __half2float(sm.fwa[fbB + d1]);
#pragma unroll
            for (int s = 16; s > 0; s >>= 1) {
                aA += __shfl_xor_sync(0xFFFFFFFFu, aA, s);
                aB += __shfl_xor_sync(0xFFFFFFFFu, aB, s);
            }
            if (lane == 0) {
                sm.al[tA * 8 + hA] = aA * nmA * sm.cut[tA];
                sm.al[tB * 8 + hB] = aB * nmB * sm.cut[tB];
            }
        }
    }
    __syncthreads();

    // scatter: inv messages via 128-bit reductions (33 float4 per edge)
    for (int i = tid; i < TE * 33; i += 256) {
        int t = i / 33, c4 = i - 33 * t;
        int f0 = 4 * c4;
        const float4 v = *(const float4*)(g_v_inv + sm.sidx[t] * Ff + f0);
        float r0 = sm.al[t * 8 + (f0 + 0) / 33] * v.x;
        float r1 = sm.al[t * 8 + (f0 + 1) / 33] * v.y;
        float r2 = sm.al[t * 8 + (f0 + 2) / 33] * v.z;
        float r3 = sm.al[t * 8 + (f0 + 3) / 33] * v.w;
        red_add_v4(g_dinv + sm.ridx[t] * Ff + f0, r0, r1, r2, r3);
    }
    // scatter: ev messages (4 float4 per edge, padded row of 16)
    for (int i = tid; i < TE * 4; i += 256) {
        int t = i >> 2, q4 = i & 3;
        int j0 = 4 * q4;
        float r[4];
#pragma unroll
        for (int u = 0; u < 4; u++) {
            int j = j0 + u;
            if (j < EVd) {
                int gg = (j < 3) ? 0 : ((j < 8) ? 1 : 2);
                r[u] = sm.al[t * 8 + 4 + gg] * sh[(e0 + t) * EVd + j];
            } else r[u] = 0.0f;
        }
        red_add_v4(g_dev + sm.ridx[t] * 16 + j0, r[0], r[1], r[2], r[3]);
    }
}

// ---------------- final node update ----------------
#define TNF 8
__global__ __launch_bounds__(256) void final_kernel(
    const float* __restrict__ inv_features,
    const float* __restrict__ ev_features,
    const float* __restrict__ W_int,
    const float* __restrict__ b_int,
    float* __restrict__ out)
{
    __shared__ float cat_s[TNF][136];
    __shared__ float ev1_s[TNF][EVd];
    __shared__ float tb_s[TNF][3];
    const int n0 = blockIdx.x * TNF;

    for (int i = threadIdx.x; i < TNF * Ff; i += blockDim.x) {
        const int t = i / Ff, f = i - Ff * t;
        cat_s[t][f] = inv_features[(n0 + t) * Ff + f] + g_dinv[(n0 + t) * Ff + f];
    }
    for (int i = threadIdx.x; i < TNF * EVd; i += blockDim.x) {
        const int t = i / EVd, j = i - EVd * t;
        ev1_s[t][j] = ev_features[(n0 + t) * EVd + j] + g_dev[(n0 + t) * 16 + j];
    }
    __syncthreads();
    for (int i = threadIdx.x; i < TNF * 3; i += blockDim.x) {
        const int t = i / 3, g = i - 3 * t;
        const int js = (g == 0) ? 0 : ((g == 1) ? 3 : 8);
        const int je = (g == 0) ? 3 : ((g == 1) ? 8 : 15);
        float a = 0.0f;
        for (int j = js; j < je; j++) {
            const float v = ev1_s[t][j];
            a += v * v;
        }
        cat_s[t][132 + g] = a;
    }
    __syncthreads();

    if (threadIdx.x < 135) {
        const int f = threadIdx.x;
        float acc[TNF];
#pragma unroll
        for (int t = 0; t < TNF; t++) acc[t] = b_int[f];
        for (int k = 0; k < 135; k++) {
            const float w = W_int[k * 135 + f];
#pragma unroll
            for (int t = 0; t < TNF; t++) acc[t] += cat_s[t][k] * w;
        }
        if (f < 132) {
#pragma unroll
            for (int t = 0; t < TNF; t++)
                out[(n0 + t) * Ff + f] = cat_s[t][f] + acc[t];
        } else {
#pragma unroll
            for (int t = 0; t < TNF; t++) tb_s[t][f - 132] = acc[t];
        }
    }
    __syncthreads();

    float* out_ev = out + Nn * Ff;
    for (int i = threadIdx.x; i < TNF * EVd; i += blockDim.x) {
        const int t = i / EVd, j = i - EVd * t;
        const int g = (j < 3) ? 0 : ((j < 8) ? 1 : 2);
        out_ev[(n0 + t) * EVd + j] = ev1_s[t][j] * (1.0f + tb_s[t][g]);
    }
}

// ---------------- launch ----------------
extern "C" void kernel_launch(void* const* d_in, const int* in_sizes, int n_in,
                              void* d_out, int out_size)
{
    const float* inv_features = (const float*)d_in[0];
    const float* ev_features  = (const float*)d_in[1];
    const float* rbf          = (const float*)d_in[2];
    const float* sh_vectors   = (const float*)d_in[3];
    const float* cutoffs      = (const float*)d_in[4];
    const int*   senders      = (const int*)d_in[5];
    const int*   receivers    = (const int*)d_in[6];
    const float* Wq_inv = (const float*)d_in[7];
    const float* Wk_inv = (const float*)d_in[8];
    const float* Wv_inv = (const float*)d_in[9];
    const float* Wq_ev  = (const float*)d_in[10];
    const float* Wk_ev  = (const float*)d_in[11];
    const float* fi_rW1 = (const float*)d_in[12];
    const float* fi_rb1 = (const float*)d_in[13];
    const float* fi_rW2 = (const float*)d_in[14];
    const float* fi_rb2 = (const float*)d_in[15];
    const float* fi_eW1 = (const float*)d_in[16];
    const float* fi_eb1 = (const float*)d_in[17];
    const float* fi_eW2 = (const float*)d_in[18];
    const float* fi_eb2 = (const float*)d_in[19];
    const float* fe_rW1 = (const float*)d_in[20];
    const float* fe_rb1 = (const float*)d_in[21];
    const float* fe_rW2 = (const float*)d_in[22];
    const float* fe_rb2 = (const float*)d_in[23];
    const float* fe_eW1 = (const float*)d_in[24];
    const float* fe_eb1 = (const float*)d_in[25];
    const float* fe_eW2 = (const float*)d_in[26];
    const float* fe_eb2 = (const float*)d_in[27];
    const float* W_int  = (const float*)d_in[28];
    const float* b_int  = (const float*)d_in[29];
    float* out = (float*)d_out;

    cudaFuncSetAttribute(gemm_kernel,
                         cudaFuncAttributeMaxDynamicSharedMemorySize,
                         (int)sizeof(GSm));

    zero_kernel<<<512, 256>>>();
    prep_kernel<<<(2 * NTT * KS2 * 64 + 255) / 256, 256>>>(
        fi_rW1, fi_rb1, fi_rW2, fi_rb2, fi_eW2, fi_eb2,
        fe_rW1, fe_rb1, fe_rW2, fe_rb2, fe_eW2, fe_eb2);
    gemm_kernel<<<GRID, 512, sizeof(GSm)>>>(
        ev_features, rbf, senders, receivers,
        fi_eW1, fi_eb1, fe_eW1, fe_eb1);
    node_proj_kernel<<<Nn / TNA, 256>>>(inv_features, Wq_inv, Wk_inv, Wv_inv,
                                        Wq_ev, Wk_ev);
    att_kernel<<<NTILES, 256>>>(cutoffs, senders, receivers, sh_vectors);
    final_kernel<<<Nn / TNF, 256>>>(inv_features, ev_features, W_int, b_int, out);
}

// round 8
// speedup vs baseline: 3.7220x; 1.0388x over previous
#include <cuda_runtime.h>
#include <cuda_fp16.h>

// Problem constants
#define Nn   50000
#define Ee   400000
#define Rr   32
#define Ff   132
#define EVd  15

#define TE     64    // edges per tile
#define NTILES 6250  // Ee / TE
#define GRID   148   // persistent blocks (K_gemm)

#define NTT  18      // n-tiles per net (N padded 144)
#define KS2  12      // layer-2 k-steps (K padded 192)
#define AS   392     // h1 row stride (halves)
#define FS   296     // fw smem row stride (halves)
#define FSG  288     // fw gmem row stride (halves)
#define RS   40      // rbf smem row stride (halves)

// ---------------- device scratch ----------------
__device__ float g_q_inv[Nn * Ff];
__device__ float g_k_inv[Nn * Ff];
__device__ float g_v_inv[Nn * Ff];
__device__ float g_q_ev [Nn * Ff];
__device__ float g_k_ev [Nn * Ff];
__device__ float g_dinv [Nn * Ff];
__device__ float g_dev  [Nn * 16];          // padded to 16 for v4 reds
__device__ __align__(16) __half g_fw[Ee * FSG];  // filter weights, per-edge 288

// fragment-packed weights (compact, block-diagonal)
__device__ unsigned int g_W2sw[2 * NTT * KS2 * 64];
__device__ unsigned int g_W1sw[2 * NTT * 2 * 64];
__device__ float g_b1c[2 * 144];
__device__ float g_b2c[2 * 144];

__device__ __forceinline__ float silu_f(float x) {
    return x / (1.0f + __expf(-x));
}

__device__ __forceinline__ void mma16816(float c[4],
    unsigned a0, unsigned a1, unsigned a2, unsigned a3,
    unsigned b0, unsigned b1)
{
    asm volatile(
        "mma.sync.aligned.m16n8k16.row.col.f32.f16.f16.f32 "
        "{%0,%1,%2,%3},{%4,%5,%6,%7},{%8,%9},{%0,%1,%2,%3};\n"
        : "+f"(c[0]), "+f"(c[1]), "+f"(c[2]), "+f"(c[3])
        : "r"(a0), "r"(a1), "r"(a2), "r"(a3), "r"(b0), "r"(b1));
}

__device__ __forceinline__ void ldsm4(unsigned& r0, unsigned& r1,
                                      unsigned& r2, unsigned& r3,
                                      unsigned addr)
{
    asm volatile(
        "ldmatrix.sync.aligned.m8n8.x4.shared.b16 {%0,%1,%2,%3}, [%4];\n"
        : "=r"(r0), "=r"(r1), "=r"(r2), "=r"(r3) : "r"(addr));
}

__device__ __forceinline__ void red_add_v4(float* p, float a, float b,
                                           float c, float d)
{
    asm volatile("red.global.add.v4.f32 [%0], {%1,%2,%3,%4};"
                 :: "l"(p), "f"(a), "f"(b), "f"(c), "f"(d) : "memory");
}

// ---------------- zero accumulators ----------------
__global__ void zero_kernel() {
    int i = blockIdx.x * blockDim.x + threadIdx.x;
    int stride = gridDim.x * blockDim.x;
    for (int j = i; j < Nn * Ff; j += stride) g_dinv[j] = 0.0f;
    for (int j = i; j < Nn * 16; j += stride) g_dev[j] = 0.0f;
}

// ---------------- weight prep (compact block-diagonal packing) ----------------
__device__ __forceinline__ float W2com(int net, int k, int n,
    const float* fi_rW2, const float* fi_eW2,
    const float* fe_rW2, const float* fe_eW2)
{
    if (n >= 132) return 0.0f;
    if (k < 132)  return (net ? fe_rW2 : fi_rW2)[k * 132 + n];
    if (k >= 144 && k < 177) return (net ? fe_eW2 : fi_eW2)[(k - 144) * 132 + n];
    return 0.0f;
}

__global__ void prep_kernel(
    const float* __restrict__ fi_rW1, const float* __restrict__ fi_rb1,
    const float* __restrict__ fi_rW2, const float* __restrict__ fi_rb2,
    const float* __restrict__ fi_eW2, const float* __restrict__ fi_eb2,
    const float* __restrict__ fe_rW1, const float* __restrict__ fe_rb1,
    const float* __restrict__ fe_rW2, const float* __restrict__ fe_rb2,
    const float* __restrict__ fe_eW2, const float* __restrict__ fe_eb2)
{
    int i = blockIdx.x * blockDim.x + threadIdx.x;
    if (i < 2 * NTT * KS2 * 64) {
        int slot = i & 63;
        int blk = i >> 6;
        int ks = blk % KS2;
        int tmp = blk / KS2;
        int tt = tmp % NTT;
        int net = tmp / NTT;
        int lane = slot & 31;
        int gq = lane >> 2, t4 = lane & 3;
        int k = ks * 16 + ((slot & 32) ? 8 : 0) + 2 * t4;
        int n = tt * 8 + gq;
        __half2 v = __floats2half2_rn(
            W2com(net, k,     n, fi_rW2, fi_eW2, fe_rW2, fe_eW2),
            W2com(net, k + 1, n, fi_rW2, fi_eW2, fe_rW2, fe_eW2));
        ((__half2*)g_W2sw)[i] = v;
    }
    if (i < 2 * NTT * 2 * 64) {
        int slot = i & 63;
        int blk = i >> 6;
        int ks = blk & 1;
        int tmp = blk >> 1;
        int tt = tmp % NTT;
        int net = tmp / NTT;
        int lane = slot & 31;
        int gq = lane >> 2, t4 = lane & 3;
        int k = ks * 16 + ((slot & 32) ? 8 : 0) + 2 * t4;
        int n = tt * 8 + gq;
        const float* W = net ? fe_rW1 : fi_rW1;
        float v0 = (n < 132) ? W[k * 132 + n] : 0.0f;
        float v1 = (n < 132) ? W[(k + 1) * 132 + n] : 0.0f;
        ((__half2*)g_W1sw)[i] = __floats2half2_rn(v0, v1);
    }
    if (i < 2 * 144) {
        int net = i / 144, n = i % 144;
        float b1 = 0.0f, b2 = 0.0f;
        if (n < 132) {
            b1 = (net ? fe_rb1 : fi_rb1)[n];
            b2 = (net ? fe_rb2 : fi_rb2)[n] + (net ? fe_eb2 : fi_eb2)[n];
        }
        g_b1c[i] = b1;
        g_b2c[i] = b2;
    }
}

// ---------------- per-node projections (transposed smem, float4 broadcast) ----------------
#define TNA 16
#define XSW 20   // xs row stride (floats): 80B rows -> 16B-aligned float4 loads
__global__ __launch_bounds__(256) void node_proj_kernel(
    const float* __restrict__ x,
    const float* __restrict__ Wq_inv, const float* __restrict__ Wk_inv,
    const float* __restrict__ Wv_inv, const float* __restrict__ Wq_ev,
    const float* __restrict__ Wk_ev)
{
    __shared__ __align__(16) float xs[Ff * XSW];
    const int n0 = blockIdx.x * TNA;
    for (int i = threadIdx.x; i < TNA * Ff; i += 256) {
        int t = i / Ff, f = i - t * Ff;
        xs[f * XSW + t] = x[n0 * Ff + i];
    }
    __syncthreads();

    for (int idx = threadIdx.x; idx < 5 * Ff; idx += 256) {
        const int m = idx / Ff, c = idx - m * Ff;
        const float* W;
        float* out;
        int D, h, e;
        bool dosilu = true;
        if (m < 3) {
            D = 33; h = c / 33; e = c - h * 33;
            W = (m == 0 ? Wq_inv : (m == 1 ? Wk_inv : Wv_inv)) + h * 33 * 33;
            out = (m == 0 ? g_q_inv : (m == 1 ? g_k_inv : g_v_inv));
            dosilu = (m != 2);
        } else {
            D = 44; h = c / 44; e = c - h * 44;
            W = (m == 3 ? Wq_ev : Wk_ev) + h * 44 * 44;
            out = (m == 3 ? g_q_ev : g_k_ev);
        }
        float4 a0 = make_float4(0.f, 0.f, 0.f, 0.f);
        float4 a1 = a0, a2 = a0, a3 = a0;
        const int xb = h * D;
        for (int d = 0; d < D; d++) {
            const float w = W[d * D + e];
            const float4* xr = (const float4*)&xs[(xb + d) * XSW];
            const float4 x0 = xr[0], x1 = xr[1], x2 = xr[2], x3 = xr[3];
            a0.x += x0.x * w; a0.y += x0.y * w; a0.z += x0.z * w; a0.w += x0.w * w;
            a1.x += x1.x * w; a1.y += x1.y * w; a1.z += x1.z * w; a1.w += x1.w * w;
            a2.x += x2.x * w; a2.y += x2.y * w; a2.z += x2.z * w; a2.w += x2.w * w;
            a3.x += x3.x * w; a3.y += x3.y * w; a3.z += x3.z * w; a3.w += x3.w * w;
        }
        float acc[TNA] = {a0.x, a0.y, a0.z, a0.w, a1.x, a1.y, a1.z, a1.w,
                          a2.x, a2.y, a2.z, a2.w, a3.x, a3.y, a3.z, a3.w};
#pragma unroll
        for (int t = 0; t < TNA; t++) {
            float v = acc[t];
            if (dosilu) v = silu_f(v);
            out[(n0 + t) * Ff + c] = v;
        }
    }
}

// ---------------- K_gemm: persistent filter-net GEMM -> g_fw ----------------
struct GSm {
    unsigned sW2[2 * NTT * KS2 * 64];
    unsigned sW1[2 * NTT * 2 * 64];
    float sb1[2 * 144];
    float sb2[2 * 144];
    float sevW[2 * 99];
    float sevB[2 * 33];
    __half h1[TE * AS];
    __half fw[TE * FS];
    __half rbfs[TE * RS];
    float ev3[TE * 3];
    int   sidx[TE];
    int   ridx[TE];
};

__global__ __launch_bounds__(512, 1) void gemm_kernel(
    const float* __restrict__ ev_features,
    const float* __restrict__ rbf_g,
    const int*   __restrict__ senders,
    const int*   __restrict__ receivers,
    const float* __restrict__ fi_eW1, const float* __restrict__ fi_eb1,
    const float* __restrict__ fe_eW1, const float* __restrict__ fe_eb1)
{
    extern __shared__ char smraw[];
    GSm& sm = *reinterpret_cast<GSm*>(smraw);
    const int tid = threadIdx.x;
    const int w = tid >> 5, lane = tid & 31;
    const int gq = lane >> 2, t4 = lane & 3;
    const int net = w >> 3, wn = w & 7;
    const int ntile = (wn < 2) ? 3 : 2;
    const int l15 = lane & 15;
    const int lc8 = (lane & 16) ? 8 : 0;

    for (int i = tid; i < 2 * NTT * KS2 * 64; i += 512) sm.sW2[i] = g_W2sw[i];
    for (int i = tid; i < 2 * NTT * 2 * 64; i += 512)   sm.sW1[i] = g_W1sw[i];
    for (int i = tid; i < 2 * 144; i += 512) { sm.sb1[i] = g_b1c[i]; sm.sb2[i] = g_b2c[i]; }
    for (int i = tid; i < 2 * 99; i += 512)
        sm.sevW[i] = (i < 99) ? fi_eW1[i] : fe_eW1[i - 99];
    for (int i = tid; i < 2 * 33; i += 512)
        sm.sevB[i] = (i < 33) ? fi_eb1[i] : fe_eb1[i - 33];
    for (int i = tid; i < TE * AS / 2; i += 512)
        ((unsigned*)sm.h1)[i] = 0u;
    __syncthreads();

    const unsigned h1s  = (unsigned)__cvta_generic_to_shared(sm.h1);
    const unsigned rbss = (unsigned)__cvta_generic_to_shared(sm.rbfs);
    const unsigned a2base = h1s  + 2 * (l15 * AS + net * 192 + lc8);
    const unsigned a1base = rbss + 2 * (l15 * RS + lc8);

    for (int tile = blockIdx.x; tile < NTILES; tile += gridDim.x) {
        const int e0 = tile * TE;
        __syncthreads();

        if (tid < TE) {
            sm.sidx[tid] = senders[e0 + tid];
            sm.ridx[tid] = receivers[e0 + tid];
        }
        for (int i = tid; i < TE * Rr; i += 512) {
            int t = i >> 5, c = i & 31;
            sm.rbfs[t * RS + c] = __float2half(rbf_g[e0 * Rr + i]);
        }
        __syncthreads();

        if (tid < TE * 3) {
            int t = tid / 3, g3 = tid - 3 * t;
            int js = (g3 == 0) ? 0 : ((g3 == 1) ? 3 : 8);
            int je = (g3 == 0) ? 3 : ((g3 == 1) ? 8 : 15);
            const float* evs = ev_features + sm.sidx[t] * EVd;
            const float* evr = ev_features + sm.ridx[t] * EVd;
            float a = 0.0f;
            for (int j = js; j < je; j++) {
                float d = evs[j] - evr[j];
                a += d * d;
            }
            sm.ev3[t * 3 + g3] = a;
        }

        // layer 1 (rbf branch)
        {
            float acc[3][4][4];
#pragma unroll
            for (int j = 0; j < 3; j++) {
                if (j < ntile) {
                    int nidx = net * 144 + (wn + 8 * j) * 8 + 2 * t4;
                    float b0f = sm.sb1[nidx], b1f = sm.sb1[nidx + 1];
#pragma unroll
                    for (int m = 0; m < 4; m++) {
                        acc[j][m][0] = b0f; acc[j][m][1] = b1f;
                        acc[j][m][2] = b0f; acc[j][m][3] = b1f;
                    }
                }
            }
#pragma unroll
            for (int ks = 0; ks < 2; ks++) {
                unsigned a[4][4];
#pragma unroll
                for (int m = 0; m < 4; m++)
                    ldsm4(a[m][0], a[m][1], a[m][2], a[m][3],
                          a1base + 2 * (m * 16 * RS + ks * 16));
#pragma unroll
                for (int j = 0; j < 3; j++) {
                    if (j < ntile) {
                        int tt = wn + 8 * j;
                        int bi = ((net * NTT + tt) * 2 + ks) * 64;
                        unsigned b0 = sm.sW1[bi + lane], b1 = sm.sW1[bi + 32 + lane];
#pragma unroll
                        for (int m = 0; m < 4; m++)
                            mma16816(acc[j][m], a[m][0], a[m][1], a[m][2], a[m][3], b0, b1);
                    }
                }
            }
#pragma unroll
            for (int j = 0; j < 3; j++) {
                if (j < ntile) {
                    int col = net * 192 + (wn + 8 * j) * 8 + 2 * t4;
#pragma unroll
                    for (int m = 0; m < 4; m++) {
                        int r = m * 16 + gq;
                        *(__half2*)&sm.h1[r * AS + col] =
                            __floats2half2_rn(silu_f(acc[j][m][0]), silu_f(acc[j][m][1]));
                        *(__half2*)&sm.h1[(r + 8) * AS + col] =
                            __floats2half2_rn(silu_f(acc[j][m][2]), silu_f(acc[j][m][3]));
                    }
                }
            }
        }
        __syncthreads();

        // layer 1 ev branch
        for (int i = tid; i < TE * 66; i += 512) {
            int t = i / 66, c = i - 66 * t;
            int nb = (c >= 33);
            int cc = c - 33 * nb;
            float v = sm.sevB[nb * 33 + cc]
                    + sm.ev3[t * 3 + 0] * sm.sevW[nb * 99 + cc]
                    + sm.ev3[t * 3 + 1] * sm.sevW[nb * 99 + 33 + cc]
                    + sm.ev3[t * 3 + 2] * sm.sevW[nb * 99 + 66 + cc];
            sm.h1[t * AS + nb * 192 + 144 + cc] = __float2half(silu_f(v));
        }
        __syncthreads();

        // layer 2
        {
            float acc[3][4][4];
#pragma unroll
            for (int j = 0; j < 3; j++) {
                if (j < ntile) {
                    int nidx = net * 144 + (wn + 8 * j) * 8 + 2 * t4;
                    float b0f = sm.sb2[nidx], b1f = sm.sb2[nidx + 1];
#pragma unroll
                    for (int m = 0; m < 4; m++) {
                        acc[j][m][0] = b0f; acc[j][m][1] = b1f;
                        acc[j][m][2] = b0f; acc[j][m][3] = b1f;
                    }
                }
            }
#pragma unroll 2
            for (int ks = 0; ks < KS2; ks++) {
                unsigned a[4][4];
#pragma unroll
                for (int m = 0; m < 4; m++)
                    ldsm4(a[m][0], a[m][1], a[m][2], a[m][3],
                          a2base + 2 * (m * 16 * AS + ks * 16));
#pragma unroll
                for (int j = 0; j < 3; j++) {
                    if (j < ntile) {
                        int tt = wn + 8 * j;
                        int bi = ((net * NTT + tt) * KS2 + ks) * 64;
                        unsigned b0 = sm.sW2[bi + lane], b1 = sm.sW2[bi + 32 + lane];
#pragma unroll
                        for (int m = 0; m < 4; m++)
                            mma16816(acc[j][m], a[m][0], a[m][1], a[m][2], a[m][3], b0, b1);
                    }
                }
            }
#pragma unroll
            for (int j = 0; j < 3; j++) {
                if (j < ntile) {
                    int col = net * 144 + (wn + 8 * j) * 8 + 2 * t4;
#pragma unroll
                    for (int m = 0; m < 4; m++) {
                        int r = m * 16 + gq;
                        *(__half2*)&sm.fw[r * FS + col] =
                            __floats2half2_rn(acc[j][m][0], acc[j][m][1]);
                        *(__half2*)&sm.fw[(r + 8) * FS + col] =
                            __floats2half2_rn(acc[j][m][2], acc[j][m][3]);
                    }
                }
            }
        }
        __syncthreads();

        // coalesced fw writeout: 64 rows x 36 uint4
        {
            uint4* dst = (uint4*)(g_fw + (size_t)e0 * FSG);
            for (int i = tid; i < TE * (FSG / 8); i += 512) {
                int r = i / (FSG / 8), c = i - r * (FSG / 8);
                dst[i] = *(const uint4*)&sm.fw[r * FS + c * 8];
            }
        }
    }
}

// ---------------- K_att: attention logits + scatter (high occupancy) ----------------
struct __align__(16) ASm {
    __half fwa[TE * FSG];   // 36864 B
    float  al [TE * 8];     //  2048 B
    float  cut[TE];
    int    sidx[TE];
    int    ridx[TE];
};

__global__ __launch_bounds__(256) void att_kernel(
    const float* __restrict__ cutoffs,
    const int*   __restrict__ senders,
    const int*   __restrict__ receivers,
    const float* __restrict__ sh)
{
    __shared__ ASm sm;
    const int tid = threadIdx.x;
    const int w = tid >> 5, lane = tid & 31;
    const int e0 = blockIdx.x * TE;

    if (tid < TE) {
        sm.sidx[tid] = senders[e0 + tid];
        sm.ridx[tid] = receivers[e0 + tid];
        sm.cut[tid]  = cutoffs[e0 + tid];
    }
    {
        const uint4* src = (const uint4*)(g_fw + (size_t)e0 * FSG);
        uint4* dst = (uint4*)sm.fwa;
        for (int i = tid; i < TE * (FSG / 8); i += 256)
            dst[i] = src[i];
    }
    __syncthreads();

    // alpha: 448 tasks over 8 warps, 2-way interleaved
    {
        const float INVN = 0.17407765595569785f;  // 1/sqrt(33)
        const float INVE = 0.15075567228888181f;  // 1/sqrt(44)
        for (int p = 0; p < 28; p++) {
            int taskA = w + 8 * (2 * p);
            int taskB = w + 8 * (2 * p + 1);
            int tA = taskA / 7, hA = taskA - 7 * tA;
            int tB = taskB / 7, hB = taskB - 7 * tB;

            const float *qA, *kA; int fbA, DA; float nmA;
            if (hA < 4) { qA = g_q_inv + sm.ridx[tA] * Ff + hA * 33;
                          kA = g_k_inv + sm.sidx[tA] * Ff + hA * 33;
                          fbA = tA * FSG + hA * 33; DA = 33; nmA = INVN; }
            else        { int hh = hA - 4;
                          qA = g_q_ev + sm.ridx[tA] * Ff + hh * 44;
                          kA = g_k_ev + sm.sidx[tA] * Ff + hh * 44;
                          fbA = tA * FSG + 144 + hh * 44; DA = 44; nmA = INVE; }
            const float *qB, *kB; int fbB, DB; float nmB;
            if (hB < 4) { qB = g_q_inv + sm.ridx[tB] * Ff + hB * 33;
                          kB = g_k_inv + sm.sidx[tB] * Ff + hB * 33;
                          fbB = tB * FSG + hB * 33; DB = 33; nmB = INVN; }
            else        { int hh = hB - 4;
                          qB = g_q_ev + sm.ridx[tB] * Ff + hh * 44;
                          kB = g_k_ev + sm.sidx[tB] * Ff + hh * 44;
                          fbB = tB * FSG + 144 + hh * 44; DB = 44; nmB = INVE; }

            float aA = qA[lane] * kA[lane] * __half2float(sm.fwa[fbA + lane]);
            float aB = qB[lane] * kB[lane] * __half2float(sm.fwa[fbB + lane]);
            int d1 = lane + 32;
            if (d1 < DA) aA += qA[d1] * kA[d1] * __half2float(sm.fwa[fbA + d1]);
            if (d1 < DB) aB += qB[d1] * kB[d1] * __half2float(sm.fwa[fbB + d1]);
#pragma unroll
            for (int s = 16; s > 0; s >>= 1) {
                aA += __shfl_xor_sync(0xFFFFFFFFu, aA, s);
                aB += __shfl_xor_sync(0xFFFFFFFFu, aB, s);
            }
            if (lane == 0) {
                sm.al[tA * 8 + hA] = aA * nmA * sm.cut[tA];
                sm.al[tB * 8 + hB] = aB * nmB * sm.cut[tB];
            }
        }
    }
    __syncthreads();

    // scatter: inv messages via 128-bit reductions (33 float4 per edge)
    for (int i = tid; i < TE * 33; i += 256) {
        int t = i / 33, c4 = i - 33 * t;
        int f0 = 4 * c4;
        const float4 v = *(const float4*)(g_v_inv + sm.sidx[t] * Ff + f0);
        float r0 = sm.al[t * 8 + (f0 + 0) / 33] * v.x;
        float r1 = sm.al[t * 8 + (f0 + 1) / 33] * v.y;
        float r2 = sm.al[t * 8 + (f0 + 2) / 33] * v.z;
        float r3 = sm.al[t * 8 + (f0 + 3) / 33] * v.w;
        red_add_v4(g_dinv + sm.ridx[t] * Ff + f0, r0, r1, r2, r3);
    }
    // scatter: ev messages (4 float4 per edge, padded row of 16)
    for (int i = tid; i < TE * 4; i += 256) {
        int t = i >> 2, q4 = i & 3;
        int j0 = 4 * q4;
        float r[4];
#pragma unroll
        for (int u = 0; u < 4; u++) {
            int j = j0 + u;
            if (j < EVd) {
                int gg = (j < 3) ? 0 : ((j < 8) ? 1 : 2);
                r[u] = sm.al[t * 8 + 4 + gg] * sh[(e0 + t) * EVd + j];
            } else r[u] = 0.0f;
        }
        red_add_v4(g_dev + sm.ridx[t] * 16 + j0, r[0], r[1], r[2], r[3]);
    }
}

// ---------------- final node update (transposed smem, float4 broadcast) ----------------
#define TNF 8
__global__ __launch_bounds__(160) void final_kernel(
    const float* __restrict__ inv_features,
    const float* __restrict__ ev_features,
    const float* __restrict__ W_int,
    const float* __restrict__ b_int,
    float* __restrict__ out)
{
    __shared__ __align__(16) float ct[136 * TNF];   // transposed cat: [k][t]
    __shared__ float ev1_s[TNF][EVd];
    __shared__ float tb_s[TNF][3];
    const int n0 = blockIdx.x * TNF;

    for (int i = threadIdx.x; i < TNF * Ff; i += 160) {
        const int t = i & 7, f = i >> 3;
        ct[f * TNF + t] = inv_features[(n0 + t) * Ff + f] + g_dinv[(n0 + t) * Ff + f];
    }
    for (int i = threadIdx.x; i < TNF * EVd; i += 160) {
        const int t = i / EVd, j = i - EVd * t;
        ev1_s[t][j] = ev_features[(n0 + t) * EVd + j] + g_dev[(n0 + t) * 16 + j];
    }
    __syncthreads();
    for (int i = threadIdx.x; i < TNF * 3; i += 160) {
        const int t = i / 3, g = i - 3 * t;
        const int js = (g == 0) ? 0 : ((g == 1) ? 3 : 8);
        const int je = (g == 0) ? 3 : ((g == 1) ? 8 : 15);
        float a = 0.0f;
        for (int j = js; j < je; j++) {
            const float v = ev1_s[t][j];
            a += v * v;
        }
        ct[(132 + g) * TNF + t] = a;
    }
    __syncthreads();

    if (threadIdx.x < 135) {
        const int f = threadIdx.x;
        const float b = b_int[f];
        float4 a0 = make_float4(b, b, b, b);
        float4 a1 = a0;
        for (int k = 0; k < 135; k++) {
            const float w = W_int[k * 135 + f];
            const float4* xr = (const float4*)&ct[k * TNF];
            const float4 x0 = xr[0], x1 = xr[1];
            a0.x += x0.x * w; a0.y += x0.y * w; a0.z += x0.z * w; a0.w += x0.w * w;
            a1.x += x1.x * w; a1.y += x1.y * w; a1.z += x1.z * w; a1.w += x1.w * w;
        }
        float acc[TNF] = {a0.x, a0.y, a0.z, a0.w, a1.x, a1.y, a1.z, a1.w};
        if (f < 132) {
#pragma unroll
            for (int t = 0; t < TNF; t++)
                out[(n0 + t) * Ff + f] = ct[f * TNF + t] + acc[t];
        } else {
#pragma unroll
            for (int t = 0; t < TNF; t++) tb_s[t][f - 132] = acc[t];
        }
    }
    __syncthreads();

    float* out_ev = out + Nn * Ff;
    for (int i = threadIdx.x; i < TNF * EVd; i += 160) {
        const int t = i / EVd, j = i - EVd * t;
        const int g = (j < 3) ? 0 : ((j < 8) ? 1 : 2);
        out_ev[(n0 + t) * EVd + j] = ev1_s[t][j] * (1.0f + tb_s[t][g]);
    }
}

// ---------------- launch ----------------
extern "C" void kernel_launch(void* const* d_in, const int* in_sizes, int n_in,
                              void* d_out, int out_size)
{
    const float* inv_features = (const float*)d_in[0];
    const float* ev_features  = (const float*)d_in[1];
    const float* rbf          = (const float*)d_in[2];
    const float* sh_vectors   = (const float*)d_in[3];
    const float* cutoffs      = (const float*)d_in[4];
    const int*   senders      = (const int*)d_in[5];
    const int*   receivers    = (const int*)d_in[6];
    const float* Wq_inv = (const float*)d_in[7];
    const float* Wk_inv = (const float*)d_in[8];
    const float* Wv_inv = (const float*)d_in[9];
    const float* Wq_ev  = (const float*)d_in[10];
    const float* Wk_ev  = (const float*)d_in[11];
    const float* fi_rW1 = (const float*)d_in[12];
    const float* fi_rb1 = (const float*)d_in[13];
    const float* fi_rW2 = (const float*)d_in[14];
    const float* fi_rb2 = (const float*)d_in[15];
    const float* fi_eW1 = (const float*)d_in[16];
    const float* fi_eb1 = (const float*)d_in[17];
    const float* fi_eW2 = (const float*)d_in[18];
    const float* fi_eb2 = (const float*)d_in[19];
    const float* fe_rW1 = (const float*)d_in[20];
    const float* fe_rb1 = (const float*)d_in[21];
    const float* fe_rW2 = (const float*)d_in[22];
    const float* fe_rb2 = (const float*)d_in[23];
    const float* fe_eW1 = (const float*)d_in[24];
    const float* fe_eb1 = (const float*)d_in[25];
    const float* fe_eW2 = (const float*)d_in[26];
    const float* fe_eb2 = (const float*)d_in[27];
    const float* W_int  = (const float*)d_in[28];
    const float* b_int  = (const float*)d_in[29];
    float* out = (float*)d_out;

    cudaFuncSetAttribute(gemm_kernel,
                         cudaFuncAttributeMaxDynamicSharedMemorySize,
                         (int)sizeof(GSm));

    zero_kernel<<<512, 256>>>();
    prep_kernel<<<(2 * NTT * KS2 * 64 + 255) / 256, 256>>>(
        fi_rW1, fi_rb1, fi_rW2, fi_rb2, fi_eW2, fi_eb2,
        fe_rW1, fe_rb1, fe_rW2, fe_rb2, fe_eW2, fe_eb2);
    node_proj_kernel<<<Nn / TNA, 256>>>(inv_features, Wq_inv, Wk_inv, Wv_inv,
                                        Wq_ev, Wk_ev);
    gemm_kernel<<<GRID, 512, sizeof(GSm)>>>(
        ev_features, rbf, senders, receivers,
        fi_eW1, fi_eb1, fe_eW1, fe_eb1);
    att_kernel<<<NTILES, 256>>>(cutoffs, senders, receivers, sh_vectors);
    final_kernel<<<Nn / TNF, 160>>>(inv_features, ev_features, W_int, b_int, out);
}

// round 9
// speedup vs baseline: 4.2086x; 1.1307x over previous
#include <cuda_runtime.h>
#include <cuda_fp16.h>

// Problem constants
#define Nn   50000
#define Ee   400000
#define Rr   32
#define Ff   132
#define EVd  15

#define TE     64    // edges per tile
#define NTILES 6250  // Ee / TE
#define GRIDG  296   // persistent gemm blocks (2 per SM)

#define NTT  18      // n-tiles per net (N padded 144)
#define KS2  12      // layer-2 k-steps (K padded 192)
#define AS2  200     // h1 row stride (halves): 400B rows, LDSM conflict-free
#define FS2  152     // fw smem row stride (halves): 304B rows
#define FSG  288     // fw gmem row stride (halves)
#define RS   40      // rbf smem row stride (halves)

// ---------------- device scratch ----------------
__device__ __half g_q_inv[Nn * Ff];
__device__ __half g_k_inv[Nn * Ff];
__device__ float  g_v_inv[Nn * Ff];
__device__ __half g_q_ev [Nn * Ff];
__device__ __half g_k_ev [Nn * Ff];
__device__ float  g_dinv [Nn * Ff];
__device__ float  g_dev  [Nn * 16];         // padded to 16 for v4 reds
__device__ __align__(16) __half g_fw[Ee * FSG];

// fragment-packed weights (compact, block-diagonal)
__device__ unsigned int g_W2sw[2 * NTT * KS2 * 64];
__device__ unsigned int g_W1sw[2 * NTT * 2 * 64];
__device__ float g_b1c[2 * 144];
__device__ float g_b2c[2 * 144];

__device__ __forceinline__ float silu_f(float x) {
    return x / (1.0f + __expf(-x));
}

__device__ __forceinline__ void mma16816(float c[4],
    unsigned a0, unsigned a1, unsigned a2, unsigned a3,
    unsigned b0, unsigned b1)
{
    asm volatile(
        "mma.sync.aligned.m16n8k16.row.col.f32.f16.f16.f32 "
        "{%0,%1,%2,%3},{%4,%5,%6,%7},{%8,%9},{%0,%1,%2,%3};\n"
        : "+f"(c[0]), "+f"(c[1]), "+f"(c[2]), "+f"(c[3])
        : "r"(a0), "r"(a1), "r"(a2), "r"(a3), "r"(b0), "r"(b1));
}

__device__ __forceinline__ void ldsm4(unsigned& r0, unsigned& r1,
                                      unsigned& r2, unsigned& r3,
                                      unsigned addr)
{
    asm volatile(
        "ldmatrix.sync.aligned.m8n8.x4.shared.b16 {%0,%1,%2,%3}, [%4];\n"
        : "=r"(r0), "=r"(r1), "=r"(r2), "=r"(r3) : "r"(addr));
}

__device__ __forceinline__ void red_add_v4(float* p, float a, float b,
                                           float c, float d)
{
    asm volatile("red.global.add.v4.f32 [%0], {%1,%2,%3,%4};"
                 :: "l"(p), "f"(a), "f"(b), "f"(c), "f"(d) : "memory");
}

// ---------------- zero accumulators ----------------
__global__ void zero_kernel() {
    int i = blockIdx.x * blockDim.x + threadIdx.x;
    int stride = gridDim.x * blockDim.x;
    for (int j = i; j < Nn * Ff; j += stride) g_dinv[j] = 0.0f;
    for (int j = i; j < Nn * 16; j += stride) g_dev[j] = 0.0f;
}

// ---------------- weight prep (compact block-diagonal packing) ----------------
__device__ __forceinline__ float W2com(int net, int k, int n,
    const float* fi_rW2, const float* fi_eW2,
    const float* fe_rW2, const float* fe_eW2)
{
    if (n >= 132) return 0.0f;
    if (k < 132)  return (net ? fe_rW2 : fi_rW2)[k * 132 + n];
    if (k >= 144 && k < 177) return (net ? fe_eW2 : fi_eW2)[(k - 144) * 132 + n];
    return 0.0f;
}

__global__ void prep_kernel(
    const float* __restrict__ fi_rW1, const float* __restrict__ fi_rb1,
    const float* __restrict__ fi_rW2, const float* __restrict__ fi_rb2,
    const float* __restrict__ fi_eW2, const float* __restrict__ fi_eb2,
    const float* __restrict__ fe_rW1, const float* __restrict__ fe_rb1,
    const float* __restrict__ fe_rW2, const float* __restrict__ fe_rb2,
    const float* __restrict__ fe_eW2, const float* __restrict__ fe_eb2)
{
    int i = blockIdx.x * blockDim.x + threadIdx.x;
    if (i < 2 * NTT * KS2 * 64) {
        int slot = i & 63;
        int blk = i >> 6;
        int ks = blk % KS2;
        int tmp = blk / KS2;
        int tt = tmp % NTT;
        int net = tmp / NTT;
        int lane = slot & 31;
        int gq = lane >> 2, t4 = lane & 3;
        int k = ks * 16 + ((slot & 32) ? 8 : 0) + 2 * t4;
        int n = tt * 8 + gq;
        __half2 v = __floats2half2_rn(
            W2com(net, k,     n, fi_rW2, fi_eW2, fe_rW2, fe_eW2),
            W2com(net, k + 1, n, fi_rW2, fi_eW2, fe_rW2, fe_eW2));
        ((__half2*)g_W2sw)[i] = v;
    }
    if (i < 2 * NTT * 2 * 64) {
        int slot = i & 63;
        int blk = i >> 6;
        int ks = blk & 1;
        int tmp = blk >> 1;
        int tt = tmp % NTT;
        int net = tmp / NTT;
        int lane = slot & 31;
        int gq = lane >> 2, t4 = lane & 3;
        int k = ks * 16 + ((slot & 32) ? 8 : 0) + 2 * t4;
        int n = tt * 8 + gq;
        const float* W = net ? fe_rW1 : fi_rW1;
        float v0 = (n < 132) ? W[k * 132 + n] : 0.0f;
        float v1 = (n < 132) ? W[(k + 1) * 132 + n] : 0.0f;
        ((__half2*)g_W1sw)[i] = __floats2half2_rn(v0, v1);
    }
    if (i < 2 * 144) {
        int net = i / 144, n = i % 144;
        float b1 = 0.0f, b2 = 0.0f;
        if (n < 132) {
            b1 = (net ? fe_rb1 : fi_rb1)[n];
            b2 = (net ? fe_rb2 : fi_rb2)[n] + (net ? fe_eb2 : fi_eb2)[n];
        }
        g_b1c[i] = b1;
        g_b2c[i] = b2;
    }
}

// ---------------- per-node projections (transposed smem, float4 broadcast) ----------------
#define TNA 16
#define XSW 20
__global__ __launch_bounds__(256) void node_proj_kernel(
    const float* __restrict__ x,
    const float* __restrict__ Wq_inv, const float* __restrict__ Wk_inv,
    const float* __restrict__ Wv_inv, const float* __restrict__ Wq_ev,
    const float* __restrict__ Wk_ev)
{
    __shared__ __align__(16) float xs[Ff * XSW];
    const int n0 = blockIdx.x * TNA;
    for (int i = threadIdx.x; i < TNA * Ff; i += 256) {
        int t = i / Ff, f = i - t * Ff;
        xs[f * XSW + t] = x[n0 * Ff + i];
    }
    __syncthreads();

    for (int idx = threadIdx.x; idx < 5 * Ff; idx += 256) {
        const int m = idx / Ff, c = idx - m * Ff;
        const float* W;
        int D, h, e;
        if (m < 3) {
            D = 33; h = c / 33; e = c - h * 33;
            W = (m == 0 ? Wq_inv : (m == 1 ? Wk_inv : Wv_inv)) + h * 33 * 33;
        } else {
            D = 44; h = c / 44; e = c - h * 44;
            W = (m == 3 ? Wq_ev : Wk_ev) + h * 44 * 44;
        }
        float4 a0 = make_float4(0.f, 0.f, 0.f, 0.f);
        float4 a1 = a0, a2 = a0, a3 = a0;
        const int xb = h * D;
        for (int d = 0; d < D; d++) {
            const float w = W[d * D + e];
            const float4* xr = (const float4*)&xs[(xb + d) * XSW];
            const float4 x0 = xr[0], x1 = xr[1], x2 = xr[2], x3 = xr[3];
            a0.x += x0.x * w; a0.y += x0.y * w; a0.z += x0.z * w; a0.w += x0.w * w;
            a1.x += x1.x * w; a1.y += x1.y * w; a1.z += x1.z * w; a1.w += x1.w * w;
            a2.x += x2.x * w; a2.y += x2.y * w; a2.z += x2.z * w; a2.w += x2.w * w;
            a3.x += x3.x * w; a3.y += x3.y * w; a3.z += x3.z * w; a3.w += x3.w * w;
        }
        float acc[TNA] = {a0.x, a0.y, a0.z, a0.w, a1.x, a1.y, a1.z, a1.w,
                          a2.x, a2.y, a2.z, a2.w, a3.x, a3.y, a3.z, a3.w};
        if (m == 2) {
#pragma unroll
            for (int t = 0; t < TNA; t++)
                g_v_inv[(n0 + t) * Ff + c] = acc[t];
        } else {
            __half* out = (m == 0) ? g_q_inv : (m == 1) ? g_k_inv
                        : (m == 3) ? g_q_ev : g_k_ev;
#pragma unroll
            for (int t = 0; t < TNA; t++)
                out[(n0 + t) * Ff + c] = __float2half(silu_f(acc[t]));
        }
    }
}

// ---------------- K_gemm: per-net persistent filter-net GEMM -> g_fw ----------------
struct GSm2 {
    unsigned sW2[NTT * KS2 * 64];   // 55296 B
    float sb1[144];                 //   576 B
    float sb2[144];                 //   576 B
    float sevW[99];                 //   396 B
    float sevB[33];                 //   132 B
    __half h1[TE * AS2];            // 25600 B
    __half fw[TE * FS2];            // 19456 B
    __half rbfs[TE * RS];           //  5120 B
    float ev3[TE * 3];              //   768 B
    int   sidx[TE];                 //   256 B
    int   ridx[TE];                 //   256 B
};                                  // ~108 KB -> 2 blocks/SM

__global__ __launch_bounds__(256, 2) void gemm_kernel(
    const float* __restrict__ ev_features,
    const float* __restrict__ rbf_g,
    const int*   __restrict__ senders,
    const int*   __restrict__ receivers,
    const float* __restrict__ fi_eW1, const float* __restrict__ fi_eb1,
    const float* __restrict__ fe_eW1, const float* __restrict__ fe_eb1)
{
    extern __shared__ char smraw[];
    GSm2& sm = *reinterpret_cast<GSm2*>(smraw);
    const int tid = threadIdx.x;
    const int w = tid >> 5, lane = tid & 31;
    const int gq = lane >> 2, t4 = lane & 3;
    const int net = blockIdx.x & 1;           // constant per block
    const int ntile = (w < 2) ? 3 : 2;        // 18 = 8*2 + 2
    const int l15 = lane & 15;
    const int lc8 = (lane & 16) ? 8 : 0;

    // one-time staging (this net only)
    {
        const unsigned* src = g_W2sw + net * NTT * KS2 * 64;
        for (int i = tid; i < NTT * KS2 * 64; i += 256) sm.sW2[i] = src[i];
    }
    for (int i = tid; i < 144; i += 256) {
        sm.sb1[i] = g_b1c[net * 144 + i];
        sm.sb2[i] = g_b2c[net * 144 + i];
    }
    {
        const float* eW = net ? fe_eW1 : fi_eW1;
        const float* eB = net ? fe_eb1 : fi_eb1;
        for (int i = tid; i < 99; i += 256) sm.sevW[i] = eW[i];
        for (int i = tid; i < 33; i += 256) sm.sevB[i] = eB[i];
    }
    for (int i = tid; i < TE * AS2 / 2; i += 256)
        ((unsigned*)sm.h1)[i] = 0u;
    __syncthreads();

    const unsigned h1s  = (unsigned)__cvta_generic_to_shared(sm.h1);
    const unsigned rbss = (unsigned)__cvta_generic_to_shared(sm.rbfs);
    const unsigned a2base = h1s  + 2 * (l15 * AS2 + lc8);
    const unsigned a1base = rbss + 2 * (l15 * RS + lc8);
    const unsigned* W1n = g_W1sw + net * NTT * 2 * 64;

    for (int u = blockIdx.x; u < 2 * NTILES; u += GRIDG) {
        const int tile = u >> 1;
        const int e0 = tile * TE;
        __syncthreads();   // protect smem reuse vs previous iteration readers

        if (tid < TE) {
            sm.sidx[tid] = senders[e0 + tid];
            sm.ridx[tid] = receivers[e0 + tid];
        }
        for (int i = tid; i < TE * Rr; i += 256) {
            int t = i >> 5, c = i & 31;
            sm.rbfs[t * RS + c] = __float2half(rbf_g[e0 * Rr + i]);
        }
        __syncthreads();

        if (tid < TE * 3) {
            int t = tid / 3, g3 = tid - 3 * t;
            int js = (g3 == 0) ? 0 : ((g3 == 1) ? 3 : 8);
            int je = (g3 == 0) ? 3 : ((g3 == 1) ? 8 : 15);
            const float* evs = ev_features + sm.sidx[t] * EVd;
            const float* evr = ev_features + sm.ridx[t] * EVd;
            float a = 0.0f;
            for (int j = js; j < je; j++) {
                float d = evs[j] - evr[j];
                a += d * d;
            }
            sm.ev3[t * 3 + g3] = a;
        }

        // layer 1 (rbf branch): [64x32] x [32x144]
        {
            float acc[3][4][4];
#pragma unroll
            for (int j = 0; j < 3; j++) {
                if (j < ntile) {
                    int nidx = (w + 8 * j) * 8 + 2 * t4;
                    float b0f = sm.sb1[nidx], b1f = sm.sb1[nidx + 1];
#pragma unroll
                    for (int m = 0; m < 4; m++) {
                        acc[j][m][0] = b0f; acc[j][m][1] = b1f;
                        acc[j][m][2] = b0f; acc[j][m][3] = b1f;
                    }
                }
            }
#pragma unroll
            for (int ks = 0; ks < 2; ks++) {
                unsigned a[4][4];
#pragma unroll
                for (int m = 0; m < 4; m++)
                    ldsm4(a[m][0], a[m][1], a[m][2], a[m][3],
                          a1base + 2 * (m * 16 * RS + ks * 16));
#pragma unroll
                for (int j = 0; j < 3; j++) {
                    if (j < ntile) {
                        int tt = w + 8 * j;
                        int bi = (tt * 2 + ks) * 64;
                        unsigned b0 = W1n[bi + lane], b1 = W1n[bi + 32 + lane];
#pragma unroll
                        for (int m = 0; m < 4; m++)
                            mma16816(acc[j][m], a[m][0], a[m][1], a[m][2], a[m][3], b0, b1);
                    }
                }
            }
#pragma unroll
            for (int j = 0; j < 3; j++) {
                if (j < ntile) {
                    int col = (w + 8 * j) * 8 + 2 * t4;
#pragma unroll
                    for (int m = 0; m < 4; m++) {
                        int r = m * 16 + gq;
                        *(__half2*)&sm.h1[r * AS2 + col] =
                            __floats2half2_rn(silu_f(acc[j][m][0]), silu_f(acc[j][m][1]));
                        *(__half2*)&sm.h1[(r + 8) * AS2 + col] =
                            __floats2half2_rn(silu_f(acc[j][m][2]), silu_f(acc[j][m][3]));
                    }
                }
            }
        }
        __syncthreads();

        // layer 1 ev branch: 3 -> 33, h1 cols 144..176
        for (int i = tid; i < TE * 33; i += 256) {
            int t = i / 33, cc = i - 33 * t;
            float v = sm.sevB[cc]
                    + sm.ev3[t * 3 + 0] * sm.sevW[cc]
                    + sm.ev3[t * 3 + 1] * sm.sevW[33 + cc]
                    + sm.ev3[t * 3 + 2] * sm.sevW[66 + cc];
            sm.h1[t * AS2 + 144 + cc] = __float2half(silu_f(v));
        }
        __syncthreads();

        // layer 2: [64x192] x [192x144]
        {
            float acc[3][4][4];
#pragma unroll
            for (int j = 0; j < 3; j++) {
                if (j < ntile) {
                    int nidx = (w + 8 * j) * 8 + 2 * t4;
                    float b0f = sm.sb2[nidx], b1f = sm.sb2[nidx + 1];
#pragma unroll
                    for (int m = 0; m < 4; m++) {
                        acc[j][m][0] = b0f; acc[j][m][1] = b1f;
                        acc[j][m][2] = b0f; acc[j][m][3] = b1f;
                    }
                }
            }
#pragma unroll 2
            for (int ks = 0; ks < KS2; ks++) {
                unsigned a[4][4];
#pragma unroll
                for (int m = 0; m < 4; m++)
                    ldsm4(a[m][0], a[m][1], a[m][2], a[m][3],
                          a2base + 2 * (m * 16 * AS2 + ks * 16));
#pragma unroll
                for (int j = 0; j < 3; j++) {
                    if (j < ntile) {
                        int tt = w + 8 * j;
                        int bi = (tt * KS2 + ks) * 64;
                        unsigned b0 = sm.sW2[bi + lane], b1 = sm.sW2[bi + 32 + lane];
#pragma unroll
                        for (int m = 0; m < 4; m++)
                            mma16816(acc[j][m], a[m][0], a[m][1], a[m][2], a[m][3], b0, b1);
                    }
                }
            }
#pragma unroll
            for (int j = 0; j < 3; j++) {
                if (j < ntile) {
                    int col = (w + 8 * j) * 8 + 2 * t4;
#pragma unroll
                    for (int m = 0; m < 4; m++) {
                        int r = m * 16 + gq;
                        *(__half2*)&sm.fw[r * FS2 + col] =
                            __floats2half2_rn(acc[j][m][0], acc[j][m][1]);
                        *(__half2*)&sm.fw[(r + 8) * FS2 + col] =
                            __floats2half2_rn(acc[j][m][2], acc[j][m][3]);
                    }
                }
            }
        }
        __syncthreads();

        // coalesced fw writeout: 64 rows x 18 uint4 into this net's column range
        {
            __half* dstbase = g_fw + (size_t)e0 * FSG + net * 144;
            for (int i = tid; i < TE * 18; i += 256) {
                int r = i / 18, c = i - r * 18;
                *(uint4*)(dstbase + r * FSG + c * 8) =
                    *(const uint4*)&sm.fw[r * FS2 + c * 8];
            }
        }
    }
}

// ---------------- K_att: attention logits + scatter (high occupancy) ----------------
struct __align__(16) ASm {
    __half fwa[TE * FSG];   // 36864 B
    float  al [TE * 8];     //  2048 B
    float  cut[TE];
    int    sidx[TE];
    int    ridx[TE];
};

__global__ __launch_bounds__(256) void att_kernel(
    const float* __restrict__ cutoffs,
    const int*   __restrict__ senders,
    const int*   __restrict__ receivers,
    const float* __restrict__ sh)
{
    __shared__ ASm sm;
    const int tid = threadIdx.x;
    const int w = tid >> 5, lane = tid & 31;
    const int e0 = blockIdx.x * TE;

    if (tid < TE) {
        sm.sidx[tid] = senders[e0 + tid];
        sm.ridx[tid] = receivers[e0 + tid];
        sm.cut[tid]  = cutoffs[e0 + tid];
    }
    {
        const uint4* src = (const uint4*)(g_fw + (size_t)e0 * FSG);
        uint4* dst = (uint4*)sm.fwa;
        for (int i = tid; i < TE * (FSG / 8); i += 256)
            dst[i] = src[i];
    }
    __syncthreads();

    // alpha: 448 tasks over 8 warps, 2-way interleaved (fp16 q/k gathers)
    {
        const float INVN = 0.17407765595569785f;  // 1/sqrt(33)
        const float INVE = 0.15075567228888181f;  // 1/sqrt(44)
        for (int p = 0; p < 28; p++) {
            int taskA = w + 8 * (2 * p);
            int taskB = w + 8 * (2 * p + 1);
            int tA = taskA / 7, hA = taskA - 7 * tA;
            int tB = taskB / 7, hB = taskB - 7 * tB;

            const __half *qA, *kA; int fbA, DA; float nmA;
            if (hA < 4) { qA = g_q_inv + sm.ridx[tA] * Ff + hA * 33;
                          kA = g_k_inv + sm.sidx[tA] * Ff + hA * 33;
                          fbA = tA * FSG + hA * 33; DA = 33; nmA = INVN; }
            else        { int hh = hA - 4;
                          qA = g_q_ev + sm.ridx[tA] * Ff + hh * 44;
                          kA = g_k_ev + sm.sidx[tA] * Ff + hh * 44;
                          fbA = tA * FSG + 144 + hh * 44; DA = 44; nmA = INVE; }
            const __half *qB, *kB; int fbB, DB; float nmB;
            if (hB < 4) { qB = g_q_inv + sm.ridx[tB] * Ff + hB * 33;
                          kB = g_k_inv + sm.sidx[tB] * Ff + hB * 33;
                          fbB = tB * FSG + hB * 33; DB = 33; nmB = INVN; }
            else        { int hh = hB - 4;
                          qB = g_q_ev + sm.ridx[tB] * Ff + hh * 44;
                          kB = g_k_ev + sm.sidx[tB] * Ff + hh * 44;
                          fbB = tB * FSG + 144 + hh * 44; DB = 44; nmB = INVE; }

            float aA = __half2float(qA[lane]) * __half2float(kA[lane])
                     * __half2float(sm.fwa[fbA + lane]);
            float aB = __half2float(qB[lane]) * __half2float(kB[lane])
                     * __half2float(sm.fwa[fbB + lane]);
            int d1 = lane + 32;
            if (d1 < DA) aA += __half2float(qA[d1]) * __half2float(kA[d1])
                             * __half2float(sm.fwa[fbA + d1]);
            if (d1 < DB) aB += __half2float(qB[d1]) * __half2float(kB[d1])
                             * __half2float(sm.fwa[fbB + d1]);
#pragma unroll
            for (int s = 16; s > 0; s >>= 1) {
                aA += __shfl_xor_sync(0xFFFFFFFFu, aA, s);
                aB += __shfl_xor_sync(0xFFFFFFFFu, aB, s);
            }
            if (lane == 0) {
                sm.al[tA * 8 + hA] = aA * nmA * sm.cut[tA];
                sm.al[tB * 8 + hB] = aB * nmB * sm.cut[tB];
            }
        }
    }
    __syncthreads();

    // scatter: inv messages via 128-bit reductions (33 float4 per edge)
    for (int i = tid; i < TE * 33; i += 256) {
        int t = i / 33, c4 = i - 33 * t;
        int f0 = 4 * c4;
        const float4 v = *(const float4*)(g_v_inv + sm.sidx[t] * Ff + f0);
        float r0 = sm.al[t * 8 + (f0 + 0) / 33] * v.x;
        float r1 = sm.al[t * 8 + (f0 + 1) / 33] * v.y;
        float r2 = sm.al[t * 8 + (f0 + 2) / 33] * v.z;
        float r3 = sm.al[t * 8 + (f0 + 3) / 33] * v.w;
        red_add_v4(g_dinv + sm.ridx[t] * Ff + f0, r0, r1, r2, r3);
    }
    // scatter: ev messages (4 float4 per edge, padded row of 16)
    for (int i = tid; i < TE * 4; i += 256) {
        int t = i >> 2, q4 = i & 3;
        int j0 = 4 * q4;
        float r[4];
#pragma unroll
        for (int u = 0; u < 4; u++) {
            int j = j0 + u;
            if (j < EVd) {
                int gg = (j < 3) ? 0 : ((j < 8) ? 1 : 2);
                r[u] = sm.al[t * 8 + 4 + gg] * sh[(e0 + t) * EVd + j];
            } else r[u] = 0.0f;
        }
        red_add_v4(g_dev + sm.ridx[t] * 16 + j0, r[0], r[1], r[2], r[3]);
    }
}

// ---------------- final node update (transposed smem, float4 broadcast) ----------------
#define TNF 8
__global__ __launch_bounds__(160) void final_kernel(
    const float* __restrict__ inv_features,
    const float* __restrict__ ev_features,
    const float* __restrict__ W_int,
    const float* __restrict__ b_int,
    float* __restrict__ out)
{
    __shared__ __align__(16) float ct[136 * TNF];   // transposed cat: [k][t]
    __shared__ float ev1_s[TNF][EVd];
    __shared__ float tb_s[TNF][3];
    const int n0 = blockIdx.x * TNF;

    for (int i = threadIdx.x; i < TNF * Ff; i += 160) {
        const int t = i & 7, f = i >> 3;
        ct[f * TNF + t] = inv_features[(n0 + t) * Ff + f] + g_dinv[(n0 + t) * Ff + f];
    }
    for (int i = threadIdx.x; i < TNF * EVd; i += 160) {
        const int t = i / EVd, j = i - EVd * t;
        ev1_s[t][j] = ev_features[(n0 + t) * EVd + j] + g_dev[(n0 + t) * 16 + j];
    }
    __syncthreads();
    for (int i = threadIdx.x; i < TNF * 3; i += 160) {
        const int t = i / 3, g = i - 3 * t;
        const int js = (g == 0) ? 0 : ((g == 1) ? 3 : 8);
        const int je = (g == 0) ? 3 : ((g == 1) ? 8 : 15);
        float a = 0.0f;
        for (int j = js; j < je; j++) {
            const float v = ev1_s[t][j];
            a += v * v;
        }
        ct[(132 + g) * TNF + t] = a;
    }
    __syncthreads();

    if (threadIdx.x < 135) {
        const int f = threadIdx.x;
        const float b = b_int[f];
        float4 a0 = make_float4(b, b, b, b);
        float4 a1 = a0;
        for (int k = 0; k < 135; k++) {
            const float w = W_int[k * 135 + f];
            const float4* xr = (const float4*)&ct[k * TNF];
            const float4 x0 = xr[0], x1 = xr[1];
            a0.x += x0.x * w; a0.y += x0.y * w; a0.z += x0.z * w; a0.w += x0.w * w;
            a1.x += x1.x * w; a1.y += x1.y * w; a1.z += x1.z * w; a1.w += x1.w * w;
        }
        float acc[TNF] = {a0.x, a0.y, a0.z, a0.w, a1.x, a1.y, a1.z, a1.w};
        if (f < 132) {
#pragma unroll
            for (int t = 0; t < TNF; t++)
                out[(n0 + t) * Ff + f] = ct[f * TNF + t] + acc[t];
        } else {
#pragma unroll
            for (int t = 0; t < TNF; t++) tb_s[t][f - 132] = acc[t];
        }
    }
    __syncthreads();

    float* out_ev = out + Nn * Ff;
    for (int i = threadIdx.x; i < TNF * EVd; i += 160) {
        const int t = i / EVd, j = i - EVd * t;
        const int g = (j < 3) ? 0 : ((j < 8) ? 1 : 2);
        out_ev[(n0 + t) * EVd + j] = ev1_s[t][j] * (1.0f + tb_s[t][g]);
    }
}

// ---------------- launch ----------------
extern "C" void kernel_launch(void* const* d_in, const int* in_sizes, int n_in,
                              void* d_out, int out_size)
{
    const float* inv_features = (const float*)d_in[0];
    const float* ev_features  = (const float*)d_in[1];
    const float* rbf          = (const float*)d_in[2];
    const float* sh_vectors   = (const float*)d_in[3];
    const float* cutoffs      = (const float*)d_in[4];
    const int*   senders      = (const int*)d_in[5];
    const int*   receivers    = (const int*)d_in[6];
    const float* Wq_inv = (const float*)d_in[7];
    const float* Wk_inv = (const float*)d_in[8];
    const float* Wv_inv = (const float*)d_in[9];
    const float* Wq_ev  = (const float*)d_in[10];
    const float* Wk_ev  = (const float*)d_in[11];
    const float* fi_rW1 = (const float*)d_in[12];
    const float* fi_rb1 = (const float*)d_in[13];
    const float* fi_rW2 = (const float*)d_in[14];
    const float* fi_rb2 = (const float*)d_in[15];
    const float* fi_eW1 = (const float*)d_in[16];
    const float* fi_eb1 = (const float*)d_in[17];
    const float* fi_eW2 = (const float*)d_in[18];
    const float* fi_eb2 = (const float*)d_in[19];
    const float* fe_rW1 = (const float*)d_in[20];
    const float* fe_rb1 = (const float*)d_in[21];
    const float* fe_rW2 = (const float*)d_in[22];
    const float* fe_rb2 = (const float*)d_in[23];
    const float* fe_eW1 = (const float*)d_in[24];
    const float* fe_eb1 = (const float*)d_in[25];
    const float* fe_eW2 = (const float*)d_in[26];
    const float* fe_eb2 = (const float*)d_in[27];
    const float* W_int  = (const float*)d_in[28];
    const float* b_int  = (const float*)d_in[29];
    float* out = (float*)d_out;

    cudaFuncSetAttribute(gemm_kernel,
                         cudaFuncAttributeMaxDynamicSharedMemorySize,
                         (int)sizeof(GSm2));

    zero_kernel<<<512, 256>>>();
    prep_kernel<<<(2 * NTT * KS2 * 64 + 255) / 256, 256>>>(
        fi_rW1, fi_rb1, fi_rW2, fi_rb2, fi_eW2, fi_eb2,
        fe_rW1, fe_rb1, fe_rW2, fe_rb2, fe_eW2, fe_eb2);
    node_proj_kernel<<<Nn / TNA, 256>>>(inv_features, Wq_inv, Wk_inv, Wv_inv,
                                        Wq_ev, Wk_ev);
    gemm_kernel<<<GRIDG, 256, sizeof(GSm2)>>>(
        ev_features, rbf, senders, receivers,
        fi_eW1, fi_eb1, fe_eW1, fe_eb1);
    att_kernel<<<NTILES, 256>>>(cutoffs, senders, receivers, sh_vectors);
    final_kernel<<<Nn / TNF, 160>>>(inv_features, ev_features, W_int, b_int, out);
}

// round 11
// speedup vs baseline: 4.4404x; 1.0551x over previous
#include <cuda_runtime.h>
#include <cuda_fp16.h>

// Problem constants
#define Nn   50000
#define Ee   400000
#define Rr   32
#define Ff   132
#define EVd  15

#define TE     64    // edges per tile
#define NTILES 6250  // Ee / TE
#define GRIDG  296   // persistent gemm blocks (2 per SM)

#define NTT  18      // n-tiles per net (N padded 144)
#define KS2  12      // layer-2 k-steps (K padded 192)
#define AS2  200     // h1 row stride (halves)
#define FS2  152     // fw smem row stride (halves)
#define FSG  288     // fw gmem row stride (halves)
#define RS   40      // rbf smem row stride (halves)

// ---------------- device scratch ----------------
__device__ __half g_q_inv[Nn * Ff];
__device__ __half g_k_inv[Nn * Ff];
__device__ float  g_v_inv[Nn * Ff];
__device__ __half g_q_ev [Nn * Ff];
__device__ __half g_k_ev [Nn * Ff];
__device__ float  g_dinv [Nn * Ff];
__device__ float  g_dev  [Nn * 16];
__device__ __align__(16) __half g_fw[Ee * FSG];

// fragment-packed weights (compact, block-diagonal)
__device__ unsigned int g_W2sw[2 * NTT * KS2 * 64];
__device__ unsigned int g_W1sw[2 * NTT * 2 * 64];
__device__ float g_b1c[2 * 144];
__device__ float g_b2c[2 * 144];

__device__ __forceinline__ float silu_f(float x) {
    return x / (1.0f + __expf(-x));
}

__device__ __forceinline__ void mma16816(float c[4],
    unsigned a0, unsigned a1, unsigned a2, unsigned a3,
    unsigned b0, unsigned b1)
{
    asm volatile(
        "mma.sync.aligned.m16n8k16.row.col.f32.f16.f16.f32 "
        "{%0,%1,%2,%3},{%4,%5,%6,%7},{%8,%9},{%0,%1,%2,%3};\n"
        : "+f"(c[0]), "+f"(c[1]), "+f"(c[2]), "+f"(c[3])
        : "r"(a0), "r"(a1), "r"(a2), "r"(a3), "r"(b0), "r"(b1));
}

__device__ __forceinline__ void ldsm4(unsigned& r0, unsigned& r1,
                                      unsigned& r2, unsigned& r3,
                                      unsigned addr)
{
    asm volatile(
        "ldmatrix.sync.aligned.m8n8.x4.shared.b16 {%0,%1,%2,%3}, [%4];\n"
        : "=r"(r0), "=r"(r1), "=r"(r2), "=r"(r3) : "r"(addr));
}

__device__ __forceinline__ void red_add_v4(float* p, float a, float b,
                                           float c, float d)
{
    asm volatile("red.global.add.v4.f32 [%0], {%1,%2,%3,%4};"
                 :: "l"(p), "f"(a), "f"(b), "f"(c), "f"(d) : "memory");
}

// ---------------- zero accumulators ----------------
__global__ void zero_kernel() {
    int i = blockIdx.x * blockDim.x + threadIdx.x;
    int stride = gridDim.x * blockDim.x;
    for (int j = i; j < Nn * Ff; j += stride) g_dinv[j] = 0.0f;
    for (int j = i; j < Nn * 16; j += stride) g_dev[j] = 0.0f;
}

// ---------------- weight prep (compact block-diagonal packing) ----------------
__device__ __forceinline__ float W2com(int net, int k, int n,
    const float* fi_rW2, const float* fi_eW2,
    const float* fe_rW2, const float* fe_eW2)
{
    if (n >= 132) return 0.0f;
    if (k < 132)  return (net ? fe_rW2 : fi_rW2)[k * 132 + n];
    if (k >= 144 && k < 177) return (net ? fe_eW2 : fi_eW2)[(k - 144) * 132 + n];
    return 0.0f;
}

__global__ void prep_kernel(
    const float* __restrict__ fi_rW1, const float* __restrict__ fi_rb1,
    const float* __restrict__ fi_rW2, const float* __restrict__ fi_rb2,
    const float* __restrict__ fi_eW2, const float* __restrict__ fi_eb2,
    const float* __restrict__ fe_rW1, const float* __restrict__ fe_rb1,
    const float* __restrict__ fe_rW2, const float* __restrict__ fe_rb2,
    const float* __restrict__ fe_eW2, const float* __restrict__ fe_eb2)
{
    int i = blockIdx.x * blockDim.x + threadIdx.x;
    if (i < 2 * NTT * KS2 * 64) {
        int slot = i & 63;
        int blk = i >> 6;
        int ks = blk % KS2;
        int tmp = blk / KS2;
        int tt = tmp % NTT;
        int net = tmp / NTT;
        int lane = slot & 31;
        int gq = lane >> 2, t4 = lane & 3;
        int k = ks * 16 + ((slot & 32) ? 8 : 0) + 2 * t4;
        int n = tt * 8 + gq;
        __half2 v = __floats2half2_rn(
            W2com(net, k,     n, fi_rW2, fi_eW2, fe_rW2, fe_eW2),
            W2com(net, k + 1, n, fi_rW2, fi_eW2, fe_rW2, fe_eW2));
        ((__half2*)g_W2sw)[i] = v;
    }
    if (i < 2 * NTT * 2 * 64) {
        int slot = i & 63;
        int blk = i >> 6;
        int ks = blk & 1;
        int tmp = blk >> 1;
        int tt = tmp % NTT;
        int net = tmp / NTT;
        int lane = slot & 31;
        int gq = lane >> 2, t4 = lane & 3;
        int k = ks * 16 + ((slot & 32) ? 8 : 0) + 2 * t4;
        int n = tt * 8 + gq;
        const float* W = net ? fe_rW1 : fi_rW1;
        float v0 = (n < 132) ? W[k * 132 + n] : 0.0f;
        float v1 = (n < 132) ? W[(k + 1) * 132 + n] : 0.0f;
        ((__half2*)g_W1sw)[i] = __floats2half2_rn(v0, v1);
    }
    if (i < 2 * 144) {
        int net = i / 144, n = i % 144;
        float b1 = 0.0f, b2 = 0.0f;
        if (n < 132) {
            b1 = (net ? fe_rb1 : fi_rb1)[n];
            b2 = (net ? fe_rb2 : fi_rb2)[n] + (net ? fe_eb2 : fi_eb2)[n];
        }
        g_b1c[i] = b1;
        g_b2c[i] = b2;
    }
}

// ---------------- per-node projections (transposed smem, float4 broadcast) ----------------
#define TNA 16
#define XSW 20
__global__ __launch_bounds__(256) void node_proj_kernel(
    const float* __restrict__ x,
    const float* __restrict__ Wq_inv, const float* __restrict__ Wk_inv,
    const float* __restrict__ Wv_inv, const float* __restrict__ Wq_ev,
    const float* __restrict__ Wk_ev)
{
    __shared__ __align__(16) float xs[Ff * XSW];
    const int n0 = blockIdx.x * TNA;
    for (int i = threadIdx.x; i < TNA * Ff; i += 256) {
        int t = i / Ff, f = i - t * Ff;
        xs[f * XSW + t] = x[n0 * Ff + i];
    }
    __syncthreads();

    for (int idx = threadIdx.x; idx < 5 * Ff; idx += 256) {
        const int m = idx / Ff, c = idx - m * Ff;
        const float* W;
        int D, h, e;
        if (m < 3) {
            D = 33; h = c / 33; e = c - h * 33;
            W = (m == 0 ? Wq_inv : (m == 1 ? Wk_inv : Wv_inv)) + h * 33 * 33;
        } else {
            D = 44; h = c / 44; e = c - h * 44;
            W = (m == 3 ? Wq_ev : Wk_ev) + h * 44 * 44;
        }
        float4 a0 = make_float4(0.f, 0.f, 0.f, 0.f);
        float4 a1 = a0, a2 = a0, a3 = a0;
        const int xb = h * D;
        for (int d = 0; d < D; d++) {
            const float w = W[d * D + e];
            const float4* xr = (const float4*)&xs[(xb + d) * XSW];
            const float4 x0 = xr[0], x1 = xr[1], x2 = xr[2], x3 = xr[3];
            a0.x += x0.x * w; a0.y += x0.y * w; a0.z += x0.z * w; a0.w += x0.w * w;
            a1.x += x1.x * w; a1.y += x1.y * w; a1.z += x1.z * w; a1.w += x1.w * w;
            a2.x += x2.x * w; a2.y += x2.y * w; a2.z += x2.z * w; a2.w += x2.w * w;
            a3.x += x3.x * w; a3.y += x3.y * w; a3.z += x3.z * w; a3.w += x3.w * w;
        }
        float acc[TNA] = {a0.x, a0.y, a0.z, a0.w, a1.x, a1.y, a1.z, a1.w,
                          a2.x, a2.y, a2.z, a2.w, a3.x, a3.y, a3.z, a3.w};
        if (m == 2) {
#pragma unroll
            for (int t = 0; t < TNA; t++)
                g_v_inv[(n0 + t) * Ff + c] = acc[t];
        } else {
            __half* out = (m == 0) ? g_q_inv : (m == 1) ? g_k_inv
                        : (m == 3) ? g_q_ev : g_k_ev;
#pragma unroll
            for (int t = 0; t < TNA; t++)
                out[(n0 + t) * Ff + c] = __float2half(silu_f(acc[t]));
        }
    }
}

// ---------------- K_gemm: per-net persistent GEMM, M-split 512 threads ----------------
struct GSm2 {
    unsigned sW2[NTT * KS2 * 64];   // 55296 B
    float sb1[144];
    float sb2[144];
    float sevW[99];
    float sevB[33];
    __half h1[TE * AS2];            // 25600 B
    __half fw[TE * FS2];            // 19456 B
    __half rbfs[TE * RS];           //  5120 B
    float ev3[TE * 3];              //   768 B
};                                  // ~107 KB -> 2 blocks/SM

__global__ __launch_bounds__(512, 2) void gemm_kernel(
    const float* __restrict__ ev_features,
    const float* __restrict__ rbf_g,
    const int*   __restrict__ senders,
    const int*   __restrict__ receivers,
    const float* __restrict__ fi_eW1, const float* __restrict__ fi_eb1,
    const float* __restrict__ fe_eW1, const float* __restrict__ fe_eb1)
{
    extern __shared__ char smraw[];
    GSm2& sm = *reinterpret_cast<GSm2*>(smraw);
    const int tid = threadIdx.x;
    const int w = tid >> 5, lane = tid & 31;
    const int gq = lane >> 2, t4 = lane & 3;
    const int net = blockIdx.x & 1;           // constant per block
    const int mh = w >> 3;                    // m-half: warps 0-7 -> m{0,1}, 8-15 -> m{2,3}
    const int wn = w & 7;
    const int ntile = (wn < 2) ? 3 : 2;       // 18 n-tiles over 8 warp columns
    const int l15 = lane & 15;
    const int lc8 = (lane & 16) ? 8 : 0;

    // one-time staging (this net only)
    {
        const unsigned* src = g_W2sw + net * NTT * KS2 * 64;
        for (int i = tid; i < NTT * KS2 * 64; i += 512) sm.sW2[i] = src[i];
    }
    for (int i = tid; i < 144; i += 512) {
        sm.sb1[i] = g_b1c[net * 144 + i];
        sm.sb2[i] = g_b2c[net * 144 + i];
    }
    {
        const float* eW = net ? fe_eW1 : fi_eW1;
        const float* eB = net ? fe_eb1 : fi_eb1;
        for (int i = tid; i < 99; i += 512) sm.sevW[i] = eW[i];
        for (int i = tid; i < 33; i += 512) sm.sevB[i] = eB[i];
    }
    for (int i = tid; i < TE * AS2 / 2; i += 512)
        ((unsigned*)sm.h1)[i] = 0u;
    __syncthreads();

    const unsigned h1s  = (unsigned)__cvta_generic_to_shared(sm.h1);
    const unsigned rbss = (unsigned)__cvta_generic_to_shared(sm.rbfs);
    const unsigned a2base = h1s  + 2 * ((2 * mh) * 16 * AS2 + l15 * AS2 + lc8);
    const unsigned a1base = rbss + 2 * ((2 * mh) * 16 * RS + l15 * RS + lc8);
    const unsigned* W1n = g_W1sw + net * NTT * 2 * 64;

    for (int u = blockIdx.x; u < 2 * NTILES; u += GRIDG) {
        const int tile = u >> 1;
        const int e0 = tile * TE;
        __syncthreads();   // protect smem reuse vs previous iteration readers

        // rbf staging + ev3 (direct index loads), same phase
        for (int i = tid; i < TE * Rr; i += 512) {
            int t = i >> 5, c = i & 31;
            sm.rbfs[t * RS + c] = __float2half(rbf_g[e0 * Rr + i]);
        }
        if (tid < TE * 3) {
            int t = tid / 3, g3 = tid - 3 * t;
            int js = (g3 == 0) ? 0 : ((g3 == 1) ? 3 : 8);
            int je = (g3 == 0) ? 3 : ((g3 == 1) ? 8 : 15);
            const float* evs = ev_features + senders[e0 + t] * EVd;
            const float* evr = ev_features + receivers[e0 + t] * EVd;
            float a = 0.0f;
            for (int j = js; j < je; j++) {
                float d = evs[j] - evr[j];
                a += d * d;
            }
            sm.ev3[t * 3 + g3] = a;
        }
        __syncthreads();

        // layer 1 (rbf branch, 2 m-tiles per warp) + ev branch, same phase
        {
            float acc[3][2][4];
#pragma unroll
            for (int j = 0; j < 3; j++) {
                if (j < ntile) {
                    int nidx = (wn + 8 * j) * 8 + 2 * t4;
                    float b0f = sm.sb1[nidx], b1f = sm.sb1[nidx + 1];
#pragma unroll
                    for (int m = 0; m < 2; m++) {
                        acc[j][m][0] = b0f; acc[j][m][1] = b1f;
                        acc[j][m][2] = b0f; acc[j][m][3] = b1f;
                    }
                }
            }
#pragma unroll
            for (int ks = 0; ks < 2; ks++) {
                unsigned a[2][4];
#pragma unroll
                for (int m = 0; m < 2; m++)
                    ldsm4(a[m][0], a[m][1], a[m][2], a[m][3],
                          a1base + 2 * (m * 16 * RS + ks * 16));
#pragma unroll
                for (int j = 0; j < 3; j++) {
                    if (j < ntile) {
                        int tt = wn + 8 * j;
                        int bi = (tt * 2 + ks) * 64;
                        unsigned b0 = W1n[bi + lane], b1 = W1n[bi + 32 + lane];
#pragma unroll
                        for (int m = 0; m < 2; m++)
                            mma16816(acc[j][m], a[m][0], a[m][1], a[m][2], a[m][3], b0, b1);
                    }
                }
            }
#pragma unroll
            for (int j = 0; j < 3; j++) {
                if (j < ntile) {
                    int col = (wn + 8 * j) * 8 + 2 * t4;
#pragma unroll
                    for (int m = 0; m < 2; m++) {
                        int r = (2 * mh + m) * 16 + gq;
                        *(__half2*)&sm.h1[r * AS2 + col] =
                            __floats2half2_rn(silu_f(acc[j][m][0]), silu_f(acc[j][m][1]));
                        *(__half2*)&sm.h1[(r + 8) * AS2 + col] =
                            __floats2half2_rn(silu_f(acc[j][m][2]), silu_f(acc[j][m][3]));
                    }
                }
            }
        }
        // ev branch: 3 -> 33, h1 cols 144..176 (disjoint from L1 epilogue cols)
        for (int i = tid; i < TE * 33; i += 512) {
            int t = i / 33, cc = i - 33 * t;
            float v = sm.sevB[cc]
                    + sm.ev3[t * 3 + 0] * sm.sevW[cc]
                    + sm.ev3[t * 3 + 1] * sm.sevW[33 + cc]
                    + sm.ev3[t * 3 + 2] * sm.sevW[66 + cc];
            sm.h1[t * AS2 + 144 + cc] = __float2half(silu_f(v));
        }
        __syncthreads();

        // layer 2: [64x192] x [192x144]
        {
            float acc[3][2][4];
#pragma unroll
            for (int j = 0; j < 3; j++) {
                if (j < ntile) {
                    int nidx = (wn + 8 * j) * 8 + 2 * t4;
                    float b0f = sm.sb2[nidx], b1f = sm.sb2[nidx + 1];
#pragma unroll
                    for (int m = 0; m < 2; m++) {
                        acc[j][m][0] = b0f; acc[j][m][1] = b1f;
                        acc[j][m][2] = b0f; acc[j][m][3] = b1f;
                    }
                }
            }
#pragma unroll 3
            for (int ks = 0; ks < KS2; ks++) {
                unsigned a[2][4];
#pragma unroll
                for (int m = 0; m < 2; m++)
                    ldsm4(a[m][0], a[m][1], a[m][2], a[m][3],
                          a2base + 2 * (m * 16 * AS2 + ks * 16));
#pragma unroll
                for (int j = 0; j < 3; j++) {
                    if (j < ntile) {
                        int tt = wn + 8 * j;
                        int bi = (tt * KS2 + ks) * 64;
                        unsigned b0 = sm.sW2[bi + lane], b1 = sm.sW2[bi + 32 + lane];
#pragma unroll
                        for (int m = 0; m < 2; m++)
                            mma16816(acc[j][m], a[m][0], a[m][1], a[m][2], a[m][3], b0, b1);
                    }
                }
            }
#pragma unroll
            for (int j = 0; j < 3; j++) {
                if (j < ntile) {
                    int col = (wn + 8 * j) * 8 + 2 * t4;
#pragma unroll
                    for (int m = 0; m < 2; m++) {
                        int r = (2 * mh + m) * 16 + gq;
                        *(__half2*)&sm.fw[r * FS2 + col] =
                            __floats2half2_rn(acc[j][m][0], acc[j][m][1]);
                        *(__half2*)&sm.fw[(r + 8) * FS2 + col] =
                            __floats2half2_rn(acc[j][m][2], acc[j][m][3]);
                    }
                }
            }
        }
        __syncthreads();

        // coalesced fw writeout: 64 rows x 18 uint4 into this net's column range
        {
            __half* dstbase = g_fw + (size_t)e0 * FSG + net * 144;
            for (int i = tid; i < TE * 18; i += 512) {
                int r = i / 18, c = i - r * 18;
                *(uint4*)(dstbase + r * FSG + c * 8) =
                    *(const uint4*)&sm.fw[r * FS2 + c * 8];
            }
        }
    }
}

// ---------------- K_att: attention logits + scatter (high occupancy) ----------------
struct __align__(16) ASm {
    __half fwa[TE * FSG];   // 36864 B
    float  al [TE * 8];     //  2048 B
    float  cut[TE];
    int    sidx[TE];
    int    ridx[TE];
};

__global__ __launch_bounds__(256) void att_kernel(
    const float* __restrict__ cutoffs,
    const int*   __restrict__ senders,
    const int*   __restrict__ receivers,
    const float* __restrict__ sh)
{
    __shared__ ASm sm;
    const int tid = threadIdx.x;
    const int w = tid >> 5, lane = tid & 31;
    const int e0 = blockIdx.x * TE;

    if (tid < TE) {
        sm.sidx[tid] = senders[e0 + tid];
        sm.ridx[tid] = receivers[e0 + tid];
        sm.cut[tid]  = cutoffs[e0 + tid];
    }
    {
        const uint4* src = (const uint4*)(g_fw + (size_t)e0 * FSG);
        uint4* dst = (uint4*)sm.fwa;
        for (int i = tid; i < TE * (FSG / 8); i += 256)
            dst[i] = src[i];
    }
    __syncthreads();

    // alpha: 448 tasks over 8 warps, 2-way interleaved (fp16 q/k gathers)
    {
        const float INVN = 0.17407765595569785f;  // 1/sqrt(33)
        const float INVE = 0.15075567228888181f;  // 1/sqrt(44)
        for (int p = 0; p < 28; p++) {
            int taskA = w + 8 * (2 * p);
            int taskB = w + 8 * (2 * p + 1);
            int tA = taskA / 7, hA = taskA - 7 * tA;
            int tB = taskB / 7, hB = taskB - 7 * tB;

            const __half *qA, *kA; int fbA, DA; float nmA;
            if (hA < 4) { qA = g_q_inv + sm.ridx[tA] * Ff + hA * 33;
                          kA = g_k_inv + sm.sidx[tA] * Ff + hA * 33;
                          fbA = tA * FSG + hA * 33; DA = 33; nmA = INVN; }
            else        { int hh = hA - 4;
                          qA = g_q_ev + sm.ridx[tA] * Ff + hh * 44;
                          kA = g_k_ev + sm.sidx[tA] * Ff + hh * 44;
                          fbA = tA * FSG + 144 + hh * 44; DA = 44; nmA = INVE; }
            const __half *qB, *kB; int fbB, DB; float nmB;
            if (hB < 4) { qB = g_q_inv + sm.ridx[tB] * Ff + hB * 33;
                          kB = g_k_inv + sm.sidx[tB] * Ff + hB * 33;
                          fbB = tB * FSG + hB * 33; DB = 33; nmB = INVN; }
            else        { int hh = hB - 4;
                          qB = g_q_ev + sm.ridx[tB] * Ff + hh * 44;
                          kB = g_k_ev + sm.sidx[tB] * Ff + hh * 44;
                          fbB = tB * FSG + 144 + hh * 44; DB = 44; nmB = INVE; }

            float aA = __half2float(qA[lane]) * __half2float(kA[lane])
                     * __half2float(sm.fwa[fbA + lane]);
            float aB = __half2float(qB[lane]) * __half2float(kB[lane])
                     * __half2float(sm.fwa[fbB + lane]);
            int d1 = lane + 32;
            if (d1 < DA) aA += __half2float(qA[d1]) * __half2float(kA[d1])
                             * __half2float(sm.fwa[fbA + d1]);
            if (d1 < DB) aB += __half2float(qB[d1]) * __half2float(kB[d1])
                             * __half2float(sm.fwa[fbB + d1]);
#pragma unroll
            for (int s = 16; s > 0; s >>= 1) {
                aA += __shfl_xor_sync(0xFFFFFFFFu, aA, s);
                aB += __shfl_xor_sync(0xFFFFFFFFu, aB, s);
            }
            if (lane == 0) {
                sm.al[tA * 8 + hA] = aA * nmA * sm.cut[tA];
                sm.al[tB * 8 + hB] = aB * nmB * sm.cut[tB];
            }
        }
    }
    __syncthreads();

    // scatter: inv messages via 128-bit reductions (33 float4 per edge)
    for (int i = tid; i < TE * 33; i += 256) {
        int t = i / 33, c4 = i - 33 * t;
        int f0 = 4 * c4;
        const float4 v = *(const float4*)(g_v_inv + sm.sidx[t] * Ff + f0);
        float r0 = sm.al[t * 8 + (f0 + 0) / 33] * v.x;
        float r1 = sm.al[t * 8 + (f0 + 1) / 33] * v.y;
        float r2 = sm.al[t * 8 + (f0 + 2) / 33] * v.z;
        float r3 = sm.al[t * 8 + (f0 + 3) / 33] * v.w;
        red_add_v4(g_dinv + sm.ridx[t] * Ff + f0, r0, r1, r2, r3);
    }
    // scatter: ev messages (4 float4 per edge, padded row of 16)
    for (int i = tid; i < TE * 4; i += 256) {
        int t = i >> 2, q4 = i & 3;
        int j0 = 4 * q4;
        float r[4];
#pragma unroll
        for (int u = 0; u < 4; u++) {
            int j = j0 + u;
            if (j < EVd) {
                int gg = (j < 3) ? 0 : ((j < 8) ? 1 : 2);
                r[u] = sm.al[t * 8 + 4 + gg] * sh[(e0 + t) * EVd + j];
            } else r[u] = 0.0f;
        }
        red_add_v4(g_dev + sm.ridx[t] * 16 + j0, r[0], r[1], r[2], r[3]);
    }
}

// ---------------- final node update (transposed smem, float4 broadcast) ----------------
#define TNF 8
__global__ __launch_bounds__(160) void final_kernel(
    const float* __restrict__ inv_features,
    const float* __restrict__ ev_features,
    const float* __restrict__ W_int,
    const float* __restrict__ b_int,
    float* __restrict__ out)
{
    __shared__ __align__(16) float ct[136 * TNF];   // transposed cat: [k][t]
    __shared__ float ev1_s[TNF][EVd];
    __shared__ float tb_s[TNF][3];
    const int n0 = blockIdx.x * TNF;

    for (int i = threadIdx.x; i < TNF * Ff; i += 160) {
        const int t = i & 7, f = i >> 3;
        ct[f * TNF + t] = inv_features[(n0 + t) * Ff + f] + g_dinv[(n0 + t) * Ff + f];
    }
    for (int i = threadIdx.x; i < TNF * EVd; i += 160) {
        const int t = i / EVd, j = i - EVd * t;
        ev1_s[t][j] = ev_features[(n0 + t) * EVd + j] + g_dev[(n0 + t) * 16 + j];
    }
    __syncthreads();
    for (int i = threadIdx.x; i < TNF * 3; i += 160) {
        const int t = i / 3, g = i - 3 * t;
        const int js = (g == 0) ? 0 : ((g == 1) ? 3 : 8);
        const int je = (g == 0) ? 3 : ((g == 1) ? 8 : 15);
        float a = 0.0f;
        for (int j = js; j < je; j++) {
            const float v = ev1_s[t][j];
            a += v * v;
        }
        ct[(132 + g) * TNF + t] = a;
    }
    __syncthreads();

    if (threadIdx.x < 135) {
        const int f = threadIdx.x;
        const float b = b_int[f];
        float4 a0 = make_float4(b, b, b, b);
        float4 a1 = a0;
        for (int k = 0; k < 135; k++) {
            const float w = W_int[k * 135 + f];
            const float4* xr = (const float4*)&ct[k * TNF];
            const float4 x0 = xr[0], x1 = xr[1];
            a0.x += x0.x * w; a0.y += x0.y * w; a0.z += x0.z * w; a0.w += x0.w * w;
            a1.x += x1.x * w; a1.y += x1.y * w; a1.z += x1.z * w; a1.w += x1.w * w;
        }
        float acc[TNF] = {a0.x, a0.y, a0.z, a0.w, a1.x, a1.y, a1.z, a1.w};
        if (f < 132) {
#pragma unroll
            for (int t = 0; t < TNF; t++)
                out[(n0 + t) * Ff + f] = ct[f * TNF + t] + acc[t];
        } else {
#pragma unroll
            for (int t = 0; t < TNF; t++) tb_s[t][f - 132] = acc[t];
        }
    }
    __syncthreads();

    float* out_ev = out + Nn * Ff;
    for (int i = threadIdx.x; i < TNF * EVd; i += 160) {
        const int t = i / EVd, j = i - EVd * t;
        const int g = (j < 3) ? 0 : ((j < 8) ? 1 : 2);
        out_ev[(n0 + t) * EVd + j] = ev1_s[t][j] * (1.0f + tb_s[t][g]);
    }
}

// ---------------- launch ----------------
extern "C" void kernel_launch(void* const* d_in, const int* in_sizes, int n_in,
                              void* d_out, int out_size)
{
    const float* inv_features = (const float*)d_in[0];
    const float* ev_features  = (const float*)d_in[1];
    const float* rbf          = (const float*)d_in[2];
    const float* sh_vectors   = (const float*)d_in[3];
    const float* cutoffs      = (const float*)d_in[4];
    const int*   senders      = (const int*)d_in[5];
    const int*   receivers    = (const int*)d_in[6];
    const float* Wq_inv = (const float*)d_in[7];
    const float* Wk_inv = (const float*)d_in[8];
    const float* Wv_inv = (const float*)d_in[9];
    const float* Wq_ev  = (const float*)d_in[10];
    const float* Wk_ev  = (const float*)d_in[11];
    const float* fi_rW1 = (const float*)d_in[12];
    const float* fi_rb1 = (const float*)d_in[13];
    const float* fi_rW2 = (const float*)d_in[14];
    const float* fi_rb2 = (const float*)d_in[15];
    const float* fi_eW1 = (const float*)d_in[16];
    const float* fi_eb1 = (const float*)d_in[17];
    const float* fi_eW2 = (const float*)d_in[18];
    const float* fi_eb2 = (const float*)d_in[19];
    const float* fe_rW1 = (const float*)d_in[20];
    const float* fe_rb1 = (const float*)d_in[21];
    const float* fe_rW2 = (const float*)d_in[22];
    const float* fe_rb2 = (const float*)d_in[23];
    const float* fe_eW1 = (const float*)d_in[24];
    const float* fe_eb1 = (const float*)d_in[25];
    const float* fe_eW2 = (const float*)d_in[26];
    const float* fe_eb2 = (const float*)d_in[27];
    const float* W_int  = (const float*)d_in[28];
    const float* b_int  = (const float*)d_in[29];
    float* out = (float*)d_out;

    cudaFuncSetAttribute(gemm_kernel,
                         cudaFuncAttributeMaxDynamicSharedMemorySize,
                         (int)sizeof(GSm2));

    zero_kernel<<<512, 256>>>();
    prep_kernel<<<(2 * NTT * KS2 * 64 + 255) / 256, 256>>>(
        fi_rW1, fi_rb1, fi_rW2, fi_rb2, fi_eW2, fi_eb2,
        fe_rW1, fe_rb1, fe_rW2, fe_rb2, fe_eW2, fe_eb2);
    node_proj_kernel<<<Nn / TNA, 256>>>(inv_features, Wq_inv, Wk_inv, Wv_inv,
                                        Wq_ev, Wk_ev);
    gemm_kernel<<<GRIDG, 512, sizeof(GSm2)>>>(
        ev_features, rbf, senders, receivers,
        fi_eW1, fi_eb1, fe_eW1, fe_eb1);
    att_kernel<<<NTILES, 256>>>(cutoffs, senders, receivers, sh_vectors);
    final_kernel<<<Nn / TNF, 160>>>(inv_features, ev_features, W_int, b_int, out);
}

// round 13
// speedup vs baseline: 4.5890x; 1.0335x over previous
#include <cuda_runtime.h>
#include <cuda_fp16.h>

// Problem constants
#define Nn   50000
#define Ee   400000
#define Rr   32
#define Ff   132
#define EVd  15

#define TE     64    // edges per tile
#define NTILES 6250  // Ee / TE
#define GRIDG  296   // persistent gemm blocks (2 per SM)

#define NTT  18      // n-tiles per net (N padded 144)
#define KS2  12      // layer-2 k-steps (K padded 192)
#define AS2  200     // h1 row stride (halves)
#define FS2  152     // fw smem row stride (halves)
#define FSG  288     // fw gmem row stride (halves)
#define RS   40      // rbf smem row stride (halves)

// ---------------- device scratch ----------------
__device__ __half g_q_inv[Nn * Ff];
__device__ __half g_k_inv[Nn * Ff];
__device__ float  g_v_inv[Nn * Ff];
__device__ __half g_q_ev [Nn * Ff];
__device__ __half g_k_ev [Nn * Ff];
__device__ float  g_dinv [Nn * Ff];
__device__ float  g_dev  [Nn * 16];
__device__ __align__(16) __half g_fw[Ee * FSG];

// fragment-packed weights, PAIRED layout: slot = 2*lane + h (h: k vs k+8 frag)
__device__ __align__(16) unsigned int g_W2sw[2 * NTT * KS2 * 64];
__device__ __align__(16) unsigned int g_W1sw[2 * NTT * 2 * 64];
__device__ float g_b1c[2 * 144];
__device__ float g_b2c[2 * 144];

__device__ __forceinline__ float silu_f(float x) {
    return x / (1.0f + __expf(-x));
}

__device__ __forceinline__ void mma16816(float c[4],
    unsigned a0, unsigned a1, unsigned a2, unsigned a3,
    unsigned b0, unsigned b1)
{
    asm volatile(
        "mma.sync.aligned.m16n8k16.row.col.f32.f16.f16.f32 "
        "{%0,%1,%2,%3},{%4,%5,%6,%7},{%8,%9},{%0,%1,%2,%3};\n"
        : "+f"(c[0]), "+f"(c[1]), "+f"(c[2]), "+f"(c[3])
        : "r"(a0), "r"(a1), "r"(a2), "r"(a3), "r"(b0), "r"(b1));
}

__device__ __forceinline__ void ldsm4(unsigned& r0, unsigned& r1,
                                      unsigned& r2, unsigned& r3,
                                      unsigned addr)
{
    asm volatile(
        "ldmatrix.sync.aligned.m8n8.x4.shared.b16 {%0,%1,%2,%3}, [%4];\n"
        : "=r"(r0), "=r"(r1), "=r"(r2), "=r"(r3) : "r"(addr));
}

__device__ __forceinline__ void red_add_v4(float* p, float a, float b,
                                           float c, float d)
{
    asm volatile("red.global.add.v4.f32 [%0], {%1,%2,%3,%4};"
                 :: "l"(p), "f"(a), "f"(b), "f"(c), "f"(d) : "memory");
}

// ---------------- zero accumulators ----------------
__global__ void zero_kernel() {
    int i = blockIdx.x * blockDim.x + threadIdx.x;
    int stride = gridDim.x * blockDim.x;
    for (int j = i; j < Nn * Ff; j += stride) g_dinv[j] = 0.0f;
    for (int j = i; j < Nn * 16; j += stride) g_dev[j] = 0.0f;
}

// ---------------- weight prep (compact block-diagonal, paired frags) ----------------
__device__ __forceinline__ float W2com(int net, int k, int n,
    const float* fi_rW2, const float* fi_eW2,
    const float* fe_rW2, const float* fe_eW2)
{
    if (n >= 132) return 0.0f;
    if (k < 132)  return (net ? fe_rW2 : fi_rW2)[k * 132 + n];
    if (k >= 144 && k < 177) return (net ? fe_eW2 : fi_eW2)[(k - 144) * 132 + n];
    return 0.0f;
}

__global__ void prep_kernel(
    const float* __restrict__ fi_rW1, const float* __restrict__ fi_rb1,
    const float* __restrict__ fi_rW2, const float* __restrict__ fi_rb2,
    const float* __restrict__ fi_eW2, const float* __restrict__ fi_eb2,
    const float* __restrict__ fe_rW1, const float* __restrict__ fe_rb1,
    const float* __restrict__ fe_rW2, const float* __restrict__ fe_rb2,
    const float* __restrict__ fe_eW2, const float* __restrict__ fe_eb2)
{
    int i = blockIdx.x * blockDim.x + threadIdx.x;
    if (i < 2 * NTT * KS2 * 64) {
        int slot = i & 63;
        int blk = i >> 6;
        int ks = blk % KS2;
        int tmp = blk / KS2;
        int tt = tmp % NTT;
        int net = tmp / NTT;
        int lane = slot >> 1, h = slot & 1;
        int gq = lane >> 2, t4 = lane & 3;
        int k = ks * 16 + h * 8 + 2 * t4;
        int n = tt * 8 + gq;
        __half2 v = __floats2half2_rn(
            W2com(net, k,     n, fi_rW2, fi_eW2, fe_rW2, fe_eW2),
            W2com(net, k + 1, n, fi_rW2, fi_eW2, fe_rW2, fe_eW2));
        ((__half2*)g_W2sw)[i] = v;
    }
    if (i < 2 * NTT * 2 * 64) {
        int slot = i & 63;
        int blk = i >> 6;
        int ks = blk & 1;
        int tmp = blk >> 1;
        int tt = tmp % NTT;
        int net = tmp / NTT;
        int lane = slot >> 1, h = slot & 1;
        int gq = lane >> 2, t4 = lane & 3;
        int k = ks * 16 + h * 8 + 2 * t4;
        int n = tt * 8 + gq;
        const float* W = net ? fe_rW1 : fi_rW1;
        float v0 = (n < 132) ? W[k * 132 + n] : 0.0f;
        float v1 = (n < 132) ? W[(k + 1) * 132 + n] : 0.0f;
        ((__half2*)g_W1sw)[i] = __floats2half2_rn(v0, v1);
    }
    if (i < 2 * 144) {
        int net = i / 144, n = i % 144;
        float b1 = 0.0f, b2 = 0.0f;
        if (n < 132) {
            b1 = (net ? fe_rb1 : fi_rb1)[n];
            b2 = (net ? fe_rb2 : fi_rb2)[n] + (net ? fe_eb2 : fi_eb2)[n];
        }
        g_b1c[i] = b1;
        g_b2c[i] = b2;
    }
}

// ---------------- per-node projections (transposed smem, float4 broadcast) ----------------
#define TNA 16
#define XSW 20
__global__ __launch_bounds__(256) void node_proj_kernel(
    const float* __restrict__ x,
    const float* __restrict__ Wq_inv, const float* __restrict__ Wk_inv,
    const float* __restrict__ Wv_inv, const float* __restrict__ Wq_ev,
    const float* __restrict__ Wk_ev)
{
    __shared__ __align__(16) float xs[Ff * XSW];
    const int n0 = blockIdx.x * TNA;
    for (int i = threadIdx.x; i < TNA * Ff; i += 256) {
        int t = i / Ff, f = i - t * Ff;
        xs[f * XSW + t] = x[n0 * Ff + i];
    }
    __syncthreads();

    for (int idx = threadIdx.x; idx < 5 * Ff; idx += 256) {
        const int m = idx / Ff, c = idx - m * Ff;
        const float* W;
        int D, h, e;
        if (m < 3) {
            D = 33; h = c / 33; e = c - h * 33;
            W = (m == 0 ? Wq_inv : (m == 1 ? Wk_inv : Wv_inv)) + h * 33 * 33;
        } else {
            D = 44; h = c / 44; e = c - h * 44;
            W = (m == 3 ? Wq_ev : Wk_ev) + h * 44 * 44;
        }
        float4 a0 = make_float4(0.f, 0.f, 0.f, 0.f);
        float4 a1 = a0, a2 = a0, a3 = a0;
        const int xb = h * D;
        for (int d = 0; d < D; d++) {
            const float w = W[d * D + e];
            const float4* xr = (const float4*)&xs[(xb + d) * XSW];
            const float4 x0 = xr[0], x1 = xr[1], x2 = xr[2], x3 = xr[3];
            a0.x += x0.x * w; a0.y += x0.y * w; a0.z += x0.z * w; a0.w += x0.w * w;
            a1.x += x1.x * w; a1.y += x1.y * w; a1.z += x1.z * w; a1.w += x1.w * w;
            a2.x += x2.x * w; a2.y += x2.y * w; a2.z += x2.z * w; a2.w += x2.w * w;
            a3.x += x3.x * w; a3.y += x3.y * w; a3.z += x3.z * w; a3.w += x3.w * w;
        }
        float acc[TNA] = {a0.x, a0.y, a0.z, a0.w, a1.x, a1.y, a1.z, a1.w,
                          a2.x, a2.y, a2.z, a2.w, a3.x, a3.y, a3.z, a3.w};
        if (m == 2) {
#pragma unroll
            for (int t = 0; t < TNA; t++)
                g_v_inv[(n0 + t) * Ff + c] = acc[t];
        } else {
            __half* out = (m == 0) ? g_q_inv : (m == 1) ? g_k_inv
                        : (m == 3) ? g_q_ev : g_k_ev;
#pragma unroll
            for (int t = 0; t < TNA; t++)
                out[(n0 + t) * Ff + c] = __float2half(silu_f(acc[t]));
        }
    }
}

// ---------------- K_gemm: per-net persistent GEMM, M-split 512 threads ----------------
struct GSm2 {
    unsigned sW2[NTT * KS2 * 64];   // 55296 B
    float sb1[144];
    float sb2[144];
    float sevW[99];
    float sevB[33];
    __half h1[TE * AS2];            // 25600 B
    __half fw[TE * FS2];            // 19456 B
    __half rbfs[TE * RS];           //  5120 B
    float ev3[TE * 3];              //   768 B
};                                  // ~107 KB -> 2 blocks/SM

__global__ __launch_bounds__(512, 2) void gemm_kernel(
    const float* __restrict__ ev_features,
    const float* __restrict__ rbf_g,
    const int*   __restrict__ senders,
    const int*   __restrict__ receivers,
    const float* __restrict__ fi_eW1, const float* __restrict__ fi_eb1,
    const float* __restrict__ fe_eW1, const float* __restrict__ fe_eb1)
{
    extern __shared__ char smraw[];
    GSm2& sm = *reinterpret_cast<GSm2*>(smraw);
    const int tid = threadIdx.x;
    const int w = tid >> 5, lane = tid & 31;
    const int gq = lane >> 2, t4 = lane & 3;
    const int net = blockIdx.x & 1;
    const int mh = w >> 3;                    // m-half
    const int wn = w & 7;
    const int ntile = (wn < 2) ? 3 : 2;
    const int l15 = lane & 15;
    const int lc8 = (lane & 16) ? 8 : 0;

    // one-time staging (this net only)
    {
        const unsigned* src = g_W2sw + net * NTT * KS2 * 64;
        for (int i = tid; i < NTT * KS2 * 64; i += 512) sm.sW2[i] = src[i];
    }
    for (int i = tid; i < 144; i += 512) {
        sm.sb1[i] = g_b1c[net * 144 + i];
        sm.sb2[i] = g_b2c[net * 144 + i];
    }
    {
        const float* eW = net ? fe_eW1 : fi_eW1;
        const float* eB = net ? fe_eb1 : fi_eb1;
        for (int i = tid; i < 99; i += 512) sm.sevW[i] = eW[i];
        for (int i = tid; i < 33; i += 512) sm.sevB[i] = eB[i];
    }
    for (int i = tid; i < TE * AS2 / 2; i += 512)
        ((unsigned*)sm.h1)[i] = 0u;
    __syncthreads();

    const unsigned h1s  = (unsigned)__cvta_generic_to_shared(sm.h1);
    const unsigned rbss = (unsigned)__cvta_generic_to_shared(sm.rbfs);
    const unsigned a2base = h1s  + 2 * ((2 * mh) * 16 * AS2 + l15 * AS2 + lc8);
    const unsigned a1base = rbss + 2 * ((2 * mh) * 16 * RS + l15 * RS + lc8);
    const unsigned* W1n = g_W1sw + net * NTT * 2 * 64;

    for (int u = blockIdx.x; u < 2 * NTILES; u += GRIDG) {
        const int tile = u >> 1;
        const int e0 = tile * TE;
        __syncthreads();

        for (int i = tid; i < TE * Rr; i += 512) {
            int t = i >> 5, c = i & 31;
            sm.rbfs[t * RS + c] = __float2half(rbf_g[e0 * Rr + i]);
        }
        if (tid < TE * 3) {
            int t = tid / 3, g3 = tid - 3 * t;
            int js = (g3 == 0) ? 0 : ((g3 == 1) ? 3 : 8);
            int je = (g3 == 0) ? 3 : ((g3 == 1) ? 8 : 15);
            const float* evs = ev_features + senders[e0 + t] * EVd;
            const float* evr = ev_features + receivers[e0 + t] * EVd;
            float a = 0.0f;
            for (int j = js; j < je; j++) {
                float d = evs[j] - evr[j];
                a += d * d;
            }
            sm.ev3[t * 3 + g3] = a;
        }
        __syncthreads();

        // layer 1 (rbf branch)
        {
            float acc[3][2][4];
#pragma unroll
            for (int j = 0; j < 3; j++) {
                if (j < ntile) {
                    int nidx = (wn + 8 * j) * 8 + 2 * t4;
                    float b0f = sm.sb1[nidx], b1f = sm.sb1[nidx + 1];
#pragma unroll
                    for (int m = 0; m < 2; m++) {
                        acc[j][m][0] = b0f; acc[j][m][1] = b1f;
                        acc[j][m][2] = b0f; acc[j][m][3] = b1f;
                    }
                }
            }
#pragma unroll
            for (int ks = 0; ks < 2; ks++) {
                unsigned a[2][4];
#pragma unroll
                for (int m = 0; m < 2; m++)
                    ldsm4(a[m][0], a[m][1], a[m][2], a[m][3],
                          a1base + 2 * (m * 16 * RS + ks * 16));
#pragma unroll
                for (int j = 0; j < 3; j++) {
                    if (j < ntile) {
                        int tt = wn + 8 * j;
                        uint2 b = ((const uint2*)(W1n + (tt * 2 + ks) * 64))[lane];
#pragma unroll
                        for (int m = 0; m < 2; m++)
                            mma16816(acc[j][m], a[m][0], a[m][1], a[m][2], a[m][3], b.x, b.y);
                    }
                }
            }
#pragma unroll
            for (int j = 0; j < 3; j++) {
                if (j < ntile) {
                    int col = (wn + 8 * j) * 8 + 2 * t4;
#pragma unroll
                    for (int m = 0; m < 2; m++) {
                        int r = (2 * mh + m) * 16 + gq;
                        *(__half2*)&sm.h1[r * AS2 + col] =
                            __floats2half2_rn(silu_f(acc[j][m][0]), silu_f(acc[j][m][1]));
                        *(__half2*)&sm.h1[(r + 8) * AS2 + col] =
                            __floats2half2_rn(silu_f(acc[j][m][2]), silu_f(acc[j][m][3]));
                    }
                }
            }
        }
        // ev branch: 3 -> 33, h1 cols 144..176
        for (int i = tid; i < TE * 33; i += 512) {
            int t = i / 33, cc = i - 33 * t;
            float v = sm.sevB[cc]
                    + sm.ev3[t * 3 + 0] * sm.sevW[cc]
                    + sm.ev3[t * 3 + 1] * sm.sevW[33 + cc]
                    + sm.ev3[t * 3 + 2] * sm.sevW[66 + cc];
            sm.h1[t * AS2 + 144 + cc] = __float2half(silu_f(v));
        }
        __syncthreads();

        // layer 2: [64x192] x [192x144]
        {
            float acc[3][2][4];
#pragma unroll
            for (int j = 0; j < 3; j++) {
                if (j < ntile) {
                    int nidx = (wn + 8 * j) * 8 + 2 * t4;
                    float b0f = sm.sb2[nidx], b1f = sm.sb2[nidx + 1];
#pragma unroll
                    for (int m = 0; m < 2; m++) {
                        acc[j][m][0] = b0f; acc[j][m][1] = b1f;
                        acc[j][m][2] = b0f; acc[j][m][3] = b1f;
                    }
                }
            }
#pragma unroll 3
            for (int ks = 0; ks < KS2; ks++) {
                unsigned a[2][4];
#pragma unroll
                for (int m = 0; m < 2; m++)
                    ldsm4(a[m][0], a[m][1], a[m][2], a[m][3],
                          a2base + 2 * (m * 16 * AS2 + ks * 16));
#pragma unroll
                for (int j = 0; j < 3; j++) {
                    if (j < ntile) {
                        int tt = wn + 8 * j;
                        uint2 b = ((const uint2*)(sm.sW2 + (tt * KS2 + ks) * 64))[lane];
#pragma unroll
                        for (int m = 0; m < 2; m++)
                            mma16816(acc[j][m], a[m][0], a[m][1], a[m][2], a[m][3], b.x, b.y);
                    }
                }
            }
#pragma unroll
            for (int j = 0; j < 3; j++) {
                if (j < ntile) {
                    int col = (wn + 8 * j) * 8 + 2 * t4;
#pragma unroll
                    for (int m = 0; m < 2; m++) {
                        int r = (2 * mh + m) * 16 + gq;
                        *(__half2*)&sm.fw[r * FS2 + col] =
                            __floats2half2_rn(acc[j][m][0], acc[j][m][1]);
                        *(__half2*)&sm.fw[(r + 8) * FS2 + col] =
                            __floats2half2_rn(acc[j][m][2], acc[j][m][3]);
                    }
                }
            }
        }
        __syncthreads();

        // coalesced fw writeout
        {
            __half* dstbase = g_fw + (size_t)e0 * FSG + net * 144;
            for (int i = tid; i < TE * 18; i += 512) {
                int r = i / 18, c = i - r * 18;
                *(uint4*)(dstbase + r * FSG + c * 8) =
                    *(const uint4*)&sm.fw[r * FS2 + c * 8];
            }
        }
    }
}

// ---------------- K_att: attention logits + scatter (no fw staging) ----------------
struct ASm {
    float  al [TE * 8];
    float  cut[TE];
    int    sidx[TE];
    int    ridx[TE];
};

__global__ __launch_bounds__(256) void att_kernel(
    const float* __restrict__ cutoffs,
    const int*   __restrict__ senders,
    const int*   __restrict__ receivers,
    const float* __restrict__ sh)
{
    __shared__ ASm sm;
    const int tid = threadIdx.x;
    const int w = tid >> 5, lane = tid & 31;
    const int e0 = blockIdx.x * TE;

    if (tid < TE) {
        sm.sidx[tid] = senders[e0 + tid];
        sm.ridx[tid] = receivers[e0 + tid];
        sm.cut[tid]  = cutoffs[e0 + tid];
    }
    __syncthreads();

    // alpha: 448 tasks over 8 warps, 2-way interleaved; fw read directly (single-use)
    {
        const float INVN = 0.17407765595569785f;  // 1/sqrt(33)
        const float INVE = 0.15075567228888181f;  // 1/sqrt(44)
        for (int p = 0; p < 28; p++) {
            int taskA = w + 8 * (2 * p);
            int taskB = w + 8 * (2 * p + 1);
            int tA = taskA / 7, hA = taskA - 7 * tA;
            int tB = taskB / 7, hB = taskB - 7 * tB;

            const __half *qA, *kA, *fA; int DA; float nmA;
            if (hA < 4) { qA = g_q_inv + sm.ridx[tA] * Ff + hA * 33;
                          kA = g_k_inv + sm.sidx[tA] * Ff + hA * 33;
                          fA = g_fw + (size_t)(e0 + tA) * FSG + hA * 33;
                          DA = 33; nmA = INVN; }
            else        { int hh = hA - 4;
                          qA = g_q_ev + sm.ridx[tA] * Ff + hh * 44;
                          kA = g_k_ev + sm.sidx[tA] * Ff + hh * 44;
                          fA = g_fw + (size_t)(e0 + tA) * FSG + 144 + hh * 44;
                          DA = 44; nmA = INVE; }
            const __half *qB, *kB, *fB; int DB; float nmB;
            if (hB < 4) { qB = g_q_inv + sm.ridx[tB] * Ff + hB * 33;
                          kB = g_k_inv + sm.sidx[tB] * Ff + hB * 33;
                          fB = g_fw + (size_t)(e0 + tB) * FSG + hB * 33;
                          DB = 33; nmB = INVN; }
            else        { int hh = hB - 4;
                          qB = g_q_ev + sm.ridx[tB] * Ff + hh * 44;
                          kB = g_k_ev + sm.sidx[tB] * Ff + hh * 44;
                          fB = g_fw + (size_t)(e0 + tB) * FSG + 144 + hh * 44;
                          DB = 44; nmB = INVE; }

            float aA = __half2float(qA[lane]) * __half2float(kA[lane])
                     * __half2float(fA[lane]);
            float aB = __half2float(qB[lane]) * __half2float(kB[lane])
                     * __half2float(fB[lane]);
            int d1 = lane + 32;
            if (d1 < DA) aA += __half2float(qA[d1]) * __half2float(kA[d1])
                             * __half2float(fA[d1]);
            if (d1 < DB) aB += __half2float(qB[d1]) * __half2float(kB[d1])
                             * __half2float(fB[d1]);
#pragma unroll
            for (int s = 16; s > 0; s >>= 1) {
                aA += __shfl_xor_sync(0xFFFFFFFFu, aA, s);
                aB += __shfl_xor_sync(0xFFFFFFFFu, aB, s);
            }
            if (lane == 0) {
                sm.al[tA * 8 + hA] = aA * nmA * sm.cut[tA];
                sm.al[tB * 8 + hB] = aB * nmB * sm.cut[tB];
            }
        }
    }
    __syncthreads();

    // scatter: inv messages via 128-bit reductions (33 float4 per edge)
    for (int i = tid; i < TE * 33; i += 256) {
        int t = i / 33, c4 = i - 33 * t;
        int f0 = 4 * c4;
        const float4 v = *(const float4*)(g_v_inv + sm.sidx[t] * Ff + f0);
        float r0 = sm.al[t * 8 + (f0 + 0) / 33] * v.x;
        float r1 = sm.al[t * 8 + (f0 + 1) / 33] * v.y;
        float r2 = sm.al[t * 8 + (f0 + 2) / 33] * v.z;
        float r3 = sm.al[t * 8 + (f0 + 3) / 33] * v.w;
        red_add_v4(g_dinv + sm.ridx[t] * Ff + f0, r0, r1, r2, r3);
    }
    // scatter: ev messages (4 float4 per edge, padded row of 16)
    for (int i = tid; i < TE * 4; i += 256) {
        int t = i >> 2, q4 = i & 3;
        int j0 = 4 * q4;
        float r[4];
#pragma unroll
        for (int u = 0; u < 4; u++) {
            int j = j0 + u;
            if (j < EVd) {
                int gg = (j < 3) ? 0 : ((j < 8) ? 1 : 2);
                r[u] = sm.al[t * 8 + 4 + gg] * sh[(e0 + t) * EVd + j];
            } else r[u] = 0.0f;
        }
        red_add_v4(g_dev + sm.ridx[t] * 16 + j0, r[0], r[1], r[2], r[3]);
    }
}

// ---------------- final node update (transposed smem, float4 broadcast) ----------------
#define TNF 8
__global__ __launch_bounds__(160) void final_kernel(
    const float* __restrict__ inv_features,
    const float* __restrict__ ev_features,
    const float* __restrict__ W_int,
    const float* __restrict__ b_int,
    float* __restrict__ out)
{
    __shared__ __align__(16) float ct[136 * TNF];
    __shared__ float ev1_s[TNF][EVd];
    __shared__ float tb_s[TNF][3];
    const int n0 = blockIdx.x * TNF;

    for (int i = threadIdx.x; i < TNF * Ff; i += 160) {
        const int t = i & 7, f = i >> 3;
        ct[f * TNF + t] = inv_features[(n0 + t) * Ff + f] + g_dinv[(n0 + t) * Ff + f];
    }
    for (int i = threadIdx.x; i < TNF * EVd; i += 160) {
        const int t = i / EVd, j = i - EVd * t;
        ev1_s[t][j] = ev_features[(n0 + t) * EVd + j] + g_dev[(n0 + t) * 16 + j];
    }
    __syncthreads();
    for (int i = threadIdx.x; i < TNF * 3; i += 160) {
        const int t = i / 3, g = i - 3 * t;
        const int js = (g == 0) ? 0 : ((g == 1) ? 3 : 8);
        const int je = (g == 0) ? 3 : ((g == 1) ? 8 : 15);
        float a = 0.0f;
        for (int j = js; j < je; j++) {
            const float v = ev1_s[t][j];
            a += v * v;
        }
        ct[(132 + g) * TNF + t] = a;
    }
    __syncthreads();

    if (threadIdx.x < 135) {
        const int f = threadIdx.x;
        const float b = b_int[f];
        float4 a0 = make_float4(b, b, b, b);
        float4 a1 = a0;
        for (int k = 0; k < 135; k++) {
            const float w = W_int[k * 135 + f];
            const float4* xr = (const float4*)&ct[k * TNF];
            const float4 x0 = xr[0], x1 = xr[1];
            a0.x += x0.x * w; a0.y += x0.y * w; a0.z += x0.z * w; a0.w += x0.w * w;
            a1.x += x1.x * w; a1.y += x1.y * w; a1.z += x1.z * w; a1.w += x1.w * w;
        }
        float acc[TNF] = {a0.x, a0.y, a0.z, a0.w, a1.x, a1.y, a1.z, a1.w};
        if (f < 132) {
#pragma unroll
            for (int t = 0; t < TNF; t++)
                out[(n0 + t) * Ff + f] = ct[f * TNF + t] + acc[t];
        } else {
#pragma unroll
            for (int t = 0; t < TNF; t++) tb_s[t][f - 132] = acc[t];
        }
    }
    __syncthreads();

    float* out_ev = out + Nn * Ff;
    for (int i = threadIdx.x; i < TNF * EVd; i += 160) {
        const int t = i / EVd, j = i - EVd * t;
        const int g = (j < 3) ? 0 : ((j < 8) ? 1 : 2);
        out_ev[(n0 + t) * EVd + j] = ev1_s[t][j] * (1.0f + tb_s[t][g]);
    }
}

// ---------------- launch ----------------
extern "C" void kernel_launch(void* const* d_in, const int* in_sizes, int n_in,
                              void* d_out, int out_size)
{
    const float* inv_features = (const float*)d_in[0];
    const float* ev_features  = (const float*)d_in[1];
    const float* rbf          = (const float*)d_in[2];
    const float* sh_vectors   = (const float*)d_in[3];
    const float* cutoffs      = (const float*)d_in[4];
    const int*   senders      = (const int*)d_in[5];
    const int*   receivers    = (const int*)d_in[6];
    const float* Wq_inv = (const float*)d_in[7];
    const float* Wk_inv = (const float*)d_in[8];
    const float* Wv_inv = (const float*)d_in[9];
    const float* Wq_ev  = (const float*)d_in[10];
    const float* Wk_ev  = (const float*)d_in[11];
    const float* fi_rW1 = (const float*)d_in[12];
    const float* fi_rb1 = (const float*)d_in[13];
    const float* fi_rW2 = (const float*)d_in[14];
    const float* fi_rb2 = (const float*)d_in[15];
    const float* fi_eW1 = (const float*)d_in[16];
    const float* fi_eb1 = (const float*)d_in[17];
    const float* fi_eW2 = (const float*)d_in[18];
    const float* fi_eb2 = (const float*)d_in[19];
    const float* fe_rW1 = (const float*)d_in[20];
    const float* fe_rb1 = (const float*)d_in[21];
    const float* fe_rW2 = (const float*)d_in[22];
    const float* fe_rb2 = (const float*)d_in[23];
    const float* fe_eW1 = (const float*)d_in[24];
    const float* fe_eb1 = (const float*)d_in[25];
    const float* fe_eW2 = (const float*)d_in[26];
    const float* fe_eb2 = (const float*)d_in[27];
    const float* W_int  = (const float*)d_in[28];
    const float* b_int  = (const float*)d_in[29];
    float* out = (float*)d_out;

    cudaFuncSetAttribute(gemm_kernel,
                         cudaFuncAttributeMaxDynamicSharedMemorySize,
                         (int)sizeof(GSm2));

    zero_kernel<<<512, 256>>>();
    prep_kernel<<<(2 * NTT * KS2 * 64 + 255) / 256, 256>>>(
        fi_rW1, fi_rb1, fi_rW2, fi_rb2, fi_eW2, fi_eb2,
        fe_rW1, fe_rb1, fe_rW2, fe_rb2, fe_eW2, fe_eb2);
    node_proj_kernel<<<Nn / TNA, 256>>>(inv_features, Wq_inv, Wk_inv, Wv_inv,
                                        Wq_ev, Wk_ev);
    gemm_kernel<<<GRIDG, 512, sizeof(GSm2)>>>(
        ev_features, rbf, senders, receivers,
        fi_eW1, fi_eb1, fe_eW1, fe_eb1);
    att_kernel<<<NTILES, 256>>>(cutoffs, senders, receivers, sh_vectors);
    final_kernel<<<Nn / TNF, 160>>>(inv_features, ev_features, W_int, b_int, out);
}

// round 14
// speedup vs baseline: 4.6603x; 1.0156x over previous
#include <cuda_runtime.h>
#include <cuda_fp16.h>

// Problem constants
#define Nn   50000
#define Ee   400000
#define Rr   32
#define Ff   132
#define EVd  15

#define TE     64    // edges per tile
#define NTILES 6250  // Ee / TE
#define GRIDG  296   // persistent gemm blocks (2 per SM)

#define NTT  18      // n-tiles per net (N padded 144)
#define KS2  11      // layer-2 k-steps (K padded 176: 132 rbf + 33 ev + pad)
#define AS2  184     // h1 row stride (halves), 368B rows
#define FS2  152     // fw smem row stride (halves)
#define FSG  288     // fw gmem row stride (halves)
#define RS   40      // rbf smem row stride (halves)

// ---------------- device scratch ----------------
__device__ __half g_q_inv[Nn * Ff];
__device__ __half g_k_inv[Nn * Ff];
__device__ float  g_v_inv[Nn * Ff];
__device__ __half g_q_ev [Nn * Ff];
__device__ __half g_k_ev [Nn * Ff];
__device__ float  g_dinv [Nn * Ff];
__device__ float  g_dev  [Nn * 16];
__device__ __align__(16) __half g_fw[Ee * FSG];

// fragment-packed weights, paired layout: slot = 2*lane + h
__device__ __align__(16) unsigned int g_W2sw[2 * NTT * KS2 * 64];
__device__ __align__(16) unsigned int g_W1sw[2 * NTT * 2 * 64];
__device__ float g_b1c[2 * 144];
__device__ float g_b2c[2 * 144];

__device__ __forceinline__ float silu_f(float x) {
    return x / (1.0f + __expf(-x));
}

__device__ __forceinline__ void mma16816(float c[4],
    unsigned a0, unsigned a1, unsigned a2, unsigned a3,
    unsigned b0, unsigned b1)
{
    asm volatile(
        "mma.sync.aligned.m16n8k16.row.col.f32.f16.f16.f32 "
        "{%0,%1,%2,%3},{%4,%5,%6,%7},{%8,%9},{%0,%1,%2,%3};\n"
        : "+f"(c[0]), "+f"(c[1]), "+f"(c[2]), "+f"(c[3])
        : "r"(a0), "r"(a1), "r"(a2), "r"(a3), "r"(b0), "r"(b1));
}

__device__ __forceinline__ void ldsm4(unsigned& r0, unsigned& r1,
                                      unsigned& r2, unsigned& r3,
                                      unsigned addr)
{
    asm volatile(
        "ldmatrix.sync.aligned.m8n8.x4.shared.b16 {%0,%1,%2,%3}, [%4];\n"
        : "=r"(r0), "=r"(r1), "=r"(r2), "=r"(r3) : "r"(addr));
}

__device__ __forceinline__ void red_add_v4(float* p, float a, float b,
                                           float c, float d)
{
    asm volatile("red.global.add.v4.f32 [%0], {%1,%2,%3,%4};"
                 :: "l"(p), "f"(a), "f"(b), "f"(c), "f"(d) : "memory");
}

// ---------------- zero accumulators ----------------
__global__ void zero_kernel() {
    int i = blockIdx.x * blockDim.x + threadIdx.x;
    int stride = gridDim.x * blockDim.x;
    for (int j = i; j < Nn * Ff; j += stride) g_dinv[j] = 0.0f;
    for (int j = i; j < Nn * 16; j += stride) g_dev[j] = 0.0f;
}

// ---------------- weight prep (K=176 packing: rbf 0..131, ev 132..164) ----------------
__device__ __forceinline__ float W2com(int net, int k, int n,
    const float* fi_rW2, const float* fi_eW2,
    const float* fe_rW2, const float* fe_eW2)
{
    if (n >= 132) return 0.0f;
    if (k < 132)  return (net ? fe_rW2 : fi_rW2)[k * 132 + n];
    if (k < 165)  return (net ? fe_eW2 : fi_eW2)[(k - 132) * 132 + n];
    return 0.0f;
}

__global__ void prep_kernel(
    const float* __restrict__ fi_rW1, const float* __restrict__ fi_rb1,
    const float* __restrict__ fi_rW2, const float* __restrict__ fi_rb2,
    const float* __restrict__ fi_eW2, const float* __restrict__ fi_eb2,
    const float* __restrict__ fe_rW1, const float* __restrict__ fe_rb1,
    const float* __restrict__ fe_rW2, const float* __restrict__ fe_rb2,
    const float* __restrict__ fe_eW2, const float* __restrict__ fe_eb2)
{
    int i = blockIdx.x * blockDim.x + threadIdx.x;
    if (i < 2 * NTT * KS2 * 64) {
        int slot = i & 63;
        int blk = i >> 6;
        int ks = blk % KS2;
        int tmp = blk / KS2;
        int tt = tmp % NTT;
        int net = tmp / NTT;
        int lane = slot >> 1, h = slot & 1;
        int gq = lane >> 2, t4 = lane & 3;
        int k = ks * 16 + h * 8 + 2 * t4;
        int n = tt * 8 + gq;
        __half2 v = __floats2half2_rn(
            W2com(net, k,     n, fi_rW2, fi_eW2, fe_rW2, fe_eW2),
            W2com(net, k + 1, n, fi_rW2, fi_eW2, fe_rW2, fe_eW2));
        ((__half2*)g_W2sw)[i] = v;
    }
    if (i < 2 * NTT * 2 * 64) {
        int slot = i & 63;
        int blk = i >> 6;
        int ks = blk & 1;
        int tmp = blk >> 1;
        int tt = tmp % NTT;
        int net = tmp / NTT;
        int lane = slot >> 1, h = slot & 1;
        int gq = lane >> 2, t4 = lane & 3;
        int k = ks * 16 + h * 8 + 2 * t4;
        int n = tt * 8 + gq;
        const float* W = net ? fe_rW1 : fi_rW1;
        float v0 = (n < 132) ? W[k * 132 + n] : 0.0f;
        float v1 = (n < 132) ? W[(k + 1) * 132 + n] : 0.0f;
        ((__half2*)g_W1sw)[i] = __floats2half2_rn(v0, v1);
    }
    if (i < 2 * 144) {
        int net = i / 144, n = i % 144;
        float b1 = 0.0f, b2 = 0.0f;
        if (n < 132) {
            b1 = (net ? fe_rb1 : fi_rb1)[n];
            b2 = (net ? fe_rb2 : fi_rb2)[n] + (net ? fe_eb2 : fi_eb2)[n];
        }
        g_b1c[i] = b1;
        g_b2c[i] = b2;
    }
}

// ---------------- per-node projections (transposed smem, float4 broadcast) ----------------
#define TNA 16
#define XSW 20
__global__ __launch_bounds__(256) void node_proj_kernel(
    const float* __restrict__ x,
    const float* __restrict__ Wq_inv, const float* __restrict__ Wk_inv,
    const float* __restrict__ Wv_inv, const float* __restrict__ Wq_ev,
    const float* __restrict__ Wk_ev)
{
    __shared__ __align__(16) float xs[Ff * XSW];
    const int n0 = blockIdx.x * TNA;
    for (int i = threadIdx.x; i < TNA * Ff; i += 256) {
        int t = i / Ff, f = i - t * Ff;
        xs[f * XSW + t] = x[n0 * Ff + i];
    }
    __syncthreads();

    for (int idx = threadIdx.x; idx < 5 * Ff; idx += 256) {
        const int m = idx / Ff, c = idx - m * Ff;
        const float* W;
        int D, h, e;
        if (m < 3) {
            D = 33; h = c / 33; e = c - h * 33;
            W = (m == 0 ? Wq_inv : (m == 1 ? Wk_inv : Wv_inv)) + h * 33 * 33;
        } else {
            D = 44; h = c / 44; e = c - h * 44;
            W = (m == 3 ? Wq_ev : Wk_ev) + h * 44 * 44;
        }
        float4 a0 = make_float4(0.f, 0.f, 0.f, 0.f);
        float4 a1 = a0, a2 = a0, a3 = a0;
        const int xb = h * D;
        for (int d = 0; d < D; d++) {
            const float w = W[d * D + e];
            const float4* xr = (const float4*)&xs[(xb + d) * XSW];
            const float4 x0 = xr[0], x1 = xr[1], x2 = xr[2], x3 = xr[3];
            a0.x += x0.x * w; a0.y += x0.y * w; a0.z += x0.z * w; a0.w += x0.w * w;
            a1.x += x1.x * w; a1.y += x1.y * w; a1.z += x1.z * w; a1.w += x1.w * w;
            a2.x += x2.x * w; a2.y += x2.y * w; a2.z += x2.z * w; a2.w += x2.w * w;
            a3.x += x3.x * w; a3.y += x3.y * w; a3.z += x3.z * w; a3.w += x3.w * w;
        }
        float acc[TNA] = {a0.x, a0.y, a0.z, a0.w, a1.x, a1.y, a1.z, a1.w,
                          a2.x, a2.y, a2.z, a2.w, a3.x, a3.y, a3.z, a3.w};
        if (m == 2) {
#pragma unroll
            for (int t = 0; t < TNA; t++)
                g_v_inv[(n0 + t) * Ff + c] = acc[t];
        } else {
            __half* out = (m == 0) ? g_q_inv : (m == 1) ? g_k_inv
                        : (m == 3) ? g_q_ev : g_k_ev;
#pragma unroll
            for (int t = 0; t < TNA; t++)
                out[(n0 + t) * Ff + c] = __float2half(silu_f(acc[t]));
        }
    }
}

// ---------------- K_gemm: per-net persistent GEMM, M-split 512 threads ----------------
struct GSm2 {
    unsigned sW2[NTT * KS2 * 64];   // 50688 B
    float sb1[144];
    float sb2[144];
    float sevW[99];
    float sevB[33];
    __half h1[TE * AS2];            // 23552 B
    __half fw[TE * FS2];            // 19456 B
    __half rbfs[TE * RS];           //  5120 B
    float ev3[TE * 3];              //   768 B
};                                  // ~101 KB -> 2 blocks/SM

__global__ __launch_bounds__(512, 2) void gemm_kernel(
    const float* __restrict__ ev_features,
    const float* __restrict__ rbf_g,
    const int*   __restrict__ senders,
    const int*   __restrict__ receivers,
    const float* __restrict__ fi_eW1, const float* __restrict__ fi_eb1,
    const float* __restrict__ fe_eW1, const float* __restrict__ fe_eb1)
{
    extern __shared__ char smraw[];
    GSm2& sm = *reinterpret_cast<GSm2*>(smraw);
    const int tid = threadIdx.x;
    const int w = tid >> 5, lane = tid & 31;
    const int gq = lane >> 2, t4 = lane & 3;
    const int net = blockIdx.x & 1;
    const int mh = w >> 3;                    // m-half
    const int wn = w & 7;
    const int ntile = (wn < 2) ? 3 : 2;
    const int l15 = lane & 15;
    const int lc8 = (lane & 16) ? 8 : 0;

    // one-time staging (this net only)
    {
        const unsigned* src = g_W2sw + net * NTT * KS2 * 64;
        for (int i = tid; i < NTT * KS2 * 64; i += 512) sm.sW2[i] = src[i];
    }
    for (int i = tid; i < 144; i += 512) {
        sm.sb1[i] = g_b1c[net * 144 + i];
        sm.sb2[i] = g_b2c[net * 144 + i];
    }
    {
        const float* eW = net ? fe_eW1 : fi_eW1;
        const float* eB = net ? fe_eb1 : fi_eb1;
        for (int i = tid; i < 99; i += 512) sm.sevW[i] = eW[i];
        for (int i = tid; i < 33; i += 512) sm.sevB[i] = eB[i];
    }
    for (int i = tid; i < TE * AS2 / 2; i += 512)
        ((unsigned*)sm.h1)[i] = 0u;
    __syncthreads();

    const unsigned h1s  = (unsigned)__cvta_generic_to_shared(sm.h1);
    const unsigned rbss = (unsigned)__cvta_generic_to_shared(sm.rbfs);
    const unsigned a2base = h1s  + 2 * ((2 * mh) * 16 * AS2 + l15 * AS2 + lc8);
    const unsigned a1base = rbss + 2 * ((2 * mh) * 16 * RS + l15 * RS + lc8);
    const unsigned* W1n = g_W1sw + net * NTT * 2 * 64;

    for (int u = blockIdx.x; u < 2 * NTILES; u += GRIDG) {
        const int tile = u >> 1;
        const int e0 = tile * TE;
        __syncthreads();

        for (int i = tid; i < TE * Rr; i += 512) {
            int t = i >> 5, c = i & 31;
            sm.rbfs[t * RS + c] = __float2half(rbf_g[e0 * Rr + i]);
        }
        if (tid < TE * 3) {
            int t = tid / 3, g3 = tid - 3 * t;
            int js = (g3 == 0) ? 0 : ((g3 == 1) ? 3 : 8);
            int je = (g3 == 0) ? 3 : ((g3 == 1) ? 8 : 15);
            const float* evs = ev_features + senders[e0 + t] * EVd;
            const float* evr = ev_features + receivers[e0 + t] * EVd;
            float a = 0.0f;
            for (int j = js; j < je; j++) {
                float d = evs[j] - evr[j];
                a += d * d;
            }
            sm.ev3[t * 3 + g3] = a;
        }
        __syncthreads();

        // layer 1 (rbf branch); stores predicated to cols < 132
        {
            float acc[3][2][4];
#pragma unroll
            for (int j = 0; j < 3; j++) {
                if (j < ntile) {
                    int nidx = (wn + 8 * j) * 8 + 2 * t4;
                    float b0f = sm.sb1[nidx], b1f = sm.sb1[nidx + 1];
#pragma unroll
                    for (int m = 0; m < 2; m++) {
                        acc[j][m][0] = b0f; acc[j][m][1] = b1f;
                        acc[j][m][2] = b0f; acc[j][m][3] = b1f;
                    }
                }
            }
#pragma unroll
            for (int ks = 0; ks < 2; ks++) {
                unsigned a[2][4];
#pragma unroll
                for (int m = 0; m < 2; m++)
                    ldsm4(a[m][0], a[m][1], a[m][2], a[m][3],
                          a1base + 2 * (m * 16 * RS + ks * 16));
#pragma unroll
                for (int j = 0; j < 3; j++) {
                    if (j < ntile) {
                        int tt = wn + 8 * j;
                        uint2 b = ((const uint2*)(W1n + (tt * 2 + ks) * 64))[lane];
#pragma unroll
                        for (int m = 0; m < 2; m++)
                            mma16816(acc[j][m], a[m][0], a[m][1], a[m][2], a[m][3], b.x, b.y);
                    }
                }
            }
#pragma unroll
            for (int j = 0; j < 3; j++) {
                if (j < ntile) {
                    int col = (wn + 8 * j) * 8 + 2 * t4;
                    if (col < 132) {   // cols >= 132 belong to the ev branch / stay zero
#pragma unroll
                        for (int m = 0; m < 2; m++) {
                            int r = (2 * mh + m) * 16 + gq;
                            *(__half2*)&sm.h1[r * AS2 + col] =
                                __floats2half2_rn(silu_f(acc[j][m][0]), silu_f(acc[j][m][1]));
                            *(__half2*)&sm.h1[(r + 8) * AS2 + col] =
                                __floats2half2_rn(silu_f(acc[j][m][2]), silu_f(acc[j][m][3]));
                        }
                    }
                }
            }
        }
        // ev branch: 3 -> 33, h1 cols 132..164
        for (int i = tid; i < TE * 33; i += 512) {
            int t = i / 33, cc = i - 33 * t;
            float v = sm.sevB[cc]
                    + sm.ev3[t * 3 + 0] * sm.sevW[cc]
                    + sm.ev3[t * 3 + 1] * sm.sevW[33 + cc]
                    + sm.ev3[t * 3 + 2] * sm.sevW[66 + cc];
            sm.h1[t * AS2 + 132 + cc] = __float2half(silu_f(v));
        }
        __syncthreads();

        // layer 2: [64x176] x [176x144]
        {
            float acc[3][2][4];
#pragma unroll
            for (int j = 0; j < 3; j++) {
                if (j < ntile) {
                    int nidx = (wn + 8 * j) * 8 + 2 * t4;
                    float b0f = sm.sb2[nidx], b1f = sm.sb2[nidx + 1];
#pragma unroll
                    for (int m = 0; m < 2; m++) {
                        acc[j][m][0] = b0f; acc[j][m][1] = b1f;
                        acc[j][m][2] = b0f; acc[j][m][3] = b1f;
                    }
                }
            }
#pragma unroll 3
            for (int ks = 0; ks < KS2; ks++) {
                unsigned a[2][4];
#pragma unroll
                for (int m = 0; m < 2; m++)
                    ldsm4(a[m][0], a[m][1], a[m][2], a[m][3],
                          a2base + 2 * (m * 16 * AS2 + ks * 16));
#pragma unroll
                for (int j = 0; j < 3; j++) {
                    if (j < ntile) {
                        int tt = wn + 8 * j;
                        uint2 b = ((const uint2*)(sm.sW2 + (tt * KS2 + ks) * 64))[lane];
#pragma unroll
                        for (int m = 0; m < 2; m++)
                            mma16816(acc[j][m], a[m][0], a[m][1], a[m][2], a[m][3], b.x, b.y);
                    }
                }
            }
#pragma unroll
            for (int j = 0; j < 3; j++) {
                if (j < ntile) {
                    int col = (wn + 8 * j) * 8 + 2 * t4;
#pragma unroll
                    for (int m = 0; m < 2; m++) {
                        int r = (2 * mh + m) * 16 + gq;
                        *(__half2*)&sm.fw[r * FS2 + col] =
                            __floats2half2_rn(acc[j][m][0], acc[j][m][1]);
                        *(__half2*)&sm.fw[(r + 8) * FS2 + col] =
                            __floats2half2_rn(acc[j][m][2], acc[j][m][3]);
                    }
                }
            }
        }
        __syncthreads();

        // coalesced fw writeout
        {
            __half* dstbase = g_fw + (size_t)e0 * FSG + net * 144;
            for (int i = tid; i < TE * 18; i += 512) {
                int r = i / 18, c = i - r * 18;
                *(uint4*)(dstbase + r * FSG + c * 8) =
                    *(const uint4*)&sm.fw[r * FS2 + c * 8];
            }
        }
    }
}

// ---------------- K_att: attention logits + scatter (4-way interleave) ----------------
struct ASm {
    float  al [TE * 8];
    float  cut[TE];
    int    sidx[TE];
    int    ridx[TE];
};

__global__ __launch_bounds__(256) void att_kernel(
    const float* __restrict__ cutoffs,
    const int*   __restrict__ senders,
    const int*   __restrict__ receivers,
    const float* __restrict__ sh)
{
    __shared__ ASm sm;
    const int tid = threadIdx.x;
    const int w = tid >> 5, lane = tid & 31;
    const int e0 = blockIdx.x * TE;

    if (tid < TE) {
        sm.sidx[tid] = senders[e0 + tid];
        sm.ridx[tid] = receivers[e0 + tid];
        sm.cut[tid]  = cutoffs[e0 + tid];
    }
    __syncthreads();

    // alpha: 448 tasks over 8 warps, 4-way interleaved; fw read directly
    {
        const float INVN = 0.17407765595569785f;  // 1/sqrt(33)
        const float INVE = 0.15075567228888181f;  // 1/sqrt(44)
        for (int p = 0; p < 14; p++) {
            float acc[4], nm[4];
            int tt[4], hh[4];
#pragma unroll
            for (int qq = 0; qq < 4; qq++) {
                int task = w + 8 * (4 * p + qq);
                int t = task / 7, h = task - 7 * t;
                tt[qq] = t; hh[qq] = h;
                const __half *q, *k, *f;
                int D;
                if (h < 4) {
                    q = g_q_inv + sm.ridx[t] * Ff + h * 33;
                    k = g_k_inv + sm.sidx[t] * Ff + h * 33;
                    f = g_fw + (size_t)(e0 + t) * FSG + h * 33;
                    D = 33; nm[qq] = INVN;
                } else {
                    int hx = h - 4;
                    q = g_q_ev + sm.ridx[t] * Ff + hx * 44;
                    k = g_k_ev + sm.sidx[t] * Ff + hx * 44;
                    f = g_fw + (size_t)(e0 + t) * FSG + 144 + hx * 44;
                    D = 44; nm[qq] = INVE;
                }
                float a = __half2float(q[lane]) * __half2float(k[lane])
                        * __half2float(f[lane]);
                int d1 = lane + 32;
                if (d1 < D)
                    a += __half2float(q[d1]) * __half2float(k[d1])
                       * __half2float(f[d1]);
                acc[qq] = a;
            }
#pragma unroll
            for (int s = 16; s > 0; s >>= 1) {
#pragma unroll
                for (int qq = 0; qq < 4; qq++)
                    acc[qq] += __shfl_xor_sync(0xFFFFFFFFu, acc[qq], s);
            }
            if (lane == 0) {
#pragma unroll
                for (int qq = 0; qq < 4; qq++)
                    sm.al[tt[qq] * 8 + hh[qq]] = acc[qq] * nm[qq] * sm.cut[tt[qq]];
            }
        }
    }
    __syncthreads();

    // scatter: inv messages via 128-bit reductions (33 float4 per edge)
    for (int i = tid; i < TE * 33; i += 256) {
        int t = i / 33, c4 = i - 33 * t;
        int f0 = 4 * c4;
        const float4 v = *(const float4*)(g_v_inv + sm.sidx[t] * Ff + f0);
        float r0 = sm.al[t * 8 + (f0 + 0) / 33] * v.x;
        float r1 = sm.al[t * 8 + (f0 + 1) / 33] * v.y;
        float r2 = sm.al[t * 8 + (f0 + 2) / 33] * v.z;
        float r3 = sm.al[t * 8 + (f0 + 3) / 33] * v.w;
        red_add_v4(g_dinv + sm.ridx[t] * Ff + f0, r0, r1, r2, r3);
    }
    // scatter: ev messages (4 float4 per edge, padded row of 16)
    for (int i = tid; i < TE * 4; i += 256) {
        int t = i >> 2, q4 = i & 3;
        int j0 = 4 * q4;
        float r[4];
#pragma unroll
        for (int u = 0; u < 4; u++) {
            int j = j0 + u;
            if (j < EVd) {
                int gg = (j < 3) ? 0 : ((j < 8) ? 1 : 2);
                r[u] = sm.al[t * 8 + 4 + gg] * sh[(e0 + t) * EVd + j];
            } else r[u] = 0.0f;
        }
        red_add_v4(g_dev + sm.ridx[t] * 16 + j0, r[0], r[1], r[2], r[3]);
    }
}

// ---------------- final node update (transposed smem, float4 broadcast) ----------------
#define TNF 8
__global__ __launch_bounds__(160) void final_kernel(
    const float* __restrict__ inv_features,
    const float* __restrict__ ev_features,
    const float* __restrict__ W_int,
    const float* __restrict__ b_int,
    float* __restrict__ out)
{
    __shared__ __align__(16) float ct[136 * TNF];
    __shared__ float ev1_s[TNF][EVd];
    __shared__ float tb_s[TNF][3];
    const int n0 = blockIdx.x * TNF;

    for (int i = threadIdx.x; i < TNF * Ff; i += 160) {
        const int t = i & 7, f = i >> 3;
        ct[f * TNF + t] = inv_features[(n0 + t) * Ff + f] + g_dinv[(n0 + t) * Ff + f];
    }
    for (int i = threadIdx.x; i < TNF * EVd; i += 160) {
        const int t = i / EVd, j = i - EVd * t;
        ev1_s[t][j] = ev_features[(n0 + t) * EVd + j] + g_dev[(n0 + t) * 16 + j];
    }
    __syncthreads();
    for (int i = threadIdx.x; i < TNF * 3; i += 160) {
        const int t = i / 3, g = i - 3 * t;
        const int js = (g == 0) ? 0 : ((g == 1) ? 3 : 8);
        const int je = (g == 0) ? 3 : ((g == 1) ? 8 : 15);
        float a = 0.0f;
        for (int j = js; j < je; j++) {
            const float v = ev1_s[t][j];
            a += v * v;
        }
        ct[(132 + g) * TNF + t] = a;
    }
    __syncthreads();

    if (threadIdx.x < 135) {
        const int f = threadIdx.x;
        const float b = b_int[f];
        float4 a0 = make_float4(b, b, b, b);
        float4 a1 = a0;
        for (int k = 0; k < 135; k++) {
            const float w = W_int[k * 135 + f];
            const float4* xr = (const float4*)&ct[k * TNF];
            const float4 x0 = xr[0], x1 = xr[1];
            a0.x += x0.x * w; a0.y += x0.y * w; a0.z += x0.z * w; a0.w += x0.w * w;
            a1.x += x1.x * w; a1.y += x1.y * w; a1.z += x1.z * w; a1.w += x1.w * w;
        }
        float acc[TNF] = {a0.x, a0.y, a0.z, a0.w, a1.x, a1.y, a1.z, a1.w};
        if (f < 132) {
#pragma unroll
            for (int t = 0; t < TNF; t++)
                out[(n0 + t) * Ff + f] = ct[f * TNF + t] + acc[t];
        } else {
#pragma unroll
            for (int t = 0; t < TNF; t++) tb_s[t][f - 132] = acc[t];
        }
    }
    __syncthreads();

    float* out_ev = out + Nn * Ff;
    for (int i = threadIdx.x; i < TNF * EVd; i += 160) {
        const int t = i / EVd, j = i - EVd * t;
        const int g = (j < 3) ? 0 : ((j < 8) ? 1 : 2);
        out_ev[(n0 + t) * EVd + j] = ev1_s[t][j] * (1.0f + tb_s[t][g]);
    }
}

// ---------------- launch ----------------
extern "C" void kernel_launch(void* const* d_in, const int* in_sizes, int n_in,
                              void* d_out, int out_size)
{
    const float* inv_features = (const float*)d_in[0];
    const float* ev_features  = (const float*)d_in[1];
    const float* rbf          = (const float*)d_in[2];
    const float* sh_vectors   = (const float*)d_in[3];
    const float* cutoffs      = (const float*)d_in[4];
    const int*   senders      = (const int*)d_in[5];
    const int*   receivers    = (const int*)d_in[6];
    const float* Wq_inv = (const float*)d_in[7];
    const float* Wk_inv = (const float*)d_in[8];
    const float* Wv_inv = (const float*)d_in[9];
    const float* Wq_ev  = (const float*)d_in[10];
    const float* Wk_ev  = (const float*)d_in[11];
    const float* fi_rW1 = (const float*)d_in[12];
    const float* fi_rb1 = (const float*)d_in[13];
    const float* fi_rW2 = (const float*)d_in[14];
    const float* fi_rb2 = (const float*)d_in[15];
    const float* fi_eW1 = (const float*)d_in[16];
    const float* fi_eb1 = (const float*)d_in[17];
    const float* fi_eW2 = (const float*)d_in[18];
    const float* fi_eb2 = (const float*)d_in[19];
    const float* fe_rW1 = (const float*)d_in[20];
    const float* fe_rb1 = (const float*)d_in[21];
    const float* fe_rW2 = (const float*)d_in[22];
    const float* fe_rb2 = (const float*)d_in[23];
    const float* fe_eW1 = (const float*)d_in[24];
    const float* fe_eb1 = (const float*)d_in[25];
    const float* fe_eW2 = (const float*)d_in[26];
    const float* fe_eb2 = (const float*)d_in[27];
    const float* W_int  = (const float*)d_in[28];
    const float* b_int  = (const float*)d_in[29];
    float* out = (float*)d_out;

    cudaFuncSetAttribute(gemm_kernel,
                         cudaFuncAttributeMaxDynamicSharedMemorySize,
                         (int)sizeof(GSm2));

    zero_kernel<<<512, 256>>>();
    prep_kernel<<<(2 * NTT * KS2 * 64 + 255) / 256, 256>>>(
        fi_rW1, fi_rb1, fi_rW2, fi_rb2, fi_eW2, fi_eb2,
        fe_rW1, fe_rb1, fe_rW2, fe_rb2, fe_eW2, fe_eb2);
    node_proj_kernel<<<Nn / TNA, 256>>>(inv_features, Wq_inv, Wk_inv, Wv_inv,
                                        Wq_ev, Wk_ev);
    gemm_kernel<<<GRIDG, 512, sizeof(GSm2)>>>(
        ev_features, rbf, senders, receivers,
        fi_eW1, fi_eb1, fe_eW1, fe_eb1);
    att_kernel<<<NTILES, 256>>>(cutoffs, senders, receivers, sh_vectors);
    final_kernel<<<Nn / TNF, 160>>>(inv_features, ev_features, W_int, b_int, out);
}

// round 15
// speedup vs baseline: 4.8157x; 1.0333x over previous
#include <cuda_runtime.h>
#include <cuda_fp16.h>

// Problem constants
#define Nn   50000
#define Ee   400000
#define Rr   32
#define Ff   132
#define EVd  15

#define TE     64    // edges per tile
#define NTILES 6250  // Ee / TE
#define GRIDG  296   // persistent gemm blocks (2 per SM)

#define NTT  18      // n-tiles per net (N padded 144)
#define KS2  11      // layer-2 k-steps (K padded 176: 132 rbf + 33 ev + pad)
#define AS2  184     // h1 row stride (halves), 368B rows
#define FSG  288     // fw gmem row stride (halves)
#define RS   40      // rbf smem row stride (halves)

// ---------------- device scratch ----------------
__device__ __half g_q_inv[Nn * Ff];
__device__ __half g_k_inv[Nn * Ff];
__device__ float  g_v_inv[Nn * Ff];
__device__ __half g_q_ev [Nn * Ff];
__device__ __half g_k_ev [Nn * Ff];
__device__ float  g_dinv [Nn * Ff];
__device__ float  g_dev  [Nn * 16];
__device__ __align__(16) __half g_fw[Ee * FSG];

// fragment-packed weights, paired layout: slot = 2*lane + h
__device__ __align__(16) unsigned int g_W2sw[2 * NTT * KS2 * 64];
__device__ __align__(16) unsigned int g_W1sw[2 * NTT * 2 * 64];
__device__ float g_b1c[2 * 144];
__device__ float g_b2c[2 * 144];

__device__ __forceinline__ float silu_f(float x) {
    return x / (1.0f + __expf(-x));
}

__device__ __forceinline__ void mma16816(float c[4],
    unsigned a0, unsigned a1, unsigned a2, unsigned a3,
    unsigned b0, unsigned b1)
{
    asm volatile(
        "mma.sync.aligned.m16n8k16.row.col.f32.f16.f16.f32 "
        "{%0,%1,%2,%3},{%4,%5,%6,%7},{%8,%9},{%0,%1,%2,%3};\n"
        : "+f"(c[0]), "+f"(c[1]), "+f"(c[2]), "+f"(c[3])
        : "r"(a0), "r"(a1), "r"(a2), "r"(a3), "r"(b0), "r"(b1));
}

__device__ __forceinline__ void ldsm4(unsigned& r0, unsigned& r1,
                                      unsigned& r2, unsigned& r3,
                                      unsigned addr)
{
    asm volatile(
        "ldmatrix.sync.aligned.m8n8.x4.shared.b16 {%0,%1,%2,%3}, [%4];\n"
        : "=r"(r0), "=r"(r1), "=r"(r2), "=r"(r3) : "r"(addr));
}

__device__ __forceinline__ void red_add_v4(float* p, float a, float b,
                                           float c, float d)
{
    asm volatile("red.global.add.v4.f32 [%0], {%1,%2,%3,%4};"
                 :: "l"(p), "f"(a), "f"(b), "f"(c), "f"(d) : "memory");
}

// ---------------- zero accumulators ----------------
__global__ void zero_kernel() {
    int i = blockIdx.x * blockDim.x + threadIdx.x;
    int stride = gridDim.x * blockDim.x;
    for (int j = i; j < Nn * Ff; j += stride) g_dinv[j] = 0.0f;
    for (int j = i; j < Nn * 16; j += stride) g_dev[j] = 0.0f;
}

// ---------------- weight prep (K=176 packing: rbf 0..131, ev 132..164) ----------------
__device__ __forceinline__ float W2com(int net, int k, int n,
    const float* fi_rW2, const float* fi_eW2,
    const float* fe_rW2, const float* fe_eW2)
{
    if (n >= 132) return 0.0f;
    if (k < 132)  return (net ? fe_rW2 : fi_rW2)[k * 132 + n];
    if (k < 165)  return (net ? fe_eW2 : fi_eW2)[(k - 132) * 132 + n];
    return 0.0f;
}

__global__ void prep_kernel(
    const float* __restrict__ fi_rW1, const float* __restrict__ fi_rb1,
    const float* __restrict__ fi_rW2, const float* __restrict__ fi_rb2,
    const float* __restrict__ fi_eW2, const float* __restrict__ fi_eb2,
    const float* __restrict__ fe_rW1, const float* __restrict__ fe_rb1,
    const float* __restrict__ fe_rW2, const float* __restrict__ fe_rb2,
    const float* __restrict__ fe_eW2, const float* __restrict__ fe_eb2)
{
    int i = blockIdx.x * blockDim.x + threadIdx.x;
    if (i < 2 * NTT * KS2 * 64) {
        int slot = i & 63;
        int blk = i >> 6;
        int ks = blk % KS2;
        int tmp = blk / KS2;
        int tt = tmp % NTT;
        int net = tmp / NTT;
        int lane = slot >> 1, h = slot & 1;
        int gq = lane >> 2, t4 = lane & 3;
        int k = ks * 16 + h * 8 + 2 * t4;
        int n = tt * 8 + gq;
        __half2 v = __floats2half2_rn(
            W2com(net, k,     n, fi_rW2, fi_eW2, fe_rW2, fe_eW2),
            W2com(net, k + 1, n, fi_rW2, fi_eW2, fe_rW2, fe_eW2));
        ((__half2*)g_W2sw)[i] = v;
    }
    if (i < 2 * NTT * 2 * 64) {
        int slot = i & 63;
        int blk = i >> 6;
        int ks = blk & 1;
        int tmp = blk >> 1;
        int tt = tmp % NTT;
        int net = tmp / NTT;
        int lane = slot >> 1, h = slot & 1;
        int gq = lane >> 2, t4 = lane & 3;
        int k = ks * 16 + h * 8 + 2 * t4;
        int n = tt * 8 + gq;
        const float* W = net ? fe_rW1 : fi_rW1;
        float v0 = (n < 132) ? W[k * 132 + n] : 0.0f;
        float v1 = (n < 132) ? W[(k + 1) * 132 + n] : 0.0f;
        ((__half2*)g_W1sw)[i] = __floats2half2_rn(v0, v1);
    }
    if (i < 2 * 144) {
        int net = i / 144, n = i % 144;
        float b1 = 0.0f, b2 = 0.0f;
        if (n < 132) {
            b1 = (net ? fe_rb1 : fi_rb1)[n];
            b2 = (net ? fe_rb2 : fi_rb2)[n] + (net ? fe_eb2 : fi_eb2)[n];
        }
        g_b1c[i] = b1;
        g_b2c[i] = b2;
    }
}

// ---------------- per-node projections (transposed smem, float4 broadcast) ----------------
#define TNA 16
#define XSW 20
__global__ __launch_bounds__(256) void node_proj_kernel(
    const float* __restrict__ x,
    const float* __restrict__ Wq_inv, const float* __restrict__ Wk_inv,
    const float* __restrict__ Wv_inv, const float* __restrict__ Wq_ev,
    const float* __restrict__ Wk_ev)
{
    __shared__ __align__(16) float xs[Ff * XSW];
    const int n0 = blockIdx.x * TNA;
    for (int i = threadIdx.x; i < TNA * Ff; i += 256) {
        int t = i / Ff, f = i - t * Ff;
        xs[f * XSW + t] = x[n0 * Ff + i];
    }
    __syncthreads();

    for (int idx = threadIdx.x; idx < 5 * Ff; idx += 256) {
        const int m = idx / Ff, c = idx - m * Ff;
        const float* W;
        int D, h, e;
        if (m < 3) {
            D = 33; h = c / 33; e = c - h * 33;
            W = (m == 0 ? Wq_inv : (m == 1 ? Wk_inv : Wv_inv)) + h * 33 * 33;
        } else {
            D = 44; h = c / 44; e = c - h * 44;
            W = (m == 3 ? Wq_ev : Wk_ev) + h * 44 * 44;
        }
        float4 a0 = make_float4(0.f, 0.f, 0.f, 0.f);
        float4 a1 = a0, a2 = a0, a3 = a0;
        const int xb = h * D;
        for (int d = 0; d < D; d++) {
            const float w = W[d * D + e];
            const float4* xr = (const float4*)&xs[(xb + d) * XSW];
            const float4 x0 = xr[0], x1 = xr[1], x2 = xr[2], x3 = xr[3];
            a0.x += x0.x * w; a0.y += x0.y * w; a0.z += x0.z * w; a0.w += x0.w * w;
            a1.x += x1.x * w; a1.y += x1.y * w; a1.z += x1.z * w; a1.w += x1.w * w;
            a2.x += x2.x * w; a2.y += x2.y * w; a2.z += x2.z * w; a2.w += x2.w * w;
            a3.x += x3.x * w; a3.y += x3.y * w; a3.z += x3.z * w; a3.w += x3.w * w;
        }
        float acc[TNA] = {a0.x, a0.y, a0.z, a0.w, a1.x, a1.y, a1.z, a1.w,
                          a2.x, a2.y, a2.z, a2.w, a3.x, a3.y, a3.z, a3.w};
        if (m == 2) {
#pragma unroll
            for (int t = 0; t < TNA; t++)
                g_v_inv[(n0 + t) * Ff + c] = acc[t];
        } else {
            __half* out = (m == 0) ? g_q_inv : (m == 1) ? g_k_inv
                        : (m == 3) ? g_q_ev : g_k_ev;
#pragma unroll
            for (int t = 0; t < TNA; t++)
                out[(n0 + t) * Ff + c] = __float2half(silu_f(acc[t]));
        }
    }
}

// ---------------- K_gemm: per-net persistent GEMM, direct fw STG ----------------
struct GSm2 {
    unsigned sW2[NTT * KS2 * 64];   // 50688 B
    float sb1[144];
    float sb2[144];
    float sevW[99];
    float sevB[33];
    __half h1[TE * AS2];            // 23552 B
    __half rbfs[TE * RS];           //  5120 B
    float ev3[TE * 3];              //   768 B
};                                  // ~82 KB -> 2 blocks/SM

__global__ __launch_bounds__(512, 2) void gemm_kernel(
    const float* __restrict__ ev_features,
    const float* __restrict__ rbf_g,
    const int*   __restrict__ senders,
    const int*   __restrict__ receivers,
    const float* __restrict__ fi_eW1, const float* __restrict__ fi_eb1,
    const float* __restrict__ fe_eW1, const float* __restrict__ fe_eb1)
{
    extern __shared__ char smraw[];
    GSm2& sm = *reinterpret_cast<GSm2*>(smraw);
    const int tid = threadIdx.x;
    const int w = tid >> 5, lane = tid & 31;
    const int gq = lane >> 2, t4 = lane & 3;
    const int net = blockIdx.x & 1;
    const int mh = w >> 3;                    // m-half
    const int wn = w & 7;
    const int ntile = (wn < 2) ? 3 : 2;
    const int l15 = lane & 15;
    const int lc8 = (lane & 16) ? 8 : 0;

    // one-time staging (this net only)
    {
        const unsigned* src = g_W2sw + net * NTT * KS2 * 64;
        for (int i = tid; i < NTT * KS2 * 64; i += 512) sm.sW2[i] = src[i];
    }
    for (int i = tid; i < 144; i += 512) {
        sm.sb1[i] = g_b1c[net * 144 + i];
        sm.sb2[i] = g_b2c[net * 144 + i];
    }
    {
        const float* eW = net ? fe_eW1 : fi_eW1;
        const float* eB = net ? fe_eb1 : fi_eb1;
        for (int i = tid; i < 99; i += 512) sm.sevW[i] = eW[i];
        for (int i = tid; i < 33; i += 512) sm.sevB[i] = eB[i];
    }
    for (int i = tid; i < TE * AS2 / 2; i += 512)
        ((unsigned*)sm.h1)[i] = 0u;
    __syncthreads();

    const unsigned h1s  = (unsigned)__cvta_generic_to_shared(sm.h1);
    const unsigned rbss = (unsigned)__cvta_generic_to_shared(sm.rbfs);
    const unsigned a2base = h1s  + 2 * ((2 * mh) * 16 * AS2 + l15 * AS2 + lc8);
    const unsigned a1base = rbss + 2 * ((2 * mh) * 16 * RS + l15 * RS + lc8);
    const unsigned* W1n = g_W1sw + net * NTT * 2 * 64;

    for (int u = blockIdx.x; u < 2 * NTILES; u += GRIDG) {
        const int tile = u >> 1;
        const int e0 = tile * TE;
        __syncthreads();

        for (int i = tid; i < TE * Rr; i += 512) {
            int t = i >> 5, c = i & 31;
            sm.rbfs[t * RS + c] = __float2half(rbf_g[e0 * Rr + i]);
        }
        if (tid < TE * 3) {
            int t = tid / 3, g3 = tid - 3 * t;
            int js = (g3 == 0) ? 0 : ((g3 == 1) ? 3 : 8);
            int je = (g3 == 0) ? 3 : ((g3 == 1) ? 8 : 15);
            const float* evs = ev_features + senders[e0 + t] * EVd;
            const float* evr = ev_features + receivers[e0 + t] * EVd;
            float a = 0.0f;
            for (int j = js; j < je; j++) {
                float d = evs[j] - evr[j];
                a += d * d;
            }
            sm.ev3[t * 3 + g3] = a;
        }
        __syncthreads();

        // layer 1 (rbf branch); stores predicated to cols < 132
        {
            float acc[3][2][4];
#pragma unroll
            for (int j = 0; j < 3; j++) {
                if (j < ntile) {
                    int nidx = (wn + 8 * j) * 8 + 2 * t4;
                    float b0f = sm.sb1[nidx], b1f = sm.sb1[nidx + 1];
#pragma unroll
                    for (int m = 0; m < 2; m++) {
                        acc[j][m][0] = b0f; acc[j][m][1] = b1f;
                        acc[j][m][2] = b0f; acc[j][m][3] = b1f;
                    }
                }
            }
#pragma unroll
            for (int ks = 0; ks < 2; ks++) {
                unsigned a[2][4];
#pragma unroll
                for (int m = 0; m < 2; m++)
                    ldsm4(a[m][0], a[m][1], a[m][2], a[m][3],
                          a1base + 2 * (m * 16 * RS + ks * 16));
#pragma unroll
                for (int j = 0; j < 3; j++) {
                    if (j < ntile) {
                        int tt = wn + 8 * j;
                        uint2 b = ((const uint2*)(W1n + (tt * 2 + ks) * 64))[lane];
#pragma unroll
                        for (int m = 0; m < 2; m++)
                            mma16816(acc[j][m], a[m][0], a[m][1], a[m][2], a[m][3], b.x, b.y);
                    }
                }
            }
#pragma unroll
            for (int j = 0; j < 3; j++) {
                if (j < ntile) {
                    int col = (wn + 8 * j) * 8 + 2 * t4;
                    if (col < 132) {
#pragma unroll
                        for (int m = 0; m < 2; m++) {
                            int r = (2 * mh + m) * 16 + gq;
                            *(__half2*)&sm.h1[r * AS2 + col] =
                                __floats2half2_rn(silu_f(acc[j][m][0]), silu_f(acc[j][m][1]));
                            *(__half2*)&sm.h1[(r + 8) * AS2 + col] =
                                __floats2half2_rn(silu_f(acc[j][m][2]), silu_f(acc[j][m][3]));
                        }
                    }
                }
            }
        }
        // ev branch: 3 -> 33, h1 cols 132..164
        for (int i = tid; i < TE * 33; i += 512) {
            int t = i / 33, cc = i - 33 * t;
            float v = sm.sevB[cc]
                    + sm.ev3[t * 3 + 0] * sm.sevW[cc]
                    + sm.ev3[t * 3 + 1] * sm.sevW[33 + cc]
                    + sm.ev3[t * 3 + 2] * sm.sevW[66 + cc];
            sm.h1[t * AS2 + 132 + cc] = __float2half(silu_f(v));
        }
        __syncthreads();

        // layer 2: [64x176] x [176x144], epilogue stores DIRECT to g_fw
        {
            float acc[3][2][4];
#pragma unroll
            for (int j = 0; j < 3; j++) {
                if (j < ntile) {
                    int nidx = (wn + 8 * j) * 8 + 2 * t4;
                    float b0f = sm.sb2[nidx], b1f = sm.sb2[nidx + 1];
#pragma unroll
                    for (int m = 0; m < 2; m++) {
                        acc[j][m][0] = b0f; acc[j][m][1] = b1f;
                        acc[j][m][2] = b0f; acc[j][m][3] = b1f;
                    }
                }
            }
#pragma unroll 3
            for (int ks = 0; ks < KS2; ks++) {
                unsigned a[2][4];
#pragma unroll
                for (int m = 0; m < 2; m++)
                    ldsm4(a[m][0], a[m][1], a[m][2], a[m][3],
                          a2base + 2 * (m * 16 * AS2 + ks * 16));
#pragma unroll
                for (int j = 0; j < 3; j++) {
                    if (j < ntile) {
                        int tt = wn + 8 * j;
                        uint2 b = ((const uint2*)(sm.sW2 + (tt * KS2 + ks) * 64))[lane];
#pragma unroll
                        for (int m = 0; m < 2; m++)
                            mma16816(acc[j][m], a[m][0], a[m][1], a[m][2], a[m][3], b.x, b.y);
                    }
                }
            }
            __half* fwbase = g_fw + (size_t)e0 * FSG + net * 144;
#pragma unroll
            for (int j = 0; j < 3; j++) {
                if (j < ntile) {
                    int col = (wn + 8 * j) * 8 + 2 * t4;
#pragma unroll
                    for (int m = 0; m < 2; m++) {
                        int r = (2 * mh + m) * 16 + gq;
                        *(__half2*)(fwbase + r * FSG + col) =
                            __floats2half2_rn(acc[j][m][0], acc[j][m][1]);
                        *(__half2*)(fwbase + (r + 8) * FSG + col) =
                            __floats2half2_rn(acc[j][m][2], acc[j][m][3]);
                    }
                }
            }
        }
    }
}

// ---------------- K_att: attention logits + scatter (2-way interleave) ----------------
struct ASm {
    float  al [TE * 8];
    float  cut[TE];
    int    sidx[TE];
    int    ridx[TE];
};

__global__ __launch_bounds__(256) void att_kernel(
    const float* __restrict__ cutoffs,
    const int*   __restrict__ senders,
    const int*   __restrict__ receivers,
    const float* __restrict__ sh)
{
    __shared__ ASm sm;
    const int tid = threadIdx.x;
    const int w = tid >> 5, lane = tid & 31;
    const int e0 = blockIdx.x * TE;

    if (tid < TE) {
        sm.sidx[tid] = senders[e0 + tid];
        sm.ridx[tid] = receivers[e0 + tid];
        sm.cut[tid]  = cutoffs[e0 + tid];
    }
    __syncthreads();

    // alpha: 448 tasks over 8 warps, 2-way interleaved; fw read directly
    {
        const float INVN = 0.17407765595569785f;  // 1/sqrt(33)
        const float INVE = 0.15075567228888181f;  // 1/sqrt(44)
        for (int p = 0; p < 28; p++) {
            int taskA = w + 8 * (2 * p);
            int taskB = w + 8 * (2 * p + 1);
            int tA = taskA / 7, hA = taskA - 7 * tA;
            int tB = taskB / 7, hB = taskB - 7 * tB;

            const __half *qA, *kA, *fA; int DA; float nmA;
            if (hA < 4) { qA = g_q_inv + sm.ridx[tA] * Ff + hA * 33;
                          kA = g_k_inv + sm.sidx[tA] * Ff + hA * 33;
                          fA = g_fw + (size_t)(e0 + tA) * FSG + hA * 33;
                          DA = 33; nmA = INVN; }
            else        { int hh = hA - 4;
                          qA = g_q_ev + sm.ridx[tA] * Ff + hh * 44;
                          kA = g_k_ev + sm.sidx[tA] * Ff + hh * 44;
                          fA = g_fw + (size_t)(e0 + tA) * FSG + 144 + hh * 44;
                          DA = 44; nmA = INVE; }
            const __half *qB, *kB, *fB; int DB; float nmB;
            if (hB < 4) { qB = g_q_inv + sm.ridx[tB] * Ff + hB * 33;
                          kB = g_k_inv + sm.sidx[tB] * Ff + hB * 33;
                          fB = g_fw + (size_t)(e0 + tB) * FSG + hB * 33;
                          DB = 33; nmB = INVN; }
            else        { int hh = hB - 4;
                          qB = g_q_ev + sm.ridx[tB] * Ff + hh * 44;
                          kB = g_k_ev + sm.sidx[tB] * Ff + hh * 44;
                          fB = g_fw + (size_t)(e0 + tB) * FSG + 144 + hh * 44;
                          DB = 44; nmB = INVE; }

            float aA = __half2float(qA[lane]) * __half2float(kA[lane])
                     * __half2float(fA[lane]);
            float aB = __half2float(qB[lane]) * __half2float(kB[lane])
                     * __half2float(fB[lane]);
            int d1 = lane + 32;
            if (d1 < DA) aA += __half2float(qA[d1]) * __half2float(kA[d1])
                             * __half2float(fA[d1]);
            if (d1 < DB) aB += __half2float(qB[d1]) * __half2float(kB[d1])
                             * __half2float(fB[d1]);
#pragma unroll
            for (int s = 16; s > 0; s >>= 1) {
                aA += __shfl_xor_sync(0xFFFFFFFFu, aA, s);
                aB += __shfl_xor_sync(0xFFFFFFFFu, aB, s);
            }
            if (lane == 0) {
                sm.al[tA * 8 + hA] = aA * nmA * sm.cut[tA];
                sm.al[tB * 8 + hB] = aB * nmB * sm.cut[tB];
            }
        }
    }
    __syncthreads();

    // scatter: inv messages via 128-bit reductions (33 float4 per edge)
    for (int i = tid; i < TE * 33; i += 256) {
        int t = i / 33, c4 = i - 33 * t;
        int f0 = 4 * c4;
        const float4 v = *(const float4*)(g_v_inv + sm.sidx[t] * Ff + f0);
        float r0 = sm.al[t * 8 + (f0 + 0) / 33] * v.x;
        float r1 = sm.al[t * 8 + (f0 + 1) / 33] * v.y;
        float r2 = sm.al[t * 8 + (f0 + 2) / 33] * v.z;
        float r3 = sm.al[t * 8 + (f0 + 3) / 33] * v.w;
        red_add_v4(g_dinv + sm.ridx[t] * Ff + f0, r0, r1, r2, r3);
    }
    // scatter: ev messages (4 float4 per edge, padded row of 16)
    for (int i = tid; i < TE * 4; i += 256) {
        int t = i >> 2, q4 = i & 3;
        int j0 = 4 * q4;
        float r[4];
#pragma unroll
        for (int u = 0; u < 4; u++) {
            int j = j0 + u;
            if (j < EVd) {
                int gg = (j < 3) ? 0 : ((j < 8) ? 1 : 2);
                r[u] = sm.al[t * 8 + 4 + gg] * sh[(e0 + t) * EVd + j];
            } else r[u] = 0.0f;
        }
        red_add_v4(g_dev + sm.ridx[t] * 16 + j0, r[0], r[1], r[2], r[3]);
    }
}

// ---------------- final node update (transposed smem, float4 broadcast) ----------------
#define TNF 8
__global__ __launch_bounds__(160) void final_kernel(
    const float* __restrict__ inv_features,
    const float* __restrict__ ev_features,
    const float* __restrict__ W_int,
    const float* __restrict__ b_int,
    float* __restrict__ out)
{
    __shared__ __align__(16) float ct[136 * TNF];
    __shared__ float ev1_s[TNF][EVd];
    __shared__ float tb_s[TNF][3];
    const int n0 = blockIdx.x * TNF;

    for (int i = threadIdx.x; i < TNF * Ff; i += 160) {
        const int t = i & 7, f = i >> 3;
        ct[f * TNF + t] = inv_features[(n0 + t) * Ff + f] + g_dinv[(n0 + t) * Ff + f];
    }
    for (int i = threadIdx.x; i < TNF * EVd; i += 160) {
        const int t = i / EVd, j = i - EVd * t;
        ev1_s[t][j] = ev_features[(n0 + t) * EVd + j] + g_dev[(n0 + t) * 16 + j];
    }
    __syncthreads();
    for (int i = threadIdx.x; i < TNF * 3; i += 160) {
        const int t = i / 3, g = i - 3 * t;
        const int js = (g == 0) ? 0 : ((g == 1) ? 3 : 8);
        const int je = (g == 0) ? 3 : ((g == 1) ? 8 : 15);
        float a = 0.0f;
        for (int j = js; j < je; j++) {
            const float v = ev1_s[t][j];
            a += v * v;
        }
        ct[(132 + g) * TNF + t] = a;
    }
    __syncthreads();

    if (threadIdx.x < 135) {
        const int f = threadIdx.x;
        const float b = b_int[f];
        float4 a0 = make_float4(b, b, b, b);
        float4 a1 = a0;
        for (int k = 0; k < 135; k++) {
            const float w = W_int[k * 135 + f];
            const float4* xr = (const float4*)&ct[k * TNF];
            const float4 x0 = xr[0], x1 = xr[1];
            a0.x += x0.x * w; a0.y += x0.y * w; a0.z += x0.z * w; a0.w += x0.w * w;
            a1.x += x1.x * w; a1.y += x1.y * w; a1.z += x1.z * w; a1.w += x1.w * w;
        }
        float acc[TNF] = {a0.x, a0.y, a0.z, a0.w, a1.x, a1.y, a1.z, a1.w};
        if (f < 132) {
#pragma unroll
            for (int t = 0; t < TNF; t++)
                out[(n0 + t) * Ff + f] = ct[f * TNF + t] + acc[t];
        } else {
#pragma unroll
            for (int t = 0; t < TNF; t++) tb_s[t][f - 132] = acc[t];
        }
    }
    __syncthreads();

    float* out_ev = out + Nn * Ff;
    for (int i = threadIdx.x; i < TNF * EVd; i += 160) {
        const int t = i / EVd, j = i - EVd * t;
        const int g = (j < 3) ? 0 : ((j < 8) ? 1 : 2);
        out_ev[(n0 + t) * EVd + j] = ev1_s[t][j] * (1.0f + tb_s[t][g]);
    }
}

// ---------------- launch ----------------
extern "C" void kernel_launch(void* const* d_in, const int* in_sizes, int n_in,
                              void* d_out, int out_size)
{
    const float* inv_features = (const float*)d_in[0];
    const float* ev_features  = (const float*)d_in[1];
    const float* rbf          = (const float*)d_in[2];
    const float* sh_vectors   = (const float*)d_in[3];
    const float* cutoffs      = (const float*)d_in[4];
    const int*   senders      = (const int*)d_in[5];
    const int*   receivers    = (const int*)d_in[6];
    const float* Wq_inv = (const float*)d_in[7];
    const float* Wk_inv = (const float*)d_in[8];
    const float* Wv_inv = (const float*)d_in[9];
    const float* Wq_ev  = (const float*)d_in[10];
    const float* Wk_ev  = (const float*)d_in[11];
    const float* fi_rW1 = (const float*)d_in[12];
    const float* fi_rb1 = (const float*)d_in[13];
    const float* fi_rW2 = (const float*)d_in[14];
    const float* fi_rb2 = (const float*)d_in[15];
    const float* fi_eW1 = (const float*)d_in[16];
    const float* fi_eb1 = (const float*)d_in[17];
    const float* fi_eW2 = (const float*)d_in[18];
    const float* fi_eb2 = (const float*)d_in[19];
    const float* fe_rW1 = (const float*)d_in[20];
    const float* fe_rb1 = (const float*)d_in[21];
    const float* fe_rW2 = (const float*)d_in[22];
    const float* fe_rb2 = (const float*)d_in[23];
    const float* fe_eW1 = (const float*)d_in[24];
    const float* fe_eb1 = (const float*)d_in[25];
    const float* fe_eW2 = (const float*)d_in[26];
    const float* fe_eb2 = (const float*)d_in[27];
    const float* W_int  = (const float*)d_in[28];
    const float* b_int  = (const float*)d_in[29];
    float* out = (float*)d_out;

    cudaFuncSetAttribute(gemm_kernel,
                         cudaFuncAttributeMaxDynamicSharedMemorySize,
                         (int)sizeof(GSm2));

    zero_kernel<<<512, 256>>>();
    prep_kernel<<<(2 * NTT * KS2 * 64 + 255) / 256, 256>>>(
        fi_rW1, fi_rb1, fi_rW2, fi_rb2, fi_eW2, fi_eb2,
        fe_rW1, fe_rb1, fe_rW2, fe_rb2, fe_eW2, fe_eb2);
    node_proj_kernel<<<Nn / TNA, 256>>>(inv_features, Wq_inv, Wk_inv, Wv_inv,
                                        Wq_ev, Wk_ev);
    gemm_kernel<<<GRIDG, 512, sizeof(GSm2)>>>(
        ev_features, rbf, senders, receivers,
        fi_eW1, fi_eb1, fe_eW1, fe_eb1);
    att_kernel<<<NTILES, 256>>>(cutoffs, senders, receivers, sh_vectors);
    final_kernel<<<Nn / TNF, 160>>>(inv_features, ev_features, W_int, b_int, out);
}

// round 16
// speedup vs baseline: 4.8684x; 1.0109x over previous
#include <cuda_runtime.h>
#include <cuda_fp16.h>

// Problem constants
#define Nn   50000
#define Ee   400000
#define Rr   32
#define Ff   132
#define EVd  15

#define TE     64    // edges per tile
#define NTILES 6250  // Ee / TE
#define GRIDG  296   // persistent gemm blocks (2 per SM)

#define NTT  18      // n-tiles per net (N padded 144)
#define KS2  11      // layer-2 k-steps (K padded 176: 132 rbf + 33 ev + pad)
#define AS2  184     // h1 row stride (halves)
#define FS2  152     // fw smem row stride (halves)
#define FSG  288     // fw gmem row stride (halves)
#define RS   40      // rbf smem row stride (halves)

// ---------------- device scratch ----------------
__device__ __half g_q_inv[Nn * Ff];
__device__ __half g_k_inv[Nn * Ff];
__device__ __align__(16) __half g_v_inv[Nn * Ff];   // fp16 now
__device__ __half g_q_ev [Nn * Ff];
__device__ __half g_k_ev [Nn * Ff];
__device__ float  g_dinv [Nn * Ff];
__device__ float  g_dev  [Nn * 16];
__device__ __align__(16) __half g_fw[Ee * FSG];

// fragment-packed weights, paired layout: slot = 2*lane + h
__device__ __align__(16) unsigned int g_W2sw[2 * NTT * KS2 * 64];
__device__ __align__(16) unsigned int g_W1sw[2 * NTT * 2 * 64];
__device__ float g_b1c[2 * 144];
__device__ float g_b2c[2 * 144];

__device__ __forceinline__ float silu_f(float x) {
    return x / (1.0f + __expf(-x));
}

__device__ __forceinline__ void mma16816(float c[4],
    unsigned a0, unsigned a1, unsigned a2, unsigned a3,
    unsigned b0, unsigned b1)
{
    asm volatile(
        "mma.sync.aligned.m16n8k16.row.col.f32.f16.f16.f32 "
        "{%0,%1,%2,%3},{%4,%5,%6,%7},{%8,%9},{%0,%1,%2,%3};\n"
        : "+f"(c[0]), "+f"(c[1]), "+f"(c[2]), "+f"(c[3])
        : "r"(a0), "r"(a1), "r"(a2), "r"(a3), "r"(b0), "r"(b1));
}

__device__ __forceinline__ void ldsm4(unsigned& r0, unsigned& r1,
                                      unsigned& r2, unsigned& r3,
                                      unsigned addr)
{
    asm volatile(
        "ldmatrix.sync.aligned.m8n8.x4.shared.b16 {%0,%1,%2,%3}, [%4];\n"
        : "=r"(r0), "=r"(r1), "=r"(r2), "=r"(r3) : "r"(addr));
}

__device__ __forceinline__ void red_add_v4(float* p, float a, float b,
                                           float c, float d)
{
    asm volatile("red.global.add.v4.f32 [%0], {%1,%2,%3,%4};"
                 :: "l"(p), "f"(a), "f"(b), "f"(c), "f"(d) : "memory");
}

// ---------------- zero accumulators ----------------
__global__ void zero_kernel() {
    int i = blockIdx.x * blockDim.x + threadIdx.x;
    int stride = gridDim.x * blockDim.x;
    for (int j = i; j < Nn * Ff; j += stride) g_dinv[j] = 0.0f;
    for (int j = i; j < Nn * 16; j += stride) g_dev[j] = 0.0f;
}

// ---------------- weight prep (K=176 packing: rbf 0..131, ev 132..164) ----------------
__device__ __forceinline__ float W2com(int net, int k, int n,
    const float* fi_rW2, const float* fi_eW2,
    const float* fe_rW2, const float* fe_eW2)
{
    if (n >= 132) return 0.0f;
    if (k < 132)  return (net ? fe_rW2 : fi_rW2)[k * 132 + n];
    if (k < 165)  return (net ? fe_eW2 : fi_eW2)[(k - 132) * 132 + n];
    return 0.0f;
}

__global__ void prep_kernel(
    const float* __restrict__ fi_rW1, const float* __restrict__ fi_rb1,
    const float* __restrict__ fi_rW2, const float* __restrict__ fi_rb2,
    const float* __restrict__ fi_eW2, const float* __restrict__ fi_eb2,
    const float* __restrict__ fe_rW1, const float* __restrict__ fe_rb1,
    const float* __restrict__ fe_rW2, const float* __restrict__ fe_rb2,
    const float* __restrict__ fe_eW2, const float* __restrict__ fe_eb2)
{
    int i = blockIdx.x * blockDim.x + threadIdx.x;
    if (i < 2 * NTT * KS2 * 64) {
        int slot = i & 63;
        int blk = i >> 6;
        int ks = blk % KS2;
        int tmp = blk / KS2;
        int tt = tmp % NTT;
        int net = tmp / NTT;
        int lane = slot >> 1, h = slot & 1;
        int gq = lane >> 2, t4 = lane & 3;
        int k = ks * 16 + h * 8 + 2 * t4;
        int n = tt * 8 + gq;
        __half2 v = __floats2half2_rn(
            W2com(net, k,     n, fi_rW2, fi_eW2, fe_rW2, fe_eW2),
            W2com(net, k + 1, n, fi_rW2, fi_eW2, fe_rW2, fe_eW2));
        ((__half2*)g_W2sw)[i] = v;
    }
    if (i < 2 * NTT * 2 * 64) {
        int slot = i & 63;
        int blk = i >> 6;
        int ks = blk & 1;
        int tmp = blk >> 1;
        int tt = tmp % NTT;
        int net = tmp / NTT;
        int lane = slot >> 1, h = slot & 1;
        int gq = lane >> 2, t4 = lane & 3;
        int k = ks * 16 + h * 8 + 2 * t4;
        int n = tt * 8 + gq;
        const float* W = net ? fe_rW1 : fi_rW1;
        float v0 = (n < 132) ? W[k * 132 + n] : 0.0f;
        float v1 = (n < 132) ? W[(k + 1) * 132 + n] : 0.0f;
        ((__half2*)g_W1sw)[i] = __floats2half2_rn(v0, v1);
    }
    if (i < 2 * 144) {
        int net = i / 144, n = i % 144;
        float b1 = 0.0f, b2 = 0.0f;
        if (n < 132) {
            b1 = (net ? fe_rb1 : fi_rb1)[n];
            b2 = (net ? fe_rb2 : fi_rb2)[n] + (net ? fe_eb2 : fi_eb2)[n];
        }
        g_b1c[i] = b1;
        g_b2c[i] = b2;
    }
}

// ---------------- per-node projections (transposed smem, float4 broadcast) ----------------
#define TNA 16
#define XSW 20
__global__ __launch_bounds__(256) void node_proj_kernel(
    const float* __restrict__ x,
    const float* __restrict__ Wq_inv, const float* __restrict__ Wk_inv,
    const float* __restrict__ Wv_inv, const float* __restrict__ Wq_ev,
    const float* __restrict__ Wk_ev)
{
    __shared__ __align__(16) float xs[Ff * XSW];
    const int n0 = blockIdx.x * TNA;
    for (int i = threadIdx.x; i < TNA * Ff; i += 256) {
        int t = i / Ff, f = i - t * Ff;
        xs[f * XSW + t] = x[n0 * Ff + i];
    }
    __syncthreads();

    for (int idx = threadIdx.x; idx < 5 * Ff; idx += 256) {
        const int m = idx / Ff, c = idx - m * Ff;
        const float* W;
        int D, h, e;
        if (m < 3) {
            D = 33; h = c / 33; e = c - h * 33;
            W = (m == 0 ? Wq_inv : (m == 1 ? Wk_inv : Wv_inv)) + h * 33 * 33;
        } else {
            D = 44; h = c / 44; e = c - h * 44;
            W = (m == 3 ? Wq_ev : Wk_ev) + h * 44 * 44;
        }
        float4 a0 = make_float4(0.f, 0.f, 0.f, 0.f);
        float4 a1 = a0, a2 = a0, a3 = a0;
        const int xb = h * D;
        for (int d = 0; d < D; d++) {
            const float w = W[d * D + e];
            const float4* xr = (const float4*)&xs[(xb + d) * XSW];
            const float4 x0 = xr[0], x1 = xr[1], x2 = xr[2], x3 = xr[3];
            a0.x += x0.x * w; a0.y += x0.y * w; a0.z += x0.z * w; a0.w += x0.w * w;
            a1.x += x1.x * w; a1.y += x1.y * w; a1.z += x1.z * w; a1.w += x1.w * w;
            a2.x += x2.x * w; a2.y += x2.y * w; a2.z += x2.z * w; a2.w += x2.w * w;
            a3.x += x3.x * w; a3.y += x3.y * w; a3.z += x3.z * w; a3.w += x3.w * w;
        }
        float acc[TNA] = {a0.x, a0.y, a0.z, a0.w, a1.x, a1.y, a1.z, a1.w,
                          a2.x, a2.y, a2.z, a2.w, a3.x, a3.y, a3.z, a3.w};
        if (m == 2) {
#pragma unroll
            for (int t = 0; t < TNA; t++)
                g_v_inv[(n0 + t) * Ff + c] = __float2half(acc[t]);
        } else {
            __half* out = (m == 0) ? g_q_inv : (m == 1) ? g_k_inv
                        : (m == 3) ? g_q_ev : g_k_ev;
#pragma unroll
            for (int t = 0; t < TNA; t++)
                out[(n0 + t) * Ff + c] = __float2half(silu_f(acc[t]));
        }
    }
}

// ---------------- K_gemm: per-net persistent GEMM, smem fw staging ----------------
struct GSm2 {
    unsigned sW2[NTT * KS2 * 64];   // 50688 B
    float sb1[144];
    float sb2[144];
    float sevW[99];
    float sevB[33];
    __half h1[TE * AS2];            // 23552 B
    __half fw[TE * FS2];            // 19456 B
    __half rbfs[TE * RS];           //  5120 B
    float ev3[TE * 3];              //   768 B
};                                  // ~101 KB -> 2 blocks/SM

__global__ __launch_bounds__(512, 2) void gemm_kernel(
    const float* __restrict__ ev_features,
    const float* __restrict__ rbf_g,
    const int*   __restrict__ senders,
    const int*   __restrict__ receivers,
    const float* __restrict__ fi_eW1, const float* __restrict__ fi_eb1,
    const float* __restrict__ fe_eW1, const float* __restrict__ fe_eb1)
{
    extern __shared__ char smraw[];
    GSm2& sm = *reinterpret_cast<GSm2*>(smraw);
    const int tid = threadIdx.x;
    const int w = tid >> 5, lane = tid & 31;
    const int gq = lane >> 2, t4 = lane & 3;
    const int net = blockIdx.x & 1;
    const int mh = w >> 3;
    const int wn = w & 7;
    const int ntile = (wn < 2) ? 3 : 2;
    const int l15 = lane & 15;
    const int lc8 = (lane & 16) ? 8 : 0;

    // one-time staging (this net only)
    {
        const unsigned* src = g_W2sw + net * NTT * KS2 * 64;
        for (int i = tid; i < NTT * KS2 * 64; i += 512) sm.sW2[i] = src[i];
    }
    for (int i = tid; i < 144; i += 512) {
        sm.sb1[i] = g_b1c[net * 144 + i];
        sm.sb2[i] = g_b2c[net * 144 + i];
    }
    {
        const float* eW = net ? fe_eW1 : fi_eW1;
        const float* eB = net ? fe_eb1 : fi_eb1;
        for (int i = tid; i < 99; i += 512) sm.sevW[i] = eW[i];
        for (int i = tid; i < 33; i += 512) sm.sevB[i] = eB[i];
    }
    for (int i = tid; i < TE * AS2 / 2; i += 512)
        ((unsigned*)sm.h1)[i] = 0u;
    __syncthreads();

    const unsigned h1s  = (unsigned)__cvta_generic_to_shared(sm.h1);
    const unsigned rbss = (unsigned)__cvta_generic_to_shared(sm.rbfs);
    const unsigned a2base = h1s  + 2 * ((2 * mh) * 16 * AS2 + l15 * AS2 + lc8);
    const unsigned a1base = rbss + 2 * ((2 * mh) * 16 * RS + l15 * RS + lc8);
    const unsigned* W1n = g_W1sw + net * NTT * 2 * 64;

    for (int u = blockIdx.x; u < 2 * NTILES; u += GRIDG) {
        const int tile = u >> 1;
        const int e0 = tile * TE;
        __syncthreads();

        for (int i = tid; i < TE * Rr; i += 512) {
            int t = i >> 5, c = i & 31;
            sm.rbfs[t * RS + c] = __float2half(rbf_g[e0 * Rr + i]);
        }
        if (tid < TE * 3) {
            int t = tid / 3, g3 = tid - 3 * t;
            int js = (g3 == 0) ? 0 : ((g3 == 1) ? 3 : 8);
            int je = (g3 == 0) ? 3 : ((g3 == 1) ? 8 : 15);
            const float* evs = ev_features + senders[e0 + t] * EVd;
            const float* evr = ev_features + receivers[e0 + t] * EVd;
            float a = 0.0f;
            for (int j = js; j < je; j++) {
                float d = evs[j] - evr[j];
                a += d * d;
            }
            sm.ev3[t * 3 + g3] = a;
        }
        __syncthreads();

        // layer 1 (rbf branch); stores predicated to cols < 132
        {
            float acc[3][2][4];
#pragma unroll
            for (int j = 0; j < 3; j++) {
                if (j < ntile) {
                    int nidx = (wn + 8 * j) * 8 + 2 * t4;
                    float b0f = sm.sb1[nidx], b1f = sm.sb1[nidx + 1];
#pragma unroll
                    for (int m = 0; m < 2; m++) {
                        acc[j][m][0] = b0f; acc[j][m][1] = b1f;
                        acc[j][m][2] = b0f; acc[j][m][3] = b1f;
                    }
                }
            }
#pragma unroll
            for (int ks = 0; ks < 2; ks++) {
                unsigned a[2][4];
#pragma unroll
                for (int m = 0; m < 2; m++)
                    ldsm4(a[m][0], a[m][1], a[m][2], a[m][3],
                          a1base + 2 * (m * 16 * RS + ks * 16));
#pragma unroll
                for (int j = 0; j < 3; j++) {
                    if (j < ntile) {
                        int tt = wn + 8 * j;
                        uint2 b = ((const uint2*)(W1n + (tt * 2 + ks) * 64))[lane];
#pragma unroll
                        for (int m = 0; m < 2; m++)
                            mma16816(acc[j][m], a[m][0], a[m][1], a[m][2], a[m][3], b.x, b.y);
                    }
                }
            }
#pragma unroll
            for (int j = 0; j < 3; j++) {
                if (j < ntile) {
                    int col = (wn + 8 * j) * 8 + 2 * t4;
                    if (col < 132) {
#pragma unroll
                        for (int m = 0; m < 2; m++) {
                            int r = (2 * mh + m) * 16 + gq;
                            *(__half2*)&sm.h1[r * AS2 + col] =
                                __floats2half2_rn(silu_f(acc[j][m][0]), silu_f(acc[j][m][1]));
                            *(__half2*)&sm.h1[(r + 8) * AS2 + col] =
                                __floats2half2_rn(silu_f(acc[j][m][2]), silu_f(acc[j][m][3]));
                        }
                    }
                }
            }
        }
        // ev branch: 3 -> 33, h1 cols 132..164
        for (int i = tid; i < TE * 33; i += 512) {
            int t = i / 33, cc = i - 33 * t;
            float v = sm.sevB[cc]
                    + sm.ev3[t * 3 + 0] * sm.sevW[cc]
                    + sm.ev3[t * 3 + 1] * sm.sevW[33 + cc]
                    + sm.ev3[t * 3 + 2] * sm.sevW[66 + cc];
            sm.h1[t * AS2 + 132 + cc] = __float2half(silu_f(v));
        }
        __syncthreads();

        // layer 2: [64x176] x [176x144] -> fw (smem)
        {
            float acc[3][2][4];
#pragma unroll
            for (int j = 0; j < 3; j++) {
                if (j < ntile) {
                    int nidx = (wn + 8 * j) * 8 + 2 * t4;
                    float b0f = sm.sb2[nidx], b1f = sm.sb2[nidx + 1];
#pragma unroll
                    for (int m = 0; m < 2; m++) {
                        acc[j][m][0] = b0f; acc[j][m][1] = b1f;
                        acc[j][m][2] = b0f; acc[j][m][3] = b1f;
                    }
                }
            }
#pragma unroll 3
            for (int ks = 0; ks < KS2; ks++) {
                unsigned a[2][4];
#pragma unroll
                for (int m = 0; m < 2; m++)
                    ldsm4(a[m][0], a[m][1], a[m][2], a[m][3],
                          a2base + 2 * (m * 16 * AS2 + ks * 16));
#pragma unroll
                for (int j = 0; j < 3; j++) {
                    if (j < ntile) {
                        int tt = wn + 8 * j;
                        uint2 b = ((const uint2*)(sm.sW2 + (tt * KS2 + ks) * 64))[lane];
#pragma unroll
                        for (int m = 0; m < 2; m++)
                            mma16816(acc[j][m], a[m][0], a[m][1], a[m][2], a[m][3], b.x, b.y);
                    }
                }
            }
#pragma unroll
            for (int j = 0; j < 3; j++) {
                if (j < ntile) {
                    int col = (wn + 8 * j) * 8 + 2 * t4;
#pragma unroll
                    for (int m = 0; m < 2; m++) {
                        int r = (2 * mh + m) * 16 + gq;
                        *(__half2*)&sm.fw[r * FS2 + col] =
                            __floats2half2_rn(acc[j][m][0], acc[j][m][1]);
                        *(__half2*)&sm.fw[(r + 8) * FS2 + col] =
                            __floats2half2_rn(acc[j][m][2], acc[j][m][3]);
                    }
                }
            }
        }
        __syncthreads();

        // coalesced fw writeout
        {
            __half* dstbase = g_fw + (size_t)e0 * FSG + net * 144;
            for (int i = tid; i < TE * 18; i += 512) {
                int r = i / 18, c = i - r * 18;
                *(uint4*)(dstbase + r * FSG + c * 8) =
                    *(const uint4*)&sm.fw[r * FS2 + c * 8];
            }
        }
    }
}

// ---------------- K_att: attention logits + scatter (2-way interleave) ----------------
struct ASm {
    float  al [TE * 8];
    float  cut[TE];
    int    sidx[TE];
    int    ridx[TE];
};

__global__ __launch_bounds__(256) void att_kernel(
    const float* __restrict__ cutoffs,
    const int*   __restrict__ senders,
    const int*   __restrict__ receivers,
    const float* __restrict__ sh)
{
    __shared__ ASm sm;
    const int tid = threadIdx.x;
    const int w = tid >> 5, lane = tid & 31;
    const int e0 = blockIdx.x * TE;

    if (tid < TE) {
        sm.sidx[tid] = senders[e0 + tid];
        sm.ridx[tid] = receivers[e0 + tid];
        sm.cut[tid]  = cutoffs[e0 + tid];
    }
    __syncthreads();

    // alpha: 448 tasks over 8 warps, 2-way interleaved; fw read directly
    {
        const float INVN = 0.17407765595569785f;  // 1/sqrt(33)
        const float INVE = 0.15075567228888181f;  // 1/sqrt(44)
        for (int p = 0; p < 28; p++) {
            int taskA = w + 8 * (2 * p);
            int taskB = w + 8 * (2 * p + 1);
            int tA = taskA / 7, hA = taskA - 7 * tA;
            int tB = taskB / 7, hB = taskB - 7 * tB;

            const __half *qA, *kA, *fA; int DA; float nmA;
            if (hA < 4) { qA = g_q_inv + sm.ridx[tA] * Ff + hA * 33;
                          kA = g_k_inv + sm.sidx[tA] * Ff + hA * 33;
                          fA = g_fw + (size_t)(e0 + tA) * FSG + hA * 33;
                          DA = 33; nmA = INVN; }
            else        { int hh = hA - 4;
                          qA = g_q_ev + sm.ridx[tA] * Ff + hh * 44;
                          kA = g_k_ev + sm.sidx[tA] * Ff + hh * 44;
                          fA = g_fw + (size_t)(e0 + tA) * FSG + 144 + hh * 44;
                          DA = 44; nmA = INVE; }
            const __half *qB, *kB, *fB; int DB; float nmB;
            if (hB < 4) { qB = g_q_inv + sm.ridx[tB] * Ff + hB * 33;
                          kB = g_k_inv + sm.sidx[tB] * Ff + hB * 33;
                          fB = g_fw + (size_t)(e0 + tB) * FSG + hB * 33;
                          DB = 33; nmB = INVN; }
            else        { int hh = hB - 4;
                          qB = g_q_ev + sm.ridx[tB] * Ff + hh * 44;
                          kB = g_k_ev + sm.sidx[tB] * Ff + hh * 44;
                          fB = g_fw + (size_t)(e0 + tB) * FSG + 144 + hh * 44;
                          DB = 44; nmB = INVE; }

            float aA = __half2float(qA[lane]) * __half2float(kA[lane])
                     * __half2float(fA[lane]);
            float aB = __half2float(qB[lane]) * __half2float(kB[lane])
                     * __half2float(fB[lane]);
            int d1 = lane + 32;
            if (d1 < DA) aA += __half2float(qA[d1]) * __half2float(kA[d1])
                             * __half2float(fA[d1]);
            if (d1 < DB) aB += __half2float(qB[d1]) * __half2float(kB[d1])
                             * __half2float(fB[d1]);
#pragma unroll
            for (int s = 16; s > 0; s >>= 1) {
                aA += __shfl_xor_sync(0xFFFFFFFFu, aA, s);
                aB += __shfl_xor_sync(0xFFFFFFFFu, aB, s);
            }
            if (lane == 0) {
                sm.al[tA * 8 + hA] = aA * nmA * sm.cut[tA];
                sm.al[tB * 8 + hB] = aB * nmB * sm.cut[tB];
            }
        }
    }
    __syncthreads();

    // scatter: inv messages (fp16 v gather, 33 reds of 4 per edge)
    for (int i = tid; i < TE * 33; i += 256) {
        int t = i / 33, c4 = i - 33 * t;
        int f0 = 4 * c4;
        uint2 raw = *(const uint2*)(g_v_inv + sm.sidx[t] * Ff + f0);
        __half2 v01 = *(__half2*)&raw.x;
        __half2 v23 = *(__half2*)&raw.y;
        float r0 = sm.al[t * 8 + (f0 + 0) / 33] * __low2float(v01);
        float r1 = sm.al[t * 8 + (f0 + 1) / 33] * __high2float(v01);
        float r2 = sm.al[t * 8 + (f0 + 2) / 33] * __low2float(v23);
        float r3 = sm.al[t * 8 + (f0 + 3) / 33] * __high2float(v23);
        red_add_v4(g_dinv + sm.ridx[t] * Ff + f0, r0, r1, r2, r3);
    }
    // scatter: ev messages (4 float4 per edge, padded row of 16)
    for (int i = tid; i < TE * 4; i += 256) {
        int t = i >> 2, q4 = i & 3;
        int j0 = 4 * q4;
        float r[4];
#pragma unroll
        for (int u = 0; u < 4; u++) {
            int j = j0 + u;
            if (j < EVd) {
                int gg = (j < 3) ? 0 : ((j < 8) ? 1 : 2);
                r[u] = sm.al[t * 8 + 4 + gg] * sh[(e0 + t) * EVd + j];
            } else r[u] = 0.0f;
        }
        red_add_v4(g_dev + sm.ridx[t] * 16 + j0, r[0], r[1], r[2], r[3]);
    }
}

// ---------------- final node update (transposed smem, float4 broadcast) ----------------
#define TNF 8
__global__ __launch_bounds__(160) void final_kernel(
    const float* __restrict__ inv_features,
    const float* __restrict__ ev_features,
    const float* __restrict__ W_int,
    const float* __restrict__ b_int,
    float* __restrict__ out)
{
    __shared__ __align__(16) float ct[136 * TNF];
    __shared__ float ev1_s[TNF][EVd];
    __shared__ float tb_s[TNF][3];
    const int n0 = blockIdx.x * TNF;

    for (int i = threadIdx.x; i < TNF * Ff; i += 160) {
        const int t = i & 7, f = i >> 3;
        ct[f * TNF + t] = inv_features[(n0 + t) * Ff + f] + g_dinv[(n0 + t) * Ff + f];
    }
    for (int i = threadIdx.x; i < TNF * EVd; i += 160) {
        const int t = i / EVd, j = i - EVd * t;
        ev1_s[t][j] = ev_features[(n0 + t) * EVd + j] + g_dev[(n0 + t) * 16 + j];
    }
    __syncthreads();
    for (int i = threadIdx.x; i < TNF * 3; i += 160) {
        const int t = i / 3, g = i - 3 * t;
        const int js = (g == 0) ? 0 : ((g == 1) ? 3 : 8);
        const int je = (g == 0) ? 3 : ((g == 1) ? 8 : 15);
        float a = 0.0f;
        for (int j = js; j < je; j++) {
            const float v = ev1_s[t][j];
            a += v * v;
        }
        ct[(132 + g) * TNF + t] = a;
    }
    __syncthreads();

    if (threadIdx.x < 135) {
        const int f = threadIdx.x;
        const float b = b_int[f];
        float4 a0 = make_float4(b, b, b, b);
        float4 a1 = a0;
        for (int k = 0; k < 135; k++) {
            const float w = W_int[k * 135 + f];
            const float4* xr = (const float4*)&ct[k * TNF];
            const float4 x0 = xr[0], x1 = xr[1];
            a0.x += x0.x * w; a0.y += x0.y * w; a0.z += x0.z * w; a0.w += x0.w * w;
            a1.x += x1.x * w; a1.y += x1.y * w; a1.z += x1.z * w; a1.w += x1.w * w;
        }
        float acc[TNF] = {a0.x, a0.y, a0.z, a0.w, a1.x, a1.y, a1.z, a1.w};
        if (f < 132) {
#pragma unroll
            for (int t = 0; t < TNF; t++)
                out[(n0 + t) * Ff + f] = ct[f * TNF + t] + acc[t];
        } else {
#pragma unroll
            for (int t = 0; t < TNF; t++) tb_s[t][f - 132] = acc[t];
        }
    }
    __syncthreads();

    float* out_ev = out + Nn * Ff;
    for (int i = threadIdx.x; i < TNF * EVd; i += 160) {
        const int t = i / EVd, j = i - EVd * t;
        const int g = (j < 3) ? 0 : ((j < 8) ? 1 : 2);
        out_ev[(n0 + t) * EVd + j] = ev1_s[t][j] * (1.0f + tb_s[t][g]);
    }
}

// ---------------- launch ----------------
extern "C" void kernel_launch(void* const* d_in, const int* in_sizes, int n_in,
                              void* d_out, int out_size)
{
    const float* inv_features = (const float*)d_in[0];
    const float* ev_features  = (const float*)d_in[1];
    const float* rbf          = (const float*)d_in[2];
    const float* sh_vectors   = (const float*)d_in[3];
    const float* cutoffs      = (const float*)d_in[4];
    const int*   senders      = (const int*)d_in[5];
    const int*   receivers    = (const int*)d_in[6];
    const float* Wq_inv = (const float*)d_in[7];
    const float* Wk_inv = (const float*)d_in[8];
    const float* Wv_inv = (const float*)d_in[9];
    const float* Wq_ev  = (const float*)d_in[10];
    const float* Wk_ev  = (const float*)d_in[11];
    const float* fi_rW1 = (const float*)d_in[12];
    const float* fi_rb1 = (const float*)d_in[13];
    const float* fi_rW2 = (const float*)d_in[14];
    const float* fi_rb2 = (const float*)d_in[15];
    const float* fi_eW1 = (const float*)d_in[16];
    const float* fi_eb1 = (const float*)d_in[17];
    const float* fi_eW2 = (const float*)d_in[18];
    const float* fi_eb2 = (const float*)d_in[19];
    const float* fe_rW1 = (const float*)d_in[20];
    const float* fe_rb1 = (const float*)d_in[21];
    const float* fe_rW2 = (const float*)d_in[22];
    const float* fe_rb2 = (const float*)d_in[23];
    const float* fe_eW1 = (const float*)d_in[24];
    const float* fe_eb1 = (const float*)d_in[25];
    const float* fe_eW2 = (const float*)d_in[26];
    const float* fe_eb2 = (const float*)d_in[27];
    const float* W_int  = (const float*)d_in[28];
    const float* b_int  = (const float*)d_in[29];
    float* out = (float*)d_out;

    cudaFuncSetAttribute(gemm_kernel,
                         cudaFuncAttributeMaxDynamicSharedMemorySize,
                         (int)sizeof(GSm2));

    zero_kernel<<<512, 256>>>();
    prep_kernel<<<(2 * NTT * KS2 * 64 + 255) / 256, 256>>>(
        fi_rW1, fi_rb1, fi_rW2, fi_rb2, fi_eW2, fi_eb2,
        fe_rW1, fe_rb1, fe_rW2, fe_rb2, fe_eW2, fe_eb2);
    node_proj_kernel<<<Nn / TNA, 256>>>(inv_features, Wq_inv, Wk_inv, Wv_inv,
                                        Wq_ev, Wk_ev);
    gemm_kernel<<<GRIDG, 512, sizeof(GSm2)>>>(
        ev_features, rbf, senders, receivers,
        fi_eW1, fi_eb1, fe_eW1, fe_eb1);
    att_kernel<<<NTILES, 256>>>(cutoffs, senders, receivers, sh_vectors);
    final_kernel<<<Nn / TNF, 160>>>(inv_features, ev_features, W_int, b_int, out);
}

// round 17
// speedup vs baseline: 4.9037x; 1.0073x over previous
#include <cuda_runtime.h>
#include <cuda_fp16.h>

// Problem constants
#define Nn   50000
#define Ee   400000
#define Rr   32
#define Ff   132
#define EVd  15

#define TE     64    // edges per tile
#define NTILES 6250  // Ee / TE
#define GRIDG  296   // persistent gemm blocks (2 per SM)

#define NTT  18      // n-tiles per net (N padded 144)
#define KS2  11      // layer-2 k-steps (K padded 176)
#define AS2  184     // h1 row stride (halves)
#define FS2  152     // fw smem row stride (halves)
#define FSG  288     // fw gmem row stride (halves)
#define RS   40      // rbf smem row stride (halves)

// ---------------- device scratch ----------------
// q/k concatenated: [0 .. Nn*Ff) = inv, [Nn*Ff .. 2*Nn*Ff) = ev
__device__ __half g_qcat[2 * Nn * Ff];
__device__ __half g_kcat[2 * Nn * Ff];
__device__ __align__(16) __half g_v_inv[Nn * Ff];
__device__ float  g_dinv [Nn * Ff];
__device__ float  g_dev  [Nn * 16];
__device__ __align__(16) __half g_fw[Ee * FSG];

// fragment-packed weights, paired layout: slot = 2*lane + h
__device__ __align__(16) unsigned int g_W2sw[2 * NTT * KS2 * 64];
__device__ __align__(16) unsigned int g_W1sw[2 * NTT * 2 * 64];
__device__ float g_b1c[2 * 144];
__device__ float g_b2c[2 * 144];

__device__ __forceinline__ float silu_f(float x) {
    return x / (1.0f + __expf(-x));
}

__device__ __forceinline__ void mma16816(float c[4],
    unsigned a0, unsigned a1, unsigned a2, unsigned a3,
    unsigned b0, unsigned b1)
{
    asm volatile(
        "mma.sync.aligned.m16n8k16.row.col.f32.f16.f16.f32 "
        "{%0,%1,%2,%3},{%4,%5,%6,%7},{%8,%9},{%0,%1,%2,%3};\n"
        : "+f"(c[0]), "+f"(c[1]), "+f"(c[2]), "+f"(c[3])
        : "r"(a0), "r"(a1), "r"(a2), "r"(a3), "r"(b0), "r"(b1));
}

__device__ __forceinline__ void ldsm4(unsigned& r0, unsigned& r1,
                                      unsigned& r2, unsigned& r3,
                                      unsigned addr)
{
    asm volatile(
        "ldmatrix.sync.aligned.m8n8.x4.shared.b16 {%0,%1,%2,%3}, [%4];\n"
        : "=r"(r0), "=r"(r1), "=r"(r2), "=r"(r3) : "r"(addr));
}

__device__ __forceinline__ void red_add_v4(float* p, float a, float b,
                                           float c, float d)
{
    asm volatile("red.global.add.v4.f32 [%0], {%1,%2,%3,%4};"
                 :: "l"(p), "f"(a), "f"(b), "f"(c), "f"(d) : "memory");
}

// ---------------- zero accumulators ----------------
__global__ void zero_kernel() {
    int i = blockIdx.x * blockDim.x + threadIdx.x;
    int stride = gridDim.x * blockDim.x;
    for (int j = i; j < Nn * Ff; j += stride) g_dinv[j] = 0.0f;
    for (int j = i; j < Nn * 16; j += stride) g_dev[j] = 0.0f;
}

// ---------------- weight prep (K=176 packing: rbf 0..131, ev 132..164) ----------------
__device__ __forceinline__ float W2com(int net, int k, int n,
    const float* fi_rW2, const float* fi_eW2,
    const float* fe_rW2, const float* fe_eW2)
{
    if (n >= 132) return 0.0f;
    if (k < 132)  return (net ? fe_rW2 : fi_rW2)[k * 132 + n];
    if (k < 165)  return (net ? fe_eW2 : fi_eW2)[(k - 132) * 132 + n];
    return 0.0f;
}

__global__ void prep_kernel(
    const float* __restrict__ fi_rW1, const float* __restrict__ fi_rb1,
    const float* __restrict__ fi_rW2, const float* __restrict__ fi_rb2,
    const float* __restrict__ fi_eW2, const float* __restrict__ fi_eb2,
    const float* __restrict__ fe_rW1, const float* __restrict__ fe_rb1,
    const float* __restrict__ fe_rW2, const float* __restrict__ fe_rb2,
    const float* __restrict__ fe_eW2, const float* __restrict__ fe_eb2)
{
    int i = blockIdx.x * blockDim.x + threadIdx.x;
    if (i < 2 * NTT * KS2 * 64) {
        int slot = i & 63;
        int blk = i >> 6;
        int ks = blk % KS2;
        int tmp = blk / KS2;
        int tt = tmp % NTT;
        int net = tmp / NTT;
        int lane = slot >> 1, h = slot & 1;
        int gq = lane >> 2, t4 = lane & 3;
        int k = ks * 16 + h * 8 + 2 * t4;
        int n = tt * 8 + gq;
        __half2 v = __floats2half2_rn(
            W2com(net, k,     n, fi_rW2, fi_eW2, fe_rW2, fe_eW2),
            W2com(net, k + 1, n, fi_rW2, fi_eW2, fe_rW2, fe_eW2));
        ((__half2*)g_W2sw)[i] = v;
    }
    if (i < 2 * NTT * 2 * 64) {
        int slot = i & 63;
        int blk = i >> 6;
        int ks = blk & 1;
        int tmp = blk >> 1;
        int tt = tmp % NTT;
        int net = tmp / NTT;
        int lane = slot >> 1, h = slot & 1;
        int gq = lane >> 2, t4 = lane & 3;
        int k = ks * 16 + h * 8 + 2 * t4;
        int n = tt * 8 + gq;
        const float* W = net ? fe_rW1 : fi_rW1;
        float v0 = (n < 132) ? W[k * 132 + n] : 0.0f;
        float v1 = (n < 132) ? W[(k + 1) * 132 + n] : 0.0f;
        ((__half2*)g_W1sw)[i] = __floats2half2_rn(v0, v1);
    }
    if (i < 2 * 144) {
        int net = i / 144, n = i % 144;
        float b1 = 0.0f, b2 = 0.0f;
        if (n < 132) {
            b1 = (net ? fe_rb1 : fi_rb1)[n];
            b2 = (net ? fe_rb2 : fi_rb2)[n] + (net ? fe_eb2 : fi_eb2)[n];
        }
        g_b1c[i] = b1;
        g_b2c[i] = b2;
    }
}

// ---------------- per-node projections (transposed smem, float4 broadcast) ----------------
#define TNA 16
#define XSW 20
__global__ __launch_bounds__(256) void node_proj_kernel(
    const float* __restrict__ x,
    const float* __restrict__ Wq_inv, const float* __restrict__ Wk_inv,
    const float* __restrict__ Wv_inv, const float* __restrict__ Wq_ev,
    const float* __restrict__ Wk_ev)
{
    __shared__ __align__(16) float xs[Ff * XSW];
    const int n0 = blockIdx.x * TNA;
    for (int i = threadIdx.x; i < TNA * Ff; i += 256) {
        int t = i / Ff, f = i - t * Ff;
        xs[f * XSW + t] = x[n0 * Ff + i];
    }
    __syncthreads();

    for (int idx = threadIdx.x; idx < 5 * Ff; idx += 256) {
        const int m = idx / Ff, c = idx - m * Ff;
        const float* W;
        int D, h, e;
        if (m < 3) {
            D = 33; h = c / 33; e = c - h * 33;
            W = (m == 0 ? Wq_inv : (m == 1 ? Wk_inv : Wv_inv)) + h * 33 * 33;
        } else {
            D = 44; h = c / 44; e = c - h * 44;
            W = (m == 3 ? Wq_ev : Wk_ev) + h * 44 * 44;
        }
        float4 a0 = make_float4(0.f, 0.f, 0.f, 0.f);
        float4 a1 = a0, a2 = a0, a3 = a0;
        const int xb = h * D;
        for (int d = 0; d < D; d++) {
            const float w = W[d * D + e];
            const float4* xr = (const float4*)&xs[(xb + d) * XSW];
            const float4 x0 = xr[0], x1 = xr[1], x2 = xr[2], x3 = xr[3];
            a0.x += x0.x * w; a0.y += x0.y * w; a0.z += x0.z * w; a0.w += x0.w * w;
            a1.x += x1.x * w; a1.y += x1.y * w; a1.z += x1.z * w; a1.w += x1.w * w;
            a2.x += x2.x * w; a2.y += x2.y * w; a2.z += x2.z * w; a2.w += x2.w * w;
            a3.x += x3.x * w; a3.y += x3.y * w; a3.z += x3.z * w; a3.w += x3.w * w;
        }
        float acc[TNA] = {a0.x, a0.y, a0.z, a0.w, a1.x, a1.y, a1.z, a1.w,
                          a2.x, a2.y, a2.z, a2.w, a3.x, a3.y, a3.z, a3.w};
        if (m == 2) {
#pragma unroll
            for (int t = 0; t < TNA; t++)
                g_v_inv[(n0 + t) * Ff + c] = __float2half(acc[t]);
        } else {
            // m==0 -> q_inv (qcat lo), m==1 -> k_inv (kcat lo),
            // m==3 -> q_ev (qcat hi), m==4 -> k_ev (kcat hi)
            __half* out = ((m == 0) ? g_qcat : (m == 1) ? g_kcat
                        : (m == 3) ? (g_qcat + Nn * Ff) : (g_kcat + Nn * Ff));
#pragma unroll
            for (int t = 0; t < TNA; t++)
                out[(n0 + t) * Ff + c] = __float2half(silu_f(acc[t]));
        }
    }
}

// ---------------- K_gemm: per-net persistent GEMM, smem fw staging ----------------
struct GSm2 {
    unsigned sW2[NTT * KS2 * 64];   // 50688 B
    float sb1[144];
    float sb2[144];
    float sevW[99];
    float sevB[33];
    __half h1[TE * AS2];            // 23552 B
    __half fw[TE * FS2];            // 19456 B
    __half rbfs[TE * RS];           //  5120 B
    float ev3[TE * 3];              //   768 B
};                                  // ~101 KB -> 2 blocks/SM

__global__ __launch_bounds__(512, 2) void gemm_kernel(
    const float* __restrict__ ev_features,
    const float* __restrict__ rbf_g,
    const int*   __restrict__ senders,
    const int*   __restrict__ receivers,
    const float* __restrict__ fi_eW1, const float* __restrict__ fi_eb1,
    const float* __restrict__ fe_eW1, const float* __restrict__ fe_eb1)
{
    extern __shared__ char smraw[];
    GSm2& sm = *reinterpret_cast<GSm2*>(smraw);
    const int tid = threadIdx.x;
    const int w = tid >> 5, lane = tid & 31;
    const int gq = lane >> 2, t4 = lane & 3;
    const int net = blockIdx.x & 1;
    const int mh = w >> 3;
    const int wn = w & 7;
    const int ntile = (wn < 2) ? 3 : 2;
    const int l15 = lane & 15;
    const int lc8 = (lane & 16) ? 8 : 0;

    // one-time staging (this net only)
    {
        const unsigned* src = g_W2sw + net * NTT * KS2 * 64;
        for (int i = tid; i < NTT * KS2 * 64; i += 512) sm.sW2[i] = src[i];
    }
    for (int i = tid; i < 144; i += 512) {
        sm.sb1[i] = g_b1c[net * 144 + i];
        sm.sb2[i] = g_b2c[net * 144 + i];
    }
    {
        const float* eW = net ? fe_eW1 : fi_eW1;
        const float* eB = net ? fe_eb1 : fi_eb1;
        for (int i = tid; i < 99; i += 512) sm.sevW[i] = eW[i];
        for (int i = tid; i < 33; i += 512) sm.sevB[i] = eB[i];
    }
    for (int i = tid; i < TE * AS2 / 2; i += 512)
        ((unsigned*)sm.h1)[i] = 0u;
    __syncthreads();

    const unsigned h1s  = (unsigned)__cvta_generic_to_shared(sm.h1);
    const unsigned rbss = (unsigned)__cvta_generic_to_shared(sm.rbfs);
    const unsigned a2base = h1s  + 2 * ((2 * mh) * 16 * AS2 + l15 * AS2 + lc8);
    const unsigned a1base = rbss + 2 * ((2 * mh) * 16 * RS + l15 * RS + lc8);
    const unsigned* W1n = g_W1sw + net * NTT * 2 * 64;

    for (int u = blockIdx.x; u < 2 * NTILES; u += GRIDG) {
        const int tile = u >> 1;
        const int e0 = tile * TE;
        // NOTE: no loop-top barrier — post-writeout/post-staging hazards are
        // covered by the three in-loop barriers (verified phase analysis).

        for (int i = tid; i < TE * Rr; i += 512) {
            int t = i >> 5, c = i & 31;
            sm.rbfs[t * RS + c] = __float2half(rbf_g[e0 * Rr + i]);
        }
        if (tid < TE * 3) {
            int t = tid / 3, g3 = tid - 3 * t;
            int js = (g3 == 0) ? 0 : ((g3 == 1) ? 3 : 8);
            int je = (g3 == 0) ? 3 : ((g3 == 1) ? 8 : 15);
            const float* evs = ev_features + senders[e0 + t] * EVd;
            const float* evr = ev_features + receivers[e0 + t] * EVd;
            float a = 0.0f;
            for (int j = js; j < je; j++) {
                float d = evs[j] - evr[j];
                a += d * d;
            }
            sm.ev3[t * 3 + g3] = a;
        }
        __syncthreads();   // B

        // layer 1 (rbf branch); stores predicated to cols < 132
        {
            float acc[3][2][4];
#pragma unroll
            for (int j = 0; j < 3; j++) {
                if (j < ntile) {
                    int nidx = (wn + 8 * j) * 8 + 2 * t4;
                    float b0f = sm.sb1[nidx], b1f = sm.sb1[nidx + 1];
#pragma unroll
                    for (int m = 0; m < 2; m++) {
                        acc[j][m][0] = b0f; acc[j][m][1] = b1f;
                        acc[j][m][2] = b0f; acc[j][m][3] = b1f;
                    }
                }
            }
#pragma unroll
            for (int ks = 0; ks < 2; ks++) {
                unsigned a[2][4];
#pragma unroll
                for (int m = 0; m < 2; m++)
                    ldsm4(a[m][0], a[m][1], a[m][2], a[m][3],
                          a1base + 2 * (m * 16 * RS + ks * 16));
#pragma unroll
                for (int j = 0; j < 3; j++) {
                    if (j < ntile) {
                        int tt = wn + 8 * j;
                        uint2 b = ((const uint2*)(W1n + (tt * 2 + ks) * 64))[lane];
#pragma unroll
                        for (int m = 0; m < 2; m++)
                            mma16816(acc[j][m], a[m][0], a[m][1], a[m][2], a[m][3], b.x, b.y);
                    }
                }
            }
#pragma unroll
            for (int j = 0; j < 3; j++) {
                if (j < ntile) {
                    int col = (wn + 8 * j) * 8 + 2 * t4;
                    if (col < 132) {
#pragma unroll
                        for (int m = 0; m < 2; m++) {
                            int r = (2 * mh + m) * 16 + gq;
                            *(__half2*)&sm.h1[r * AS2 + col] =
                                __floats2half2_rn(silu_f(acc[j][m][0]), silu_f(acc[j][m][1]));
                            *(__half2*)&sm.h1[(r + 8) * AS2 + col] =
                                __floats2half2_rn(silu_f(acc[j][m][2]), silu_f(acc[j][m][3]));
                        }
                    }
                }
            }
        }
        // ev branch: 3 -> 33, h1 cols 132..164
        for (int i = tid; i < TE * 33; i += 512) {
            int t = i / 33, cc = i - 33 * t;
            float v = sm.sevB[cc]
                    + sm.ev3[t * 3 + 0] * sm.sevW[cc]
                    + sm.ev3[t * 3 + 1] * sm.sevW[33 + cc]
                    + sm.ev3[t * 3 + 2] * sm.sevW[66 + cc];
            sm.h1[t * AS2 + 132 + cc] = __float2half(silu_f(v));
        }
        __syncthreads();   // C

        // layer 2: [64x176] x [176x144] -> fw (smem)
        {
            float acc[3][2][4];
#pragma unroll
            for (int j = 0; j < 3; j++) {
                if (j < ntile) {
                    int nidx = (wn + 8 * j) * 8 + 2 * t4;
                    float b0f = sm.sb2[nidx], b1f = sm.sb2[nidx + 1];
#pragma unroll
                    for (int m = 0; m < 2; m++) {
                        acc[j][m][0] = b0f; acc[j][m][1] = b1f;
                        acc[j][m][2] = b0f; acc[j][m][3] = b1f;
                    }
                }
            }
#pragma unroll 3
            for (int ks = 0; ks < KS2; ks++) {
                unsigned a[2][4];
#pragma unroll
                for (int m = 0; m < 2; m++)
                    ldsm4(a[m][0], a[m][1], a[m][2], a[m][3],
                          a2base + 2 * (m * 16 * AS2 + ks * 16));
#pragma unroll
                for (int j = 0; j < 3; j++) {
                    if (j < ntile) {
                        int tt = wn + 8 * j;
                        uint2 b = ((const uint2*)(sm.sW2 + (tt * KS2 + ks) * 64))[lane];
#pragma unroll
                        for (int m = 0; m < 2; m++)
                            mma16816(acc[j][m], a[m][0], a[m][1], a[m][2], a[m][3], b.x, b.y);
                    }
                }
            }
#pragma unroll
            for (int j = 0; j < 3; j++) {
                if (j < ntile) {
                    int col = (wn + 8 * j) * 8 + 2 * t4;
#pragma unroll
                    for (int m = 0; m < 2; m++) {
                        int r = (2 * mh + m) * 16 + gq;
                        *(__half2*)&sm.fw[r * FS2 + col] =
                            __floats2half2_rn(acc[j][m][0], acc[j][m][1]);
                        *(__half2*)&sm.fw[(r + 8) * FS2 + col] =
                            __floats2half2_rn(acc[j][m][2], acc[j][m][3]);
                    }
                }
            }
        }
        __syncthreads();   // D

        // coalesced fw writeout
        {
            __half* dstbase = g_fw + (size_t)e0 * FSG + net * 144;
            for (int i = tid; i < TE * 18; i += 512) {
                int r = i / 18, c = i - r * 18;
                *(uint4*)(dstbase + r * FSG + c * 8) =
                    *(const uint4*)&sm.fw[r * FS2 + c * 8];
            }
        }
    }
}

// ---------------- K_att: attention logits + scatter (32-bit offsets) ----------------
struct ASm {
    float  al [TE * 8];
    float  cut[TE];
    int    sidx[TE];
    int    ridx[TE];
};

__global__ __launch_bounds__(256, 5) void att_kernel(
    const float* __restrict__ cutoffs,
    const int*   __restrict__ senders,
    const int*   __restrict__ receivers,
    const float* __restrict__ sh)
{
    __shared__ ASm sm;
    const int tid = threadIdx.x;
    const int w = tid >> 5, lane = tid & 31;
    const int e0 = blockIdx.x * TE;

    if (tid < TE) {
        sm.sidx[tid] = senders[e0 + tid];
        sm.ridx[tid] = receivers[e0 + tid];
        sm.cut[tid]  = cutoffs[e0 + tid];
    }
    __syncthreads();

    // alpha: 448 tasks over 8 warps, 2-way interleaved; single base pointers,
    // 32-bit offsets (ev segment at +Nn*Ff in qcat/kcat)
    {
        const float INVN = 0.17407765595569785f;  // 1/sqrt(33)
        const float INVE = 0.15075567228888181f;  // 1/sqrt(44)
        const __half* qb = g_qcat;
        const __half* kb = g_kcat;
        const __half* fb = g_fw;
        for (int p = 0; p < 28; p++) {
            int taskA = w + 8 * (2 * p);
            int taskB = w + 8 * (2 * p + 1);
            int tA = taskA / 7, hA = taskA - 7 * tA;
            int tB = taskB / 7, hB = taskB - 7 * tB;

            unsigned qoA, koA, foA; int DA; float nmA;
            if (hA < 4) {
                qoA = sm.ridx[tA] * Ff + hA * 33;
                koA = sm.sidx[tA] * Ff + hA * 33;
                foA = (unsigned)(e0 + tA) * FSG + hA * 33;
                DA = 33; nmA = INVN;
            } else {
                int hh = hA - 4;
                qoA = (unsigned)(Nn * Ff) + sm.ridx[tA] * Ff + hh * 44;
                koA = (unsigned)(Nn * Ff) + sm.sidx[tA] * Ff + hh * 44;
                foA = (unsigned)(e0 + tA) * FSG + 144 + hh * 44;
                DA = 44; nmA = INVE;
            }
            unsigned qoB, koB, foB; int DB; float nmB;
            if (hB < 4) {
                qoB = sm.ridx[tB] * Ff + hB * 33;
                koB = sm.sidx[tB] * Ff + hB * 33;
                foB = (unsigned)(e0 + tB) * FSG + hB * 33;
                DB = 33; nmB = INVN;
            } else {
                int hh = hB - 4;
                qoB = (unsigned)(Nn * Ff) + sm.ridx[tB] * Ff + hh * 44;
                koB = (unsigned)(Nn * Ff) + sm.sidx[tB] * Ff + hh * 44;
                foB = (unsigned)(e0 + tB) * FSG + 144 + hh * 44;
                DB = 44; nmB = INVE;
            }

            float aA = __half2float(qb[qoA + lane]) * __half2float(kb[koA + lane])
                     * __half2float(fb[foA + lane]);
            float aB = __half2float(qb[qoB + lane]) * __half2float(kb[koB + lane])
                     * __half2float(fb[foB + lane]);
            int d1 = lane + 32;
            if (d1 < DA) aA += __half2float(qb[qoA + d1]) * __half2float(kb[koA + d1])
                             * __half2float(fb[foA + d1]);
            if (d1 < DB) aB += __half2float(qb[qoB + d1]) * __half2float(kb[koB + d1])
                             * __half2float(fb[foB + d1]);
#pragma unroll
            for (int s = 16; s > 0; s >>= 1) {
                aA += __shfl_xor_sync(0xFFFFFFFFu, aA, s);
                aB += __shfl_xor_sync(0xFFFFFFFFu, aB, s);
            }
            if (lane == 0) {
                sm.al[tA * 8 + hA] = aA * nmA * sm.cut[tA];
                sm.al[tB * 8 + hB] = aB * nmB * sm.cut[tB];
            }
        }
    }
    __syncthreads();

    // scatter: inv messages (fp16 v gather, 33 reds of 4 per edge)
    for (int i = tid; i < TE * 33; i += 256) {
        int t = i / 33, c4 = i - 33 * t;
        int f0 = 4 * c4;
        uint2 raw = *(const uint2*)(g_v_inv + sm.sidx[t] * Ff + f0);
        __half2 v01 = *(__half2*)&raw.x;
        __half2 v23 = *(__half2*)&raw.y;
        float r0 = sm.al[t * 8 + (f0 + 0) / 33] * __low2float(v01);
        float r1 = sm.al[t * 8 + (f0 + 1) / 33] * __high2float(v01);
        float r2 = sm.al[t * 8 + (f0 + 2) / 33] * __low2float(v23);
        float r3 = sm.al[t * 8 + (f0 + 3) / 33] * __high2float(v23);
        red_add_v4(g_dinv + sm.ridx[t] * Ff + f0, r0, r1, r2, r3);
    }
    // scatter: ev messages (4 float4 per edge, padded row of 16)
    for (int i = tid; i < TE * 4; i += 256) {
        int t = i >> 2, q4 = i & 3;
        int j0 = 4 * q4;
        float r[4];
#pragma unroll
        for (int u = 0; u < 4; u++) {
            int j = j0 + u;
            if (j < EVd) {
                int gg = (j < 3) ? 0 : ((j < 8) ? 1 : 2);
                r[u] = sm.al[t * 8 + 4 + gg] * sh[(e0 + t) * EVd + j];
            } else r[u] = 0.0f;
        }
        red_add_v4(g_dev + sm.ridx[t] * 16 + j0, r[0], r[1], r[2], r[3]);
    }
}

// ---------------- final node update (transposed smem, float4 broadcast) ----------------
#define TNF 8
__global__ __launch_bounds__(160) void final_kernel(
    const float* __restrict__ inv_features,
    const float* __restrict__ ev_features,
    const float* __restrict__ W_int,
    const float* __restrict__ b_int,
    float* __restrict__ out)
{
    __shared__ __align__(16) float ct[136 * TNF];
    __shared__ float ev1_s[TNF][EVd];
    __shared__ float tb_s[TNF][3];
    const int n0 = blockIdx.x * TNF;

    for (int i = threadIdx.x; i < TNF * Ff; i += 160) {
        const int t = i & 7, f = i >> 3;
        ct[f * TNF + t] = inv_features[(n0 + t) * Ff + f] + g_dinv[(n0 + t) * Ff + f];
    }
    for (int i = threadIdx.x; i < TNF * EVd; i += 160) {
        const int t = i / EVd, j = i - EVd * t;
        ev1_s[t][j] = ev_features[(n0 + t) * EVd + j] + g_dev[(n0 + t) * 16 + j];
    }
    __syncthreads();
    for (int i = threadIdx.x; i < TNF * 3; i += 160) {
        const int t = i / 3, g = i - 3 * t;
        const int js = (g == 0) ? 0 : ((g == 1) ? 3 : 8);
        const int je = (g == 0) ? 3 : ((g == 1) ? 8 : 15);
        float a = 0.0f;
        for (int j = js; j < je; j++) {
            const float v = ev1_s[t][j];
            a += v * v;
        }
        ct[(132 + g) * TNF + t] = a;
    }
    __syncthreads();

    if (threadIdx.x < 135) {
        const int f = threadIdx.x;
        const float b = b_int[f];
        float4 a0 = make_float4(b, b, b, b);
        float4 a1 = a0;
        for (int k = 0; k < 135; k++) {
            const float w = W_int[k * 135 + f];
            const float4* xr = (const float4*)&ct[k * TNF];
            const float4 x0 = xr[0], x1 = xr[1];
            a0.x += x0.x * w; a0.y += x0.y * w; a0.z += x0.z * w; a0.w += x0.w * w;
            a1.x += x1.x * w; a1.y += x1.y * w; a1.z += x1.z * w; a1.w += x1.w * w;
        }
        float acc[TNF] = {a0.x, a0.y, a0.z, a0.w, a1.x, a1.y, a1.z, a1.w};
        if (f < 132) {
#pragma unroll
            for (int t = 0; t < TNF; t++)
                out[(n0 + t) * Ff + f] = ct[f * TNF + t] + acc[t];
        } else {
#pragma unroll
            for (int t = 0; t < TNF; t++) tb_s[t][f - 132] = acc[t];
        }
    }
    __syncthreads();

    float* out_ev = out + Nn * Ff;
    for (int i = threadIdx.x; i < TNF * EVd; i += 160) {
        const int t = i / EVd, j = i - EVd * t;
        const int g = (j < 3) ? 0 : ((j < 8) ? 1 : 2);
        out_ev[(n0 + t) * EVd + j] = ev1_s[t][j] * (1.0f + tb_s[t][g]);
    }
}

// ---------------- launch ----------------
extern "C" void kernel_launch(void* const* d_in, const int* in_sizes, int n_in,
                              void* d_out, int out_size)
{
    const float* inv_features = (const float*)d_in[0];
    const float* ev_features  = (const float*)d_in[1];
    const float* rbf          = (const float*)d_in[2];
    const float* sh_vectors   = (const float*)d_in[3];
    const float* cutoffs      = (const float*)d_in[4];
    const int*   senders      = (const int*)d_in[5];
    const int*   receivers    = (const int*)d_in[6];
    const float* Wq_inv = (const float*)d_in[7];
    const float* Wk_inv = (const float*)d_in[8];
    const float* Wv_inv = (const float*)d_in[9];
    const float* Wq_ev  = (const float*)d_in[10];
    const float* Wk_ev  = (const float*)d_in[11];
    const float* fi_rW1 = (const float*)d_in[12];
    const float* fi_rb1 = (const float*)d_in[13];
    const float* fi_rW2 = (const float*)d_in[14];
    const float* fi_rb2 = (const float*)d_in[15];
    const float* fi_eW1 = (const float*)d_in[16];
    const float* fi_eb1 = (const float*)d_in[17];
    const float* fi_eW2 = (const float*)d_in[18];
    const float* fi_eb2 = (const float*)d_in[19];
    const float* fe_rW1 = (const float*)d_in[20];
    const float* fe_rb1 = (const float*)d_in[21];
    const float* fe_rW2 = (const float*)d_in[22];
    const float* fe_rb2 = (const float*)d_in[23];
    const float* fe_eW1 = (const float*)d_in[24];
    const float* fe_eb1 = (const float*)d_in[25];
    const float* fe_eW2 = (const float*)d_in[26];
    const float* fe_eb2 = (const float*)d_in[27];
    const float* W_int  = (const float*)d_in[28];
    const float* b_int  = (const float*)d_in[29];
    float* out = (float*)d_out;

    cudaFuncSetAttribute(gemm_kernel,
                         cudaFuncAttributeMaxDynamicSharedMemorySize,
                         (int)sizeof(GSm2));

    zero_kernel<<<512, 256>>>();
    prep_kernel<<<(2 * NTT * KS2 * 64 + 255) / 256, 256>>>(
        fi_rW1, fi_rb1, fi_rW2, fi_rb2, fi_eW2, fi_eb2,
        fe_rW1, fe_rb1, fe_rW2, fe_rb2, fe_eW2, fe_eb2);
    node_proj_kernel<<<Nn / TNA, 256>>>(inv_features, Wq_inv, Wk_inv, Wv_inv,
                                        Wq_ev, Wk_ev);
    gemm_kernel<<<GRIDG, 512, sizeof(GSm2)>>>(
        ev_features, rbf, senders, receivers,
        fi_eW1, fi_eb1, fe_eW1, fe_eb1);
    att_kernel<<<NTILES, 256>>>(cutoffs, senders, receivers, sh_vectors);
    final_kernel<<<Nn / TNF, 160>>>(inv_features, ev_features, W_int, b_int, out);
}